// round 1
// baseline (speedup 1.0000x reference)
#include <cuda_runtime.h>

#define NN 150000
#define EE 300000
#define GG 4096
#define HH 256

// ---------------- scratch (device globals; no allocations) ----------------
__device__ float g_h[(size_t)NN * HH];
__device__ float g_h2[(size_t)NN * HH];
__device__ float g_agg[(size_t)NN * HH];
__device__ float g_vn[GG * HH];
__device__ float g_pool[GG * HH];
__device__ float g_vtmp[GG * HH];
__device__ float g_sum[HH];     // zero at module load; re-zeroed by k_bnfin
__device__ float g_sq[HH];
__device__ float g_scale[HH];
__device__ float g_shift[HH];

// ---------------- helpers ----------------
__device__ __forceinline__ unsigned long long pk(float x, float y) {
    unsigned long long r;
    asm("mov.b64 %0, {%1, %2};" : "=l"(r) : "f"(x), "f"(y));
    return r;
}
__device__ __forceinline__ void fma2(unsigned long long& d, unsigned long long a,
                                     unsigned long long b) {
    asm("fma.rn.f32x2 %0, %1, %2, %0;" : "+l"(d) : "l"(a), "l"(b));
}
__device__ __forceinline__ float2 unpk(unsigned long long v) {
    float2 r;
    asm("mov.b64 {%0, %1}, %2;" : "=f"(r.x), "=f"(r.y) : "l"(v));
    return r;
}
__device__ __forceinline__ void red_add4(float* p, float4 v) {
    asm volatile("red.global.add.v4.f32 [%0], {%1, %2, %3, %4};"
                 :: "l"(p), "f"(v.x), "f"(v.y), "f"(v.z), "f"(v.w) : "memory");
}

// ---------------- elementwise / encode kernels ----------------
// AtomEncoder: h[n,:] = sum_f atom_emb[f, x[n,f], :] + vn_weight[:]
__global__ void k_atom(const int* __restrict__ x, const float* __restrict__ aemb,
                       const float* __restrict__ vnw, float* __restrict__ h) {
    int t = threadIdx.x;
    int n = blockIdx.x * 4 + (t >> 6);
    if (n >= NN) return;
    int c = (t & 63) << 2;
    float4 s = *(const float4*)&vnw[c];
#pragma unroll
    for (int f = 0; f < 9; ++f) {
        int v = x[n * 9 + f];
        float4 ev = *(const float4*)&aemb[(size_t)((f << 6) + v) * HH + c];
        s.x += ev.x; s.y += ev.y; s.z += ev.z; s.w += ev.w;
    }
    *(float4*)&h[(size_t)n * HH + c] = s;
}

__global__ void k_vninit(float* __restrict__ vn, const float* __restrict__ vnw) {
    int t = threadIdx.x;
    int g = blockIdx.x * 4 + (t >> 6);
    int c = (t & 63) << 2;
    *(float4*)&vn[(size_t)g * HH + c] = *(const float4*)&vnw[c];
}

__global__ void k_copy(float4* __restrict__ d, const float4* __restrict__ s, size_t n) {
    size_t i = (size_t)blockIdx.x * blockDim.x + threadIdx.x;
    size_t stride = (size_t)gridDim.x * blockDim.x;
    for (; i < n; i += stride) d[i] = s[i];
}

__global__ void k_zero(float4* __restrict__ d, size_t n) {
    size_t i = (size_t)blockIdx.x * blockDim.x + threadIdx.x;
    size_t stride = (size_t)gridDim.x * blockDim.x;
    float4 z = make_float4(0.f, 0.f, 0.f, 0.f);
    for (; i < n; i += stride) d[i] = z;
}

// GENConv messages: agg[dst,:] += relu(h[src,:] + bond_emb(e)) + 1e-7
__global__ void k_msg(const float* __restrict__ hin, const int* __restrict__ ei,
                      const int* __restrict__ ea, const float* __restrict__ bemb,
                      float* __restrict__ agg) {
    int t = threadIdx.x;
    int e = blockIdx.x * 4 + (t >> 6);
    if (e >= EE) return;
    int c = (t & 63) << 2;
    int src = ei[e];
    int dst = ei[EE + e];
    int a0 = ea[e * 3 + 0], a1 = ea[e * 3 + 1], a2 = ea[e * 3 + 2];
    float4 hv = *(const float4*)&hin[(size_t)src * HH + c];
    float4 b0 = *(const float4*)&bemb[(size_t)(0 * 8 + a0) * HH + c];
    float4 b1 = *(const float4*)&bemb[(size_t)(1 * 8 + a1) * HH + c];
    float4 b2 = *(const float4*)&bemb[(size_t)(2 * 8 + a2) * HH + c];
    float4 m;
    m.x = fmaxf(hv.x + b0.x + b1.x + b2.x, 0.f) + 1e-7f;
    m.y = fmaxf(hv.y + b0.y + b1.y + b2.y, 0.f) + 1e-7f;
    m.z = fmaxf(hv.z + b0.z + b1.z + b2.z, 0.f) + 1e-7f;
    m.w = fmaxf(hv.w + b0.w + b1.w + b2.w, 0.f) + 1e-7f;
    red_add4(&agg[(size_t)dst * HH + c], m);
}

// ---------------- BatchNorm ----------------
__global__ void k_bnred(const float* __restrict__ X, int M) {
    int c = threadIdx.x;
    int r0 = blockIdx.x * 1024;
    int r1 = min(r0 + 1024, M);
    float s = 0.f, ss = 0.f;
    for (int r = r0; r < r1; ++r) {
        float v = X[(size_t)r * HH + c];
        s += v;
        ss += v * v;
    }
    atomicAdd(&g_sum[c], s);
    atomicAdd(&g_sq[c], ss);
}

__global__ void k_bnfin(const float* __restrict__ gamma, const float* __restrict__ beta,
                        float invM) {
    int c = threadIdx.x;
    float mu = g_sum[c] * invM;
    float var = g_sq[c] * invM - mu * mu;
    float sc = gamma[c] * rsqrtf(var + 1e-5f);
    g_scale[c] = sc;
    g_shift[c] = beta[c] - mu * sc;
    g_sum[c] = 0.f;   // reset for next use (keeps every launch deterministic)
    g_sq[c] = 0.f;
}

// h2 = relu(bn(h)); pool[batch[n]] += h2   (pool pre-initialized to vn)
__global__ void k_bnapp_pool(const float* __restrict__ X, float* __restrict__ Y,
                             const int* __restrict__ batch, float* __restrict__ pool) {
    int t = threadIdx.x;
    int n = blockIdx.x * 4 + (t >> 6);
    if (n >= NN) return;
    int c = (t & 63) << 2;
    float4 xv = *(const float4*)&X[(size_t)n * HH + c];
    float4 sc = *(const float4*)&g_scale[c];
    float4 sh = *(const float4*)&g_shift[c];
    float4 v;
    v.x = fmaxf(fmaf(xv.x, sc.x, sh.x), 0.f);
    v.y = fmaxf(fmaf(xv.y, sc.y, sh.y), 0.f);
    v.z = fmaxf(fmaf(xv.z, sc.z, sh.z), 0.f);
    v.w = fmaxf(fmaf(xv.w, sc.w, sh.w), 0.f);
    *(float4*)&Y[(size_t)n * HH + c] = v;
    red_add4(&pool[(size_t)batch[n] * HH + c], v);
}

// Y = relu(bn(X)) over M rows (vn MLP)
__global__ void k_bnrelu(const float* __restrict__ X, float* __restrict__ Y, int M) {
    int t = threadIdx.x;
    int n = blockIdx.x * 4 + (t >> 6);
    if (n >= M) return;
    int c = (t & 63) << 2;
    float4 xv = *(const float4*)&X[(size_t)n * HH + c];
    float4 sc = *(const float4*)&g_scale[c];
    float4 sh = *(const float4*)&g_shift[c];
    float4 v;
    v.x = fmaxf(fmaf(xv.x, sc.x, sh.x), 0.f);
    v.y = fmaxf(fmaf(xv.y, sc.y, sh.y), 0.f);
    v.z = fmaxf(fmaf(xv.z, sc.z, sh.z), 0.f);
    v.w = fmaxf(fmaf(xv.w, sc.w, sh.w), 0.f);
    *(float4*)&Y[(size_t)n * HH + c] = v;
}

// h2 += vn[batch]; agg = h2
__global__ void k_addvn(float* __restrict__ h2, const int* __restrict__ batch,
                        const float* __restrict__ vn, float* __restrict__ agg) {
    int t = threadIdx.x;
    int n = blockIdx.x * 4 + (t >> 6);
    if (n >= NN) return;
    int c = (t & 63) << 2;
    size_t i = (size_t)n * HH + c;
    float4 a = *(const float4*)&h2[i];
    float4 b = *(const float4*)&vn[(size_t)batch[n] * HH + c];
    a.x += b.x; a.y += b.y; a.z += b.z; a.w += b.w;
    *(float4*)&h2[i] = a;
    *(float4*)&agg[i] = a;
}

// out[batch[n]] += bn(h[n])  (final pooling; no relu)
__global__ void k_outpool(const float* __restrict__ X, const int* __restrict__ batch,
                          float* __restrict__ out) {
    int t = threadIdx.x;
    int n = blockIdx.x * 4 + (t >> 6);
    if (n >= NN) return;
    int c = (t & 63) << 2;
    float4 xv = *(const float4*)&X[(size_t)n * HH + c];
    float4 sc = *(const float4*)&g_scale[c];
    float4 sh = *(const float4*)&g_shift[c];
    float4 v;
    v.x = fmaf(xv.x, sc.x, sh.x);
    v.y = fmaf(xv.y, sc.y, sh.y);
    v.z = fmaf(xv.z, sc.z, sh.z);
    v.w = fmaf(xv.w, sc.w, sh.w);
    red_add4(&out[(size_t)batch[n] * HH + c], v);
}

// ---------------- SGEMM: C[M,256] = A[M,256] @ W[256,256] + bias (+R) ----------------
// BM=128, BN=64, BK=16, 128 threads, 8x8 outputs/thread, packed f32x2 FMA.
__global__ void __launch_bounds__(128) k_gemm(const float* __restrict__ A,
                                              const float* __restrict__ W,
                                              const float* __restrict__ bias,
                                              const float* __restrict__ R,
                                              float* __restrict__ C, int M) {
    __shared__ float As[16][132];  // [k][m], padded: conflict-lite stores, aligned f4 reads
    __shared__ float Bs[16][64];   // [k][n]
    int tid = threadIdx.x;
    int tx = tid & 7;
    int ty = tid >> 3;
    int row0 = blockIdx.y * 128;
    int col0 = blockIdx.x * 64;

    unsigned long long acc[8][4];
#pragma unroll
    for (int i = 0; i < 8; ++i)
#pragma unroll
        for (int j = 0; j < 4; ++j) acc[i][j] = 0ULL;

    for (int k0 = 0; k0 < 256; k0 += 16) {
#pragma unroll
        for (int i = 0; i < 4; ++i) {  // A tile: 128x16 = 512 float4
            int f = tid + i * 128;
            int r = f >> 2;
            int kk4 = (f & 3) << 2;
            float4 v = make_float4(0.f, 0.f, 0.f, 0.f);
            int row = row0 + r;
            if (row < M) v = *(const float4*)&A[(size_t)row * 256 + k0 + kk4];
            As[kk4 + 0][r] = v.x;
            As[kk4 + 1][r] = v.y;
            As[kk4 + 2][r] = v.z;
            As[kk4 + 3][r] = v.w;
        }
#pragma unroll
        for (int i = 0; i < 2; ++i) {  // B tile: 16x64 = 256 float4
            int f = tid + i * 128;
            int kk = f >> 4;
            int c4 = (f & 15) << 2;
            *(float4*)&Bs[kk][c4] = *(const float4*)&W[(size_t)(k0 + kk) * 256 + col0 + c4];
        }
        __syncthreads();
#pragma unroll
        for (int kk = 0; kk < 16; ++kk) {
            float4 bA = *(const float4*)&Bs[kk][tx * 8];
            float4 bB = *(const float4*)&Bs[kk][tx * 8 + 4];
            unsigned long long bp0 = pk(bA.x, bA.y), bp1 = pk(bA.z, bA.w);
            unsigned long long bp2 = pk(bB.x, bB.y), bp3 = pk(bB.z, bB.w);
            float4 aA = *(const float4*)&As[kk][ty * 8];
            float4 aB = *(const float4*)&As[kk][ty * 8 + 4];
            float av[8] = {aA.x, aA.y, aA.z, aA.w, aB.x, aB.y, aB.z, aB.w};
#pragma unroll
            for (int i = 0; i < 8; ++i) {
                unsigned long long a2 = pk(av[i], av[i]);
                fma2(acc[i][0], a2, bp0);
                fma2(acc[i][1], a2, bp1);
                fma2(acc[i][2], a2, bp2);
                fma2(acc[i][3], a2, bp3);
            }
        }
        __syncthreads();
    }

    float4 bv0 = *(const float4*)&bias[col0 + tx * 8];
    float4 bv1 = *(const float4*)&bias[col0 + tx * 8 + 4];
#pragma unroll
    for (int i = 0; i < 8; ++i) {
        int row = row0 + ty * 8 + i;
        if (row >= M) return;
        float2 p0 = unpk(acc[i][0]), p1 = unpk(acc[i][1]);
        float2 p2 = unpk(acc[i][2]), p3 = unpk(acc[i][3]);
        float4 o0 = make_float4(p0.x + bv0.x, p0.y + bv0.y, p1.x + bv0.z, p1.y + bv0.w);
        float4 o1 = make_float4(p2.x + bv1.x, p2.y + bv1.y, p3.x + bv1.z, p3.y + bv1.w);
        size_t base = (size_t)row * 256 + col0 + tx * 8;
        if (R) {
            float4 r0 = *(const float4*)&R[base];
            float4 r1 = *(const float4*)&R[base + 4];
            o0.x += r0.x; o0.y += r0.y; o0.z += r0.z; o0.w += r0.w;
            o1.x += r1.x; o1.y += r1.y; o1.z += r1.z; o1.w += r1.w;
        }
        *(float4*)&C[base] = o0;
        *(float4*)&C[base + 4] = o1;
    }
}

// ---------------- host orchestration ----------------
extern "C" void kernel_launch(void* const* d_in, const int* in_sizes, int n_in,
                              void* d_out, int out_size) {
    const int* x = (const int*)d_in[0];
    const int* ei = (const int*)d_in[1];
    const int* ea = (const int*)d_in[2];
    const int* batch = (const int*)d_in[3];
    const float* aemb = (const float*)d_in[4];
    const float* bemb = (const float*)d_in[5];
    const float* vnw = (const float*)d_in[6];
    const float* cw = (const float*)d_in[7];
    const float* cb = (const float*)d_in[8];
    const float* ng = (const float*)d_in[9];
    const float* nbt = (const float*)d_in[10];
    const float* vw = (const float*)d_in[11];
    const float* vb = (const float*)d_in[12];
    const float* vg = (const float*)d_in[13];
    const float* vbt = (const float*)d_in[14];
    float* out = (float*)d_out;

    float *ph, *ph2, *pagg, *pvn, *ppool, *pvtmp;
    cudaGetSymbolAddress((void**)&ph, g_h);
    cudaGetSymbolAddress((void**)&ph2, g_h2);
    cudaGetSymbolAddress((void**)&pagg, g_agg);
    cudaGetSymbolAddress((void**)&pvn, g_vn);
    cudaGetSymbolAddress((void**)&ppool, g_pool);
    cudaGetSymbolAddress((void**)&pvtmp, g_vtmp);

    const int gN4 = (NN + 3) / 4;       // node-grain grid
    const int gE4 = (EE + 3) / 4;       // edge-grain grid
    const size_t NH4 = (size_t)NN * HH / 4;
    const size_t GH4 = (size_t)GG * HH / 4;
    const dim3 gemmN(4, (NN + 127) / 128);
    const dim3 gemmG(4, GG / 128);
    const int bnN = (NN + 1023) / 1024;

    // encode + vn init
    k_atom<<<gN4, 256>>>(x, aemb, vnw, ph);
    k_vninit<<<GG / 4, 256>>>(pvn, vnw);

    // conv 0: agg = h + sum msgs; h = agg @ W0 + b0
    k_copy<<<2048, 256>>>((float4*)pagg, (const float4*)ph, NH4);
    k_msg<<<gE4, 256>>>(ph, ei, ea, bemb, pagg);
    k_gemm<<<gemmN, 128>>>(pagg, cw, cb, nullptr, ph, NN);

    for (int l = 1; l < 7; ++l) {
        // h2 = relu(bn(h)); pool = vn + segment_sum(h2)
        k_bnred<<<bnN, 256>>>(ph, NN);
        k_bnfin<<<1, 256>>>(ng + (l - 1) * HH, nbt + (l - 1) * HH, 1.0f / NN);
        k_copy<<<64, 256>>>((float4*)ppool, (const float4*)pvn, GH4);
        k_bnapp_pool<<<gN4, 256>>>(ph, ph2, batch, ppool);

        // vn MLP: two (Linear -> BN -> ReLU)
        const float* vwl = vw + (size_t)(l - 1) * 2 * HH * HH;
        const float* vbl = vb + (size_t)(l - 1) * 2 * HH;
        const float* vgl = vg + (size_t)(l - 1) * 2 * HH;
        const float* vbl2 = vbt + (size_t)(l - 1) * 2 * HH;
        k_gemm<<<gemmG, 128>>>(ppool, vwl, vbl, nullptr, pvtmp, GG);
        k_bnred<<<4, 256>>>(pvtmp, GG);
        k_bnfin<<<1, 256>>>(vgl, vbl2, 1.0f / GG);
        k_bnrelu<<<GG / 4, 256>>>(pvtmp, ppool, GG);
        k_gemm<<<gemmG, 128>>>(ppool, vwl + HH * HH, vbl + HH, nullptr, pvtmp, GG);
        k_bnred<<<4, 256>>>(pvtmp, GG);
        k_bnfin<<<1, 256>>>(vgl + HH, vbl2 + HH, 1.0f / GG);
        k_bnrelu<<<GG / 4, 256>>>(pvtmp, pvn, GG);

        // h2 += vn[batch]; agg = h2; messages; h = agg @ Wl + bl + h
        k_addvn<<<gN4, 256>>>(ph2, batch, pvn, pagg);
        k_msg<<<gE4, 256>>>(ph2, ei, ea, bemb, pagg);
        k_gemm<<<gemmN, 128>>>(pagg, cw + (size_t)l * HH * HH, cb + l * HH, ph, ph, NN);
    }

    // final BN + global_add_pool
    k_bnred<<<bnN, 256>>>(ph, NN);
    k_bnfin<<<1, 256>>>(ng + 6 * HH, nbt + 6 * HH, 1.0f / NN);
    k_zero<<<512, 256>>>((float4*)out, GH4);
    k_outpool<<<gN4, 256>>>(ph, batch, out);
}

// round 4
// speedup vs baseline: 1.3825x; 1.3825x over previous
#include <cuda_runtime.h>
#include <cuda_bf16.h>
#include <cstdint>

#define NN 150000
#define EE 300000
#define GG 4096
#define HH 256
#define NMAT 19

// ---------------- scratch (device globals; no allocations) ----------------
__device__ float g_h[(size_t)NN * HH];
__device__ float g_h2[(size_t)NN * HH];
__device__ float g_agg[(size_t)NN * HH];
__device__ float g_vn[GG * HH];
__device__ float g_pool[GG * HH];
__device__ float g_vtmp[GG * HH];
__device__ float g_sum[HH];     // zero at module load; re-zeroed by k_bnfin
__device__ float g_sq[HH];
__device__ float g_scale[HH];
__device__ float g_shift[HH];
// split GEMM inputs: A hi/lo bf16 [rows][256]
__device__ __align__(16) __nv_bfloat16 g_ah[(size_t)NN * HH];
__device__ __align__(16) __nv_bfloat16 g_al[(size_t)NN * HH];
// prebuilt B' per matrix: [768][256] bf16 = rows [Bhi ; Bhi ; Blo]
__device__ __align__(16) __nv_bfloat16 g_bw[(size_t)NMAT * 768 * HH];

// ---------------- PTX helpers ----------------
__device__ __forceinline__ uint32_t s2u(const void* p) {
    uint32_t a;
    asm("{ .reg .u64 t; cvta.to.shared.u64 t, %1; cvt.u32.u64 %0, t; }" : "=r"(a) : "l"(p));
    return a;
}
__device__ __forceinline__ void cpasync16(uint32_t dst, const void* src) {
    asm volatile("cp.async.cg.shared.global [%0], [%1], 16;" :: "r"(dst), "l"(src));
}
__device__ __forceinline__ void cp_commit() {
    asm volatile("cp.async.commit_group;" ::: "memory");
}
__device__ __forceinline__ void cp_wait1() {
    asm volatile("cp.async.wait_group 1;" ::: "memory");
}
__device__ __forceinline__ void ldsm4(uint32_t a, uint32_t& r0, uint32_t& r1, uint32_t& r2,
                                      uint32_t& r3) {
    asm volatile("ldmatrix.sync.aligned.m8n8.x4.shared.b16 {%0,%1,%2,%3}, [%4];"
                 : "=r"(r0), "=r"(r1), "=r"(r2), "=r"(r3) : "r"(a));
}
__device__ __forceinline__ void ldsm4t(uint32_t a, uint32_t& r0, uint32_t& r1, uint32_t& r2,
                                       uint32_t& r3) {
    asm volatile("ldmatrix.sync.aligned.m8n8.x4.trans.shared.b16 {%0,%1,%2,%3}, [%4];"
                 : "=r"(r0), "=r"(r1), "=r"(r2), "=r"(r3) : "r"(a));
}
__device__ __forceinline__ void mma16816(float* c, const uint32_t* a, uint32_t b0, uint32_t b1) {
    asm volatile(
        "mma.sync.aligned.m16n8k16.row.col.f32.bf16.bf16.f32 "
        "{%0,%1,%2,%3}, {%4,%5,%6,%7}, {%8,%9}, {%0,%1,%2,%3};"
        : "+f"(c[0]), "+f"(c[1]), "+f"(c[2]), "+f"(c[3])
        : "r"(a[0]), "r"(a[1]), "r"(a[2]), "r"(a[3]), "r"(b0), "r"(b1));
}
__device__ __forceinline__ void red_add4(float* p, float4 v) {
    asm volatile("red.global.add.v4.f32 [%0], {%1, %2, %3, %4};"
                 :: "l"(p), "f"(v.x), "f"(v.y), "f"(v.z), "f"(v.w) : "memory");
}
__device__ __forceinline__ uint32_t pkbf(float a, float b) {
    __nv_bfloat16 h0 = __float2bfloat16(a), h1 = __float2bfloat16(b);
    return (uint32_t)__bfloat16_as_ushort(h0) | ((uint32_t)__bfloat16_as_ushort(h1) << 16);
}

// ---------------- weight prep: W[k][n] fp32 -> B'[768][256] bf16 ----------------
__global__ void k_prepw(const float* __restrict__ W, __nv_bfloat16* __restrict__ out) {
    int b = blockIdx.x;
    int mat = b >> 8;
    int k = b & 255;
    int n = threadIdx.x;
    float v = W[(size_t)mat * 65536 + k * 256 + n];
    __nv_bfloat16 h = __float2bfloat16(v);
    __nv_bfloat16 l = __float2bfloat16(v - __bfloat162float(h));
    size_t base = (size_t)mat * 768 * 256;
    out[base + (size_t)k * 256 + n] = h;
    out[base + (size_t)(k + 256) * 256 + n] = h;
    out[base + (size_t)(k + 512) * 256 + n] = l;
}

// ---------------- A split: fp32 [M][256] -> hi/lo bf16 ----------------
__global__ void k_split(const float* __restrict__ X, __nv_bfloat16* __restrict__ hi,
                        __nv_bfloat16* __restrict__ lo, int M) {
    int t = threadIdx.x;
    int n = blockIdx.x * 4 + (t >> 6);
    if (n >= M) return;
    int c = (t & 63) << 2;
    size_t o = (size_t)n * 256 + c;
    float4 v = *(const float4*)&X[o];
    float hx = __bfloat162float(__float2bfloat16(v.x));
    float hy = __bfloat162float(__float2bfloat16(v.y));
    float hz = __bfloat162float(__float2bfloat16(v.z));
    float hw = __bfloat162float(__float2bfloat16(v.w));
    uint2 hw2, lw2;
    hw2.x = pkbf(v.x, v.y);
    hw2.y = pkbf(v.z, v.w);
    lw2.x = pkbf(v.x - hx, v.y - hy);
    lw2.y = pkbf(v.z - hz, v.w - hw);
    *(uint2*)&hi[o] = hw2;
    *(uint2*)&lo[o] = lw2;
}

// ---------------- bf16 HMMA GEMM: C[M,256] = A'[M,768] @ B'[768,256] + bias (+R) ----
// BM=128, BN=256, BK=32, 3-stage cp.async, 8 warps (2x4), warp tile 64x64.
#define ASZ 8192
#define BSZ 16384
#define STAGE_SZ (ASZ + BSZ)
#define MG_SMEM (3 * STAGE_SZ)
#define NKC 24

__device__ __forceinline__ void mg_issue(int kc, uint32_t sb, int row0, int M, int tid,
                                         const __nv_bfloat16* __restrict__ Ah,
                                         const __nv_bfloat16* __restrict__ Al,
                                         const __nv_bfloat16* __restrict__ Bw) {
    int stage = kc % 3;
    uint32_t abase = sb + stage * STAGE_SZ;
    uint32_t bbase = abase + ASZ;
    const __nv_bfloat16* asrc = (kc < 8 || kc >= 16) ? Ah : Al;
    int col0 = (kc & 7) * 32;
#pragma unroll
    for (int i = 0; i < 2; ++i) {
        int f = tid + i * 256;   // 0..511
        int r = f >> 2, c = f & 3;
        int row = row0 + r;
        if (row >= M) row = M - 1;
        uint32_t dst = abase + r * 64 + ((c ^ (r & 3)) << 4);
        cpasync16(dst, asrc + (size_t)row * 256 + col0 + c * 8);
    }
    const __nv_bfloat16* bsrc = Bw + (size_t)kc * 32 * 256;
#pragma unroll
    for (int i = 0; i < 4; ++i) {
        int f = tid + i * 256;   // 0..1023
        int k = f >> 5, c = f & 31;
        uint32_t dst = bbase + k * 512 + ((c ^ (k & 7)) << 4);
        cpasync16(dst, bsrc + k * 256 + c * 8);
    }
    cp_commit();
}

__global__ void __launch_bounds__(256, 1)
k_mgemm(const __nv_bfloat16* __restrict__ Ah, const __nv_bfloat16* __restrict__ Al,
        const __nv_bfloat16* __restrict__ Bw, const float* __restrict__ bias,
        const float* __restrict__ R, float* __restrict__ C, int M) {
    extern __shared__ char sm[];
    uint32_t sb = s2u(sm);
    int tid = threadIdx.x;
    int lane = tid & 31;
    int wid = tid >> 5;
    int wm = wid & 1;          // warp M 0..1 (64 rows each)
    int wn = wid >> 1;         // warp N 0..3 (64 cols each)
    int row0 = blockIdx.x * 128;

    float acc[4][8][4];
#pragma unroll
    for (int mi = 0; mi < 4; ++mi)
#pragma unroll
        for (int ni = 0; ni < 8; ++ni)
#pragma unroll
            for (int q = 0; q < 4; ++q) acc[mi][ni][q] = 0.f;

    mg_issue(0, sb, row0, M, tid, Ah, Al, Bw);
    mg_issue(1, sb, row0, M, tid, Ah, Al, Bw);

    for (int kc = 0; kc < NKC; ++kc) {
        cp_wait1();
        __syncthreads();
        if (kc + 2 < NKC) mg_issue(kc + 2, sb, row0, M, tid, Ah, Al, Bw);
        else cp_commit();   // empty group keeps wait_group 1 semantics correct

        int stage = kc % 3;
        uint32_t abase = sb + stage * STAGE_SZ;
        uint32_t bbase = abase + ASZ;
#pragma unroll
        for (int ks = 0; ks < 2; ++ks) {
            uint32_t afr[4][4];
            int rl = lane & 15;
            int kofz = ks * 16 + ((lane >> 4) << 3);
            int achunk = kofz >> 3;
#pragma unroll
            for (int mi = 0; mi < 4; ++mi) {
                int r = wm * 64 + mi * 16 + rl;
                uint32_t addr = abase + r * 64 + ((achunk ^ (r & 3)) << 4);
                ldsm4(addr, afr[mi][0], afr[mi][1], afr[mi][2], afr[mi][3]);
            }
            uint32_t bfr[4][4];
            int kb = ks * 16 + (lane & 15);
#pragma unroll
            for (int nj = 0; nj < 4; ++nj) {
                int n = wn * 64 + nj * 16 + ((lane >> 4) << 3);
                int cN = n >> 3;
                uint32_t addr = bbase + kb * 512 + ((cN ^ (kb & 7)) << 4);
                ldsm4t(addr, bfr[nj][0], bfr[nj][1], bfr[nj][2], bfr[nj][3]);
            }
#pragma unroll
            for (int mi = 0; mi < 4; ++mi)
#pragma unroll
                for (int nj = 0; nj < 4; ++nj) {
                    mma16816(acc[mi][nj * 2 + 0], afr[mi], bfr[nj][0], bfr[nj][1]);
                    mma16816(acc[mi][nj * 2 + 1], afr[mi], bfr[nj][2], bfr[nj][3]);
                }
        }
    }

    // epilogue
    int r_c = lane >> 2;
    int c_c = (lane & 3) * 2;
    float bv[8][2];
#pragma unroll
    for (int ni = 0; ni < 8; ++ni) {
        int gc = wn * 64 + ni * 8 + c_c;
        bv[ni][0] = bias[gc];
        bv[ni][1] = bias[gc + 1];
    }
#pragma unroll
    for (int mi = 0; mi < 4; ++mi) {
        int gr0 = row0 + wm * 64 + mi * 16 + r_c;
#pragma unroll
        for (int ni = 0; ni < 8; ++ni) {
            int gc = wn * 64 + ni * 8 + c_c;
            if (gr0 < M) {
                size_t o = (size_t)gr0 * 256 + gc;
                float x0 = acc[mi][ni][0] + bv[ni][0];
                float x1 = acc[mi][ni][1] + bv[ni][1];
                if (R) { float2 rv = *(const float2*)&R[o]; x0 += rv.x; x1 += rv.y; }
                *(float2*)&C[o] = make_float2(x0, x1);
            }
            int gr1 = gr0 + 8;
            if (gr1 < M) {
                size_t o = (size_t)gr1 * 256 + gc;
                float x2 = acc[mi][ni][2] + bv[ni][0];
                float x3 = acc[mi][ni][3] + bv[ni][1];
                if (R) { float2 rv = *(const float2*)&R[o]; x2 += rv.x; x3 += rv.y; }
                *(float2*)&C[o] = make_float2(x2, x3);
            }
        }
    }
}

// ---------------- elementwise / encode kernels ----------------
__global__ void k_atom(const int* __restrict__ x, const float* __restrict__ aemb,
                       const float* __restrict__ vnw, float* __restrict__ h) {
    int t = threadIdx.x;
    int n = blockIdx.x * 4 + (t >> 6);
    if (n >= NN) return;
    int c = (t & 63) << 2;
    float4 s = *(const float4*)&vnw[c];
#pragma unroll
    for (int f = 0; f < 9; ++f) {
        int v = x[n * 9 + f];
        float4 ev = *(const float4*)&aemb[(size_t)((f << 6) + v) * HH + c];
        s.x += ev.x; s.y += ev.y; s.z += ev.z; s.w += ev.w;
    }
    *(float4*)&h[(size_t)n * HH + c] = s;
}

__global__ void k_vninit(float* __restrict__ vn, const float* __restrict__ vnw) {
    int t = threadIdx.x;
    int g = blockIdx.x * 4 + (t >> 6);
    int c = (t & 63) << 2;
    *(float4*)&vn[(size_t)g * HH + c] = *(const float4*)&vnw[c];
}

__global__ void k_copy(float4* __restrict__ d, const float4* __restrict__ s, size_t n) {
    size_t i = (size_t)blockIdx.x * blockDim.x + threadIdx.x;
    size_t stride = (size_t)gridDim.x * blockDim.x;
    for (; i < n; i += stride) d[i] = s[i];
}

__global__ void k_zero(float4* __restrict__ d, size_t n) {
    size_t i = (size_t)blockIdx.x * blockDim.x + threadIdx.x;
    size_t stride = (size_t)gridDim.x * blockDim.x;
    float4 z = make_float4(0.f, 0.f, 0.f, 0.f);
    for (; i < n; i += stride) d[i] = z;
}

__global__ void k_msg(const float* __restrict__ hin, const int* __restrict__ ei,
                      const int* __restrict__ ea, const float* __restrict__ bemb,
                      float* __restrict__ agg) {
    int t = threadIdx.x;
    int e = blockIdx.x * 4 + (t >> 6);
    if (e >= EE) return;
    int c = (t & 63) << 2;
    int src = ei[e];
    int dst = ei[EE + e];
    int a0 = ea[e * 3 + 0], a1 = ea[e * 3 + 1], a2 = ea[e * 3 + 2];
    float4 hv = *(const float4*)&hin[(size_t)src * HH + c];
    float4 b0 = *(const float4*)&bemb[(size_t)(0 * 8 + a0) * HH + c];
    float4 b1 = *(const float4*)&bemb[(size_t)(1 * 8 + a1) * HH + c];
    float4 b2 = *(const float4*)&bemb[(size_t)(2 * 8 + a2) * HH + c];
    float4 m;
    m.x = fmaxf(hv.x + b0.x + b1.x + b2.x, 0.f) + 1e-7f;
    m.y = fmaxf(hv.y + b0.y + b1.y + b2.y, 0.f) + 1e-7f;
    m.z = fmaxf(hv.z + b0.z + b1.z + b2.z, 0.f) + 1e-7f;
    m.w = fmaxf(hv.w + b0.w + b1.w + b2.w, 0.f) + 1e-7f;
    red_add4(&agg[(size_t)dst * HH + c], m);
}

// ---------------- BatchNorm ----------------
__global__ void k_bnred(const float* __restrict__ X, int M) {
    int c = threadIdx.x;
    int r0 = blockIdx.x * 256;
    int r1 = min(r0 + 256, M);
    float s = 0.f, ss = 0.f;
    for (int r = r0; r < r1; ++r) {
        float v = X[(size_t)r * HH + c];
        s += v;
        ss += v * v;
    }
    atomicAdd(&g_sum[c], s);
    atomicAdd(&g_sq[c], ss);
}

__global__ void k_bnfin(const float* __restrict__ gamma, const float* __restrict__ beta,
                        float invM) {
    int c = threadIdx.x;
    float mu = g_sum[c] * invM;
    float var = g_sq[c] * invM - mu * mu;
    float sc = gamma[c] * rsqrtf(var + 1e-5f);
    g_scale[c] = sc;
    g_shift[c] = beta[c] - mu * sc;
    g_sum[c] = 0.f;
    g_sq[c] = 0.f;
}

__global__ void k_bnapp_pool(const float* __restrict__ X, float* __restrict__ Y,
                             const int* __restrict__ batch, float* __restrict__ pool) {
    int t = threadIdx.x;
    int n = blockIdx.x * 4 + (t >> 6);
    if (n >= NN) return;
    int c = (t & 63) << 2;
    float4 xv = *(const float4*)&X[(size_t)n * HH + c];
    float4 sc = *(const float4*)&g_scale[c];
    float4 sh = *(const float4*)&g_shift[c];
    float4 v;
    v.x = fmaxf(fmaf(xv.x, sc.x, sh.x), 0.f);
    v.y = fmaxf(fmaf(xv.y, sc.y, sh.y), 0.f);
    v.z = fmaxf(fmaf(xv.z, sc.z, sh.z), 0.f);
    v.w = fmaxf(fmaf(xv.w, sc.w, sh.w), 0.f);
    *(float4*)&Y[(size_t)n * HH + c] = v;
    red_add4(&pool[(size_t)batch[n] * HH + c], v);
}

// Y = relu(bn(X)); optionally also write split bf16 hi/lo (for feeding GEMM)
__global__ void k_bnrelu(const float* __restrict__ X, float* __restrict__ Y,
                         __nv_bfloat16* __restrict__ hi, __nv_bfloat16* __restrict__ lo,
                         int M) {
    int t = threadIdx.x;
    int n = blockIdx.x * 4 + (t >> 6);
    if (n >= M) return;
    int c = (t & 63) << 2;
    size_t o = (size_t)n * HH + c;
    float4 xv = *(const float4*)&X[o];
    float4 sc = *(const float4*)&g_scale[c];
    float4 sh = *(const float4*)&g_shift[c];
    float4 v;
    v.x = fmaxf(fmaf(xv.x, sc.x, sh.x), 0.f);
    v.y = fmaxf(fmaf(xv.y, sc.y, sh.y), 0.f);
    v.z = fmaxf(fmaf(xv.z, sc.z, sh.z), 0.f);
    v.w = fmaxf(fmaf(xv.w, sc.w, sh.w), 0.f);
    if (Y) *(float4*)&Y[o] = v;
    if (hi) {
        float hx = __bfloat162float(__float2bfloat16(v.x));
        float hy = __bfloat162float(__float2bfloat16(v.y));
        float hz = __bfloat162float(__float2bfloat16(v.z));
        float hw = __bfloat162float(__float2bfloat16(v.w));
        uint2 hw2, lw2;
        hw2.x = pkbf(v.x, v.y);
        hw2.y = pkbf(v.z, v.w);
        lw2.x = pkbf(v.x - hx, v.y - hy);
        lw2.y = pkbf(v.z - hz, v.w - hw);
        *(uint2*)&hi[o] = hw2;
        *(uint2*)&lo[o] = lw2;
    }
}

__global__ void k_addvn(float* __restrict__ h2, const int* __restrict__ batch,
                        const float* __restrict__ vn, float* __restrict__ agg) {
    int t = threadIdx.x;
    int n = blockIdx.x * 4 + (t >> 6);
    if (n >= NN) return;
    int c = (t & 63) << 2;
    size_t i = (size_t)n * HH + c;
    float4 a = *(const float4*)&h2[i];
    float4 b = *(const float4*)&vn[(size_t)batch[n] * HH + c];
    a.x += b.x; a.y += b.y; a.z += b.z; a.w += b.w;
    *(float4*)&h2[i] = a;
    *(float4*)&agg[i] = a;
}

__global__ void k_outpool(const float* __restrict__ X, const int* __restrict__ batch,
                          float* __restrict__ out) {
    int t = threadIdx.x;
    int n = blockIdx.x * 4 + (t >> 6);
    if (n >= NN) return;
    int c = (t & 63) << 2;
    float4 xv = *(const float4*)&X[(size_t)n * HH + c];
    float4 sc = *(const float4*)&g_scale[c];
    float4 sh = *(const float4*)&g_shift[c];
    float4 v;
    v.x = fmaf(xv.x, sc.x, sh.x);
    v.y = fmaf(xv.y, sc.y, sh.y);
    v.z = fmaf(xv.z, sc.z, sh.z);
    v.w = fmaf(xv.w, sc.w, sh.w);
    red_add4(&out[(size_t)batch[n] * HH + c], v);
}

// ---------------- host orchestration ----------------
extern "C" void kernel_launch(void* const* d_in, const int* in_sizes, int n_in,
                              void* d_out, int out_size) {
    const int* x = (const int*)d_in[0];
    const int* ei = (const int*)d_in[1];
    const int* ea = (const int*)d_in[2];
    const int* batch = (const int*)d_in[3];
    const float* aemb = (const float*)d_in[4];
    const float* bemb = (const float*)d_in[5];
    const float* vnw = (const float*)d_in[6];
    const float* cw = (const float*)d_in[7];
    const float* cb = (const float*)d_in[8];
    const float* ng = (const float*)d_in[9];
    const float* nbt = (const float*)d_in[10];
    const float* vw = (const float*)d_in[11];
    const float* vb = (const float*)d_in[12];
    const float* vg = (const float*)d_in[13];
    const float* vbt = (const float*)d_in[14];
    float* out = (float*)d_out;

    float *ph, *ph2, *pagg, *pvn, *ppool, *pvtmp;
    __nv_bfloat16 *pah, *pal, *pbw;
    cudaGetSymbolAddress((void**)&ph, g_h);
    cudaGetSymbolAddress((void**)&ph2, g_h2);
    cudaGetSymbolAddress((void**)&pagg, g_agg);
    cudaGetSymbolAddress((void**)&pvn, g_vn);
    cudaGetSymbolAddress((void**)&ppool, g_pool);
    cudaGetSymbolAddress((void**)&pvtmp, g_vtmp);
    cudaGetSymbolAddress((void**)&pah, g_ah);
    cudaGetSymbolAddress((void**)&pal, g_al);
    cudaGetSymbolAddress((void**)&pbw, g_bw);

    cudaFuncSetAttribute(k_mgemm, cudaFuncAttributeMaxDynamicSharedMemorySize, MG_SMEM);

    const int gN4 = (NN + 3) / 4;
    const int gE4 = (EE + 3) / 4;
    const size_t NH4 = (size_t)NN * HH / 4;
    const size_t GH4 = (size_t)GG * HH / 4;
    const int tilesN = (NN + 127) / 128;
    const int tilesG = GG / 128;
    const int bnN = (NN + 255) / 256;
    const size_t WSTRIDE = (size_t)768 * HH;

    // weight prep: conv weights -> mats 0..6, vn weights -> mats 7..18
    k_prepw<<<7 * 256, 256>>>(cw, pbw);
    k_prepw<<<12 * 256, 256>>>(vw, pbw + 7 * WSTRIDE);

    // encode + vn init
    k_atom<<<gN4, 256>>>(x, aemb, vnw, ph);
    k_vninit<<<GG / 4, 256>>>(pvn, vnw);

    // conv 0: agg = h + sum msgs; h = agg @ W0 + b0
    k_copy<<<2048, 256>>>((float4*)pagg, (const float4*)ph, NH4);
    k_msg<<<gE4, 256>>>(ph, ei, ea, bemb, pagg);
    k_split<<<gN4, 256>>>(pagg, pah, pal, NN);
    k_mgemm<<<tilesN, 256, MG_SMEM>>>(pah, pal, pbw, cb, nullptr, ph, NN);

    for (int l = 1; l < 7; ++l) {
        // h2 = relu(bn(h)); pool = vn + segment_sum(h2)
        k_bnred<<<bnN, 256>>>(ph, NN);
        k_bnfin<<<1, 256>>>(ng + (l - 1) * HH, nbt + (l - 1) * HH, 1.0f / NN);
        k_copy<<<64, 256>>>((float4*)ppool, (const float4*)pvn, GH4);
        k_bnapp_pool<<<gN4, 256>>>(ph, ph2, batch, ppool);

        // vn MLP: two (Linear -> BN -> ReLU)
        int m0 = 7 + (l - 1) * 2;
        const float* vbl = vb + (size_t)(l - 1) * 2 * HH;
        const float* vgl = vg + (size_t)(l - 1) * 2 * HH;
        const float* vbl2 = vbt + (size_t)(l - 1) * 2 * HH;
        k_split<<<GG / 4, 256>>>(ppool, pah, pal, GG);
        k_mgemm<<<tilesG, 256, MG_SMEM>>>(pah, pal, pbw + (size_t)m0 * WSTRIDE, vbl,
                                          nullptr, pvtmp, GG);
        k_bnred<<<16, 256>>>(pvtmp, GG);
        k_bnfin<<<1, 256>>>(vgl, vbl2, 1.0f / GG);
        k_bnrelu<<<GG / 4, 256>>>(pvtmp, nullptr, pah, pal, GG);
        k_mgemm<<<tilesG, 256, MG_SMEM>>>(pah, pal, pbw + (size_t)(m0 + 1) * WSTRIDE,
                                          vbl + HH, nullptr, pvtmp, GG);
        k_bnred<<<16, 256>>>(pvtmp, GG);
        k_bnfin<<<1, 256>>>(vgl + HH, vbl2 + HH, 1.0f / GG);
        k_bnrelu<<<GG / 4, 256>>>(pvtmp, pvn, nullptr, nullptr, GG);

        // h2 += vn[batch]; agg = h2; messages; h = agg @ Wl + bl + h
        k_addvn<<<gN4, 256>>>(ph2, batch, pvn, pagg);
        k_msg<<<gE4, 256>>>(ph2, ei, ea, bemb, pagg);
        k_split<<<gN4, 256>>>(pagg, pah, pal, NN);
        k_mgemm<<<tilesN, 256, MG_SMEM>>>(pah, pal, pbw + (size_t)l * WSTRIDE, cb + l * HH,
                                          ph, ph, NN);
    }

    // final BN + global_add_pool
    k_bnred<<<bnN, 256>>>(ph, NN);
    k_bnfin<<<1, 256>>>(ng + 6 * HH, nbt + 6 * HH, 1.0f / NN);
    k_zero<<<512, 256>>>((float4*)out, GH4);
    k_outpool<<<gN4, 256>>>(ph, batch, out);
}

// round 5
// speedup vs baseline: 1.5226x; 1.1013x over previous
#include <cuda_runtime.h>
#include <cuda_bf16.h>
#include <cstdint>

#define NN 150000
#define EE 300000
#define GG 4096
#define HH 256
#define NMAT 19

// ---------------- scratch (device globals; no allocations) ----------------
__device__ float g_h[(size_t)NN * HH];
__device__ float g_h2[(size_t)NN * HH];
__device__ float g_msg[(size_t)NN * HH];
__device__ float g_vn[GG * HH];
__device__ float g_pool[GG * HH];
__device__ float g_vtmp[GG * HH];
__device__ float g_sum[HH];     // zero at module load; re-zeroed by k_bnfin
__device__ float g_sq[HH];
__device__ float g_scale[HH];
__device__ float g_shift[HH];
// prebuilt B' per matrix: [768][256] bf16 = rows [Bhi ; Bhi ; Blo]
__device__ __align__(16) __nv_bfloat16 g_bw[(size_t)NMAT * 768 * HH];

// ---------------- PTX helpers ----------------
__device__ __forceinline__ uint32_t s2u(const void* p) {
    uint32_t a;
    asm("{ .reg .u64 t; cvta.to.shared.u64 t, %1; cvt.u32.u64 %0, t; }" : "=r"(a) : "l"(p));
    return a;
}
__device__ __forceinline__ void cpasync16(uint32_t dst, const void* src) {
    asm volatile("cp.async.cg.shared.global [%0], [%1], 16;" :: "r"(dst), "l"(src));
}
__device__ __forceinline__ void cp_commit() {
    asm volatile("cp.async.commit_group;" ::: "memory");
}
__device__ __forceinline__ void cp_wait1() {
    asm volatile("cp.async.wait_group 1;" ::: "memory");
}
__device__ __forceinline__ void ldsm4(uint32_t a, uint32_t& r0, uint32_t& r1, uint32_t& r2,
                                      uint32_t& r3) {
    asm volatile("ldmatrix.sync.aligned.m8n8.x4.shared.b16 {%0,%1,%2,%3}, [%4];"
                 : "=r"(r0), "=r"(r1), "=r"(r2), "=r"(r3) : "r"(a));
}
__device__ __forceinline__ void ldsm4t(uint32_t a, uint32_t& r0, uint32_t& r1, uint32_t& r2,
                                       uint32_t& r3) {
    asm volatile("ldmatrix.sync.aligned.m8n8.x4.trans.shared.b16 {%0,%1,%2,%3}, [%4];"
                 : "=r"(r0), "=r"(r1), "=r"(r2), "=r"(r3) : "r"(a));
}
__device__ __forceinline__ void mma16816(float* c, const uint32_t* a, uint32_t b0, uint32_t b1) {
    asm volatile(
        "mma.sync.aligned.m16n8k16.row.col.f32.bf16.bf16.f32 "
        "{%0,%1,%2,%3}, {%4,%5,%6,%7}, {%8,%9}, {%0,%1,%2,%3};"
        : "+f"(c[0]), "+f"(c[1]), "+f"(c[2]), "+f"(c[3])
        : "r"(a[0]), "r"(a[1]), "r"(a[2]), "r"(a[3]), "r"(b0), "r"(b1));
}
__device__ __forceinline__ void red_add4(float* p, float4 v) {
    asm volatile("red.global.add.v4.f32 [%0], {%1, %2, %3, %4};"
                 :: "l"(p), "f"(v.x), "f"(v.y), "f"(v.z), "f"(v.w) : "memory");
}
__device__ __forceinline__ void red_addf(float* p, float v) {
    asm volatile("red.global.add.f32 [%0], %1;" :: "l"(p), "f"(v) : "memory");
}
__device__ __forceinline__ uint32_t pkbf(float a, float b) {
    __nv_bfloat16 h0 = __float2bfloat16(a), h1 = __float2bfloat16(b);
    return (uint32_t)__bfloat16_as_ushort(h0) | ((uint32_t)__bfloat16_as_ushort(h1) << 16);
}

// ---------------- weight prep: W[k][n] fp32 -> B'[768][256] bf16 ----------------
__global__ void k_prepw(const float* __restrict__ W, __nv_bfloat16* __restrict__ out) {
    int b = blockIdx.x;
    int mat = b >> 8;
    int k = b & 255;
    int n = threadIdx.x;
    float v = W[(size_t)mat * 65536 + k * 256 + n];
    __nv_bfloat16 h = __float2bfloat16(v);
    __nv_bfloat16 l = __float2bfloat16(v - __bfloat162float(h));
    size_t base = (size_t)mat * 768 * 256;
    out[base + (size_t)k * 256 + n] = h;
    out[base + (size_t)(k + 256) * 256 + n] = h;
    out[base + (size_t)(k + 512) * 256 + n] = l;
}

// ---------------- fused bf16 HMMA GEMM ------------------------------------------
// C[M,256] = (X + MS? + VN[bt]?)[M,256] @ B'[768,256] + bias (+R)
// A split to bf16 hi/lo in-kernel, persistent in SMEM (128KB). B 3-stage cp.async.
// Epilogue accumulates per-channel sum / sumsq into g_sum / g_sq (for next BN).
#define BSTG 16384
#define FG_SMEM (131072 + 3 * BSTG)
#define NKC 24

__device__ __forceinline__ void bg_issue(int kc, uint32_t sb, int tid,
                                         const __nv_bfloat16* __restrict__ Bw) {
    uint32_t bbase = sb + 131072u + (uint32_t)(kc % 3) * BSTG;
    const __nv_bfloat16* bsrc = Bw + (size_t)kc * 32 * 256;
#pragma unroll
    for (int i = 0; i < 4; ++i) {
        int f = tid + i * 256;
        int k = f >> 5, c = f & 31;
        uint32_t dst = bbase + k * 512 + ((c ^ (k & 7)) << 4);
        cpasync16(dst, bsrc + k * 256 + c * 8);
    }
    cp_commit();
}

__global__ void __launch_bounds__(256, 1)
k_fgemm(const float* __restrict__ X, const float* __restrict__ MS,
        const int* __restrict__ bt, const float* __restrict__ VN,
        const __nv_bfloat16* __restrict__ Bw, const float* __restrict__ bias,
        const float* __restrict__ R, float* __restrict__ C, int M) {
    extern __shared__ char sm[];
    uint32_t sb = s2u(sm);
    int tid = threadIdx.x;
    int lane = tid & 31;
    int wid = tid >> 5;
    int wm = wid & 1;
    int wn = wid >> 1;
    int row0 = blockIdx.x * 128;

    bg_issue(0, sb, tid, Bw);
    bg_issue(1, sb, tid, Bw);

    // A load (fp32, fused sum of sources) + split hi/lo into persistent SMEM
#pragma unroll 4
    for (int it = 0; it < 16; ++it) {
        int f = tid + it * 256;
        int r = f >> 5, ci = f & 31;
        int row = row0 + r;
        float v[8];
        if (row < M) {
            size_t o = (size_t)row * 256 + ci * 8;
            float4 a0 = *(const float4*)&X[o];
            float4 a1 = *(const float4*)&X[o + 4];
            v[0] = a0.x; v[1] = a0.y; v[2] = a0.z; v[3] = a0.w;
            v[4] = a1.x; v[5] = a1.y; v[6] = a1.z; v[7] = a1.w;
            if (MS) {
                float4 m0 = *(const float4*)&MS[o];
                float4 m1 = *(const float4*)&MS[o + 4];
                v[0] += m0.x; v[1] += m0.y; v[2] += m0.z; v[3] += m0.w;
                v[4] += m1.x; v[5] += m1.y; v[6] += m1.z; v[7] += m1.w;
            }
            if (VN) {
                size_t vo = (size_t)bt[row] * 256 + ci * 8;
                float4 w0 = *(const float4*)&VN[vo];
                float4 w1 = *(const float4*)&VN[vo + 4];
                v[0] += w0.x; v[1] += w0.y; v[2] += w0.z; v[3] += w0.w;
                v[4] += w1.x; v[5] += w1.y; v[6] += w1.z; v[7] += w1.w;
            }
        } else {
#pragma unroll
            for (int i = 0; i < 8; ++i) v[i] = 0.f;
        }
        uint32_t hw[4], lw[4];
#pragma unroll
        for (int i = 0; i < 4; ++i) {
            float x = v[2 * i], y = v[2 * i + 1];
            float hx = __bfloat162float(__float2bfloat16(x));
            float hy = __bfloat162float(__float2bfloat16(y));
            hw[i] = pkbf(x, y);
            lw[i] = pkbf(x - hx, y - hy);
        }
        uint32_t off = (uint32_t)(r * 512) + (uint32_t)((ci ^ (r & 7)) << 4);
        asm volatile("st.shared.v4.b32 [%0], {%1,%2,%3,%4};"
                     :: "r"(sb + off), "r"(hw[0]), "r"(hw[1]), "r"(hw[2]), "r"(hw[3]));
        asm volatile("st.shared.v4.b32 [%0], {%1,%2,%3,%4};"
                     :: "r"(sb + 65536u + off), "r"(lw[0]), "r"(lw[1]), "r"(lw[2]), "r"(lw[3]));
    }

    float acc[4][8][4];
#pragma unroll
    for (int mi = 0; mi < 4; ++mi)
#pragma unroll
        for (int ni = 0; ni < 8; ++ni)
#pragma unroll
            for (int q = 0; q < 4; ++q) acc[mi][ni][q] = 0.f;

    for (int kc = 0; kc < NKC; ++kc) {
        cp_wait1();
        __syncthreads();
        if (kc + 2 < NKC) bg_issue(kc + 2, sb, tid, Bw);
        else cp_commit();

        uint32_t abase = sb + ((kc >= 8 && kc < 16) ? 65536u : 0u);
        int cb8 = (kc & 7) * 4;
        uint32_t bbase = sb + 131072u + (uint32_t)(kc % 3) * BSTG;
#pragma unroll
        for (int ks = 0; ks < 2; ++ks) {
            uint32_t afr[4][4];
            int rl = lane & 15;
            int ci = cb8 + ks * 2 + (lane >> 4);
#pragma unroll
            for (int mi = 0; mi < 4; ++mi) {
                int r = wm * 64 + mi * 16 + rl;
                uint32_t addr = abase + r * 512 + ((ci ^ (r & 7)) << 4);
                ldsm4(addr, afr[mi][0], afr[mi][1], afr[mi][2], afr[mi][3]);
            }
            uint32_t bfr[4][4];
            int kb = ks * 16 + (lane & 15);
#pragma unroll
            for (int nj = 0; nj < 4; ++nj) {
                int n = wn * 64 + nj * 16 + ((lane >> 4) << 3);
                int cN = n >> 3;
                uint32_t addr = bbase + kb * 512 + ((cN ^ (kb & 7)) << 4);
                ldsm4t(addr, bfr[nj][0], bfr[nj][1], bfr[nj][2], bfr[nj][3]);
            }
#pragma unroll
            for (int mi = 0; mi < 4; ++mi)
#pragma unroll
                for (int nj = 0; nj < 4; ++nj) {
                    mma16816(acc[mi][nj * 2 + 0], afr[mi], bfr[nj][0], bfr[nj][1]);
                    mma16816(acc[mi][nj * 2 + 1], afr[mi], bfr[nj][2], bfr[nj][3]);
                }
        }
    }

    // epilogue: bias (+R) write, plus per-channel sum / sumsq accumulation
    int r_c = lane >> 2;
    int c_c = (lane & 3) * 2;
    float bv[8][2];
#pragma unroll
    for (int ni = 0; ni < 8; ++ni) {
        int gc = wn * 64 + ni * 8 + c_c;
        bv[ni][0] = bias[gc];
        bv[ni][1] = bias[gc + 1];
    }
    float ss[8][2], qq[8][2];
#pragma unroll
    for (int ni = 0; ni < 8; ++ni) {
        ss[ni][0] = ss[ni][1] = 0.f;
        qq[ni][0] = qq[ni][1] = 0.f;
    }
#pragma unroll
    for (int mi = 0; mi < 4; ++mi) {
        int gr0 = row0 + wm * 64 + mi * 16 + r_c;
        int gr1 = gr0 + 8;
#pragma unroll
        for (int ni = 0; ni < 8; ++ni) {
            int gc = wn * 64 + ni * 8 + c_c;
            if (gr0 < M) {
                size_t o = (size_t)gr0 * 256 + gc;
                float x0 = acc[mi][ni][0] + bv[ni][0];
                float x1 = acc[mi][ni][1] + bv[ni][1];
                if (R) { float2 rv = *(const float2*)&R[o]; x0 += rv.x; x1 += rv.y; }
                *(float2*)&C[o] = make_float2(x0, x1);
                ss[ni][0] += x0; qq[ni][0] += x0 * x0;
                ss[ni][1] += x1; qq[ni][1] += x1 * x1;
            }
            if (gr1 < M) {
                size_t o = (size_t)gr1 * 256 + gc;
                float x2 = acc[mi][ni][2] + bv[ni][0];
                float x3 = acc[mi][ni][3] + bv[ni][1];
                if (R) { float2 rv = *(const float2*)&R[o]; x2 += rv.x; x3 += rv.y; }
                *(float2*)&C[o] = make_float2(x2, x3);
                ss[ni][0] += x2; qq[ni][0] += x2 * x2;
                ss[ni][1] += x3; qq[ni][1] += x3 * x3;
            }
        }
    }
    // reduce over the 8 lanes sharing each column (lane>>2 axis), then red.global
#pragma unroll
    for (int ni = 0; ni < 8; ++ni)
#pragma unroll
        for (int j = 0; j < 2; ++j) {
            float s = ss[ni][j], q = qq[ni][j];
            s += __shfl_xor_sync(0xffffffffu, s, 4);
            s += __shfl_xor_sync(0xffffffffu, s, 8);
            s += __shfl_xor_sync(0xffffffffu, s, 16);
            q += __shfl_xor_sync(0xffffffffu, q, 4);
            q += __shfl_xor_sync(0xffffffffu, q, 8);
            q += __shfl_xor_sync(0xffffffffu, q, 16);
            ss[ni][j] = s; qq[ni][j] = q;
        }
    if (r_c == 0) {
#pragma unroll
        for (int ni = 0; ni < 8; ++ni) {
            int gc = wn * 64 + ni * 8 + c_c;
            red_addf(&g_sum[gc], ss[ni][0]);
            red_addf(&g_sum[gc + 1], ss[ni][1]);
            red_addf(&g_sq[gc], qq[ni][0]);
            red_addf(&g_sq[gc + 1], qq[ni][1]);
        }
    }
}

// ---------------- elementwise / encode kernels ----------------
// AtomEncoder (+vn_weight) and zero the message buffer
__global__ void k_atom(const int* __restrict__ x, const float* __restrict__ aemb,
                       const float* __restrict__ vnw, float* __restrict__ h,
                       float* __restrict__ msg) {
    int t = threadIdx.x;
    int n = blockIdx.x * 4 + (t >> 6);
    if (n >= NN) return;
    int c = (t & 63) << 2;
    float4 s = *(const float4*)&vnw[c];
#pragma unroll
    for (int f = 0; f < 9; ++f) {
        int v = x[n * 9 + f];
        float4 ev = *(const float4*)&aemb[(size_t)((f << 6) + v) * HH + c];
        s.x += ev.x; s.y += ev.y; s.z += ev.z; s.w += ev.w;
    }
    *(float4*)&h[(size_t)n * HH + c] = s;
    *(float4*)&msg[(size_t)n * HH + c] = make_float4(0.f, 0.f, 0.f, 0.f);
}

__global__ void k_vninit(float* __restrict__ vn, const float* __restrict__ vnw) {
    int t = threadIdx.x;
    int g = blockIdx.x * 4 + (t >> 6);
    int c = (t & 63) << 2;
    *(float4*)&vn[(size_t)g * HH + c] = *(const float4*)&vnw[c];
}

__global__ void k_copy(float4* __restrict__ d, const float4* __restrict__ s, size_t n) {
    size_t i = (size_t)blockIdx.x * blockDim.x + threadIdx.x;
    size_t stride = (size_t)gridDim.x * blockDim.x;
    for (; i < n; i += stride) d[i] = s[i];
}

__global__ void k_zero(float4* __restrict__ d, size_t n) {
    size_t i = (size_t)blockIdx.x * blockDim.x + threadIdx.x;
    size_t stride = (size_t)gridDim.x * blockDim.x;
    float4 z = make_float4(0.f, 0.f, 0.f, 0.f);
    for (; i < n; i += stride) d[i] = z;
}

// messages: agg[dst] += relu(hin[src] (+vn[batch[src]]) + bond_emb(e)) + 1e-7
__global__ void k_msg(const float* __restrict__ hin, const int* __restrict__ ei,
                      const int* __restrict__ ea, const float* __restrict__ bemb,
                      const int* __restrict__ batch, const float* __restrict__ vn,
                      float* __restrict__ agg) {
    int t = threadIdx.x;
    int e = blockIdx.x * 4 + (t >> 6);
    if (e >= EE) return;
    int c = (t & 63) << 2;
    int src = ei[e];
    int dst = ei[EE + e];
    int a0 = ea[e * 3 + 0], a1 = ea[e * 3 + 1], a2 = ea[e * 3 + 2];
    float4 hv = *(const float4*)&hin[(size_t)src * HH + c];
    if (vn) {
        float4 vv = *(const float4*)&vn[(size_t)batch[src] * HH + c];
        hv.x += vv.x; hv.y += vv.y; hv.z += vv.z; hv.w += vv.w;
    }
    float4 b0 = *(const float4*)&bemb[(size_t)(0 * 8 + a0) * HH + c];
    float4 b1 = *(const float4*)&bemb[(size_t)(1 * 8 + a1) * HH + c];
    float4 b2 = *(const float4*)&bemb[(size_t)(2 * 8 + a2) * HH + c];
    float4 m;
    m.x = fmaxf(hv.x + b0.x + b1.x + b2.x, 0.f) + 1e-7f;
    m.y = fmaxf(hv.y + b0.y + b1.y + b2.y, 0.f) + 1e-7f;
    m.z = fmaxf(hv.z + b0.z + b1.z + b2.z, 0.f) + 1e-7f;
    m.w = fmaxf(hv.w + b0.w + b1.w + b2.w, 0.f) + 1e-7f;
    red_add4(&agg[(size_t)dst * HH + c], m);
}

// ---------------- BatchNorm finalize (stats come from GEMM epilogues) -----------
__global__ void k_bnfin(const float* __restrict__ gamma, const float* __restrict__ beta,
                        float invM) {
    int c = threadIdx.x;
    float mu = g_sum[c] * invM;
    float var = g_sq[c] * invM - mu * mu;
    float sc = gamma[c] * rsqrtf(var + 1e-5f);
    g_scale[c] = sc;
    g_shift[c] = beta[c] - mu * sc;
    g_sum[c] = 0.f;
    g_sq[c] = 0.f;
}

// h2 = relu(bn(h)); pool[batch[n]] += h2 (pool pre-init to vn); msg = 0
__global__ void k_bnapp_pool(const float* __restrict__ X, float* __restrict__ Y,
                             const int* __restrict__ batch, float* __restrict__ pool,
                             float* __restrict__ msg) {
    int t = threadIdx.x;
    int n = blockIdx.x * 4 + (t >> 6);
    if (n >= NN) return;
    int c = (t & 63) << 2;
    float4 xv = *(const float4*)&X[(size_t)n * HH + c];
    float4 sc = *(const float4*)&g_scale[c];
    float4 sh = *(const float4*)&g_shift[c];
    float4 v;
    v.x = fmaxf(fmaf(xv.x, sc.x, sh.x), 0.f);
    v.y = fmaxf(fmaf(xv.y, sc.y, sh.y), 0.f);
    v.z = fmaxf(fmaf(xv.z, sc.z, sh.z), 0.f);
    v.w = fmaxf(fmaf(xv.w, sc.w, sh.w), 0.f);
    *(float4*)&Y[(size_t)n * HH + c] = v;
    *(float4*)&msg[(size_t)n * HH + c] = make_float4(0.f, 0.f, 0.f, 0.f);
    red_add4(&pool[(size_t)batch[n] * HH + c], v);
}

// Y = relu(bn(X)) over M rows (vn MLP)
__global__ void k_bnrelu(const float* __restrict__ X, float* __restrict__ Y, int M) {
    int t = threadIdx.x;
    int n = blockIdx.x * 4 + (t >> 6);
    if (n >= M) return;
    int c = (t & 63) << 2;
    size_t o = (size_t)n * HH + c;
    float4 xv = *(const float4*)&X[o];
    float4 sc = *(const float4*)&g_scale[c];
    float4 sh = *(const float4*)&g_shift[c];
    float4 v;
    v.x = fmaxf(fmaf(xv.x, sc.x, sh.x), 0.f);
    v.y = fmaxf(fmaf(xv.y, sc.y, sh.y), 0.f);
    v.z = fmaxf(fmaf(xv.z, sc.z, sh.z), 0.f);
    v.w = fmaxf(fmaf(xv.w, sc.w, sh.w), 0.f);
    *(float4*)&Y[o] = v;
}

// out[batch[n]] += bn(h[n])  (final pooling; no relu)
__global__ void k_outpool(const float* __restrict__ X, const int* __restrict__ batch,
                          float* __restrict__ out) {
    int t = threadIdx.x;
    int n = blockIdx.x * 4 + (t >> 6);
    if (n >= NN) return;
    int c = (t & 63) << 2;
    float4 xv = *(const float4*)&X[(size_t)n * HH + c];
    float4 sc = *(const float4*)&g_scale[c];
    float4 sh = *(const float4*)&g_shift[c];
    float4 v;
    v.x = fmaf(xv.x, sc.x, sh.x);
    v.y = fmaf(xv.y, sc.y, sh.y);
    v.z = fmaf(xv.z, sc.z, sh.z);
    v.w = fmaf(xv.w, sc.w, sh.w);
    red_add4(&out[(size_t)batch[n] * HH + c], v);
}

// ---------------- host orchestration ----------------
extern "C" void kernel_launch(void* const* d_in, const int* in_sizes, int n_in,
                              void* d_out, int out_size) {
    const int* x = (const int*)d_in[0];
    const int* ei = (const int*)d_in[1];
    const int* ea = (const int*)d_in[2];
    const int* batch = (const int*)d_in[3];
    const float* aemb = (const float*)d_in[4];
    const float* bemb = (const float*)d_in[5];
    const float* vnw = (const float*)d_in[6];
    const float* cw = (const float*)d_in[7];
    const float* cb = (const float*)d_in[8];
    const float* ng = (const float*)d_in[9];
    const float* nbt = (const float*)d_in[10];
    const float* vw = (const float*)d_in[11];
    const float* vb = (const float*)d_in[12];
    const float* vg = (const float*)d_in[13];
    const float* vbt = (const float*)d_in[14];
    float* out = (float*)d_out;

    float *ph, *ph2, *pmsg, *pvn, *ppool, *pvtmp;
    __nv_bfloat16* pbw;
    cudaGetSymbolAddress((void**)&ph, g_h);
    cudaGetSymbolAddress((void**)&ph2, g_h2);
    cudaGetSymbolAddress((void**)&pmsg, g_msg);
    cudaGetSymbolAddress((void**)&pvn, g_vn);
    cudaGetSymbolAddress((void**)&ppool, g_pool);
    cudaGetSymbolAddress((void**)&pvtmp, g_vtmp);
    cudaGetSymbolAddress((void**)&pbw, g_bw);

    cudaFuncSetAttribute(k_fgemm, cudaFuncAttributeMaxDynamicSharedMemorySize, FG_SMEM);

    const int gN4 = (NN + 3) / 4;
    const int gE4 = (EE + 3) / 4;
    const size_t GH4 = (size_t)GG * HH / 4;
    const int tilesN = (NN + 127) / 128;
    const int tilesG = GG / 128;
    const size_t WSTRIDE = (size_t)768 * HH;

    // weight prep: conv weights -> mats 0..6, vn weights -> mats 7..18
    k_prepw<<<7 * 256, 256>>>(cw, pbw);
    k_prepw<<<12 * 256, 256>>>(vw, pbw + 7 * WSTRIDE);

    // encode (+ zero msgbuf) + vn init
    k_atom<<<gN4, 256>>>(x, aemb, vnw, ph, pmsg);
    k_vninit<<<GG / 4, 256>>>(pvn, vnw);

    // conv 0: msg into pmsg; h = (h + msg) @ W0 + b0 ; stats accumulated in epilogue
    k_msg<<<gE4, 256>>>(ph, ei, ea, bemb, batch, nullptr, pmsg);
    k_fgemm<<<tilesN, 256, FG_SMEM>>>(ph, pmsg, nullptr, nullptr, pbw, cb, nullptr, ph, NN);

    for (int l = 1; l < 7; ++l) {
        // finalize BN of h (stats from previous GEMM), h2 = relu(bn(h)), pool, msg=0
        k_bnfin<<<1, 256>>>(ng + (l - 1) * HH, nbt + (l - 1) * HH, 1.0f / NN);
        k_copy<<<64, 256>>>((float4*)ppool, (const float4*)pvn, GH4);
        k_bnapp_pool<<<gN4, 256>>>(ph, ph2, batch, ppool, pmsg);

        // vn MLP: two (Linear -> BN -> ReLU), stats fused in GEMM epilogues
        int m0 = 7 + (l - 1) * 2;
        const float* vbl = vb + (size_t)(l - 1) * 2 * HH;
        const float* vgl = vg + (size_t)(l - 1) * 2 * HH;
        const float* vbl2 = vbt + (size_t)(l - 1) * 2 * HH;
        k_fgemm<<<tilesG, 256, FG_SMEM>>>(ppool, nullptr, nullptr, nullptr,
                                          pbw + (size_t)m0 * WSTRIDE, vbl, nullptr, pvtmp, GG);
        k_bnfin<<<1, 256>>>(vgl, vbl2, 1.0f / GG);
        k_bnrelu<<<GG / 4, 256>>>(pvtmp, ppool, GG);
        k_fgemm<<<tilesG, 256, FG_SMEM>>>(ppool, nullptr, nullptr, nullptr,
                                          pbw + (size_t)(m0 + 1) * WSTRIDE, vbl + HH, nullptr,
                                          pvtmp, GG);
        k_bnfin<<<1, 256>>>(vgl + HH, vbl2 + HH, 1.0f / GG);
        k_bnrelu<<<GG / 4, 256>>>(pvtmp, pvn, GG);

        // messages on (h2 + vn[batch]) gathered on the fly; then fused GEMM:
        // h = (h2 + vn[batch] + msg) @ Wl + bl + h
        k_msg<<<gE4, 256>>>(ph2, ei, ea, bemb, batch, pvn, pmsg);
        k_fgemm<<<tilesN, 256, FG_SMEM>>>(ph2, pmsg, batch, pvn,
                                          pbw + (size_t)l * WSTRIDE, cb + l * HH, ph, ph, NN);
    }

    // final BN (stats from last GEMM) + global_add_pool
    k_bnfin<<<1, 256>>>(ng + 6 * HH, nbt + 6 * HH, 1.0f / NN);
    k_zero<<<512, 256>>>((float4*)out, GH4);
    k_outpool<<<gN4, 256>>>(ph, batch, out);
}

// round 6
// speedup vs baseline: 1.6716x; 1.0978x over previous
#include <cuda_runtime.h>
#include <cuda_bf16.h>
#include <cstdint>

#define NN 150000
#define EE 300000
#define GG 4096
#define HH 256
#define NMAT 19

// ---------------- scratch (device globals; no allocations) ----------------
__device__ float g_h[(size_t)NN * HH];
__device__ float g_msg[(size_t)NN * HH];
__device__ float g_vn[GG * HH];
__device__ float g_pool[GG * HH];
__device__ float g_vtmp[GG * HH];
__device__ float g_sum[HH];     // zero at module load; re-zeroed by finalizers
__device__ float g_sq[HH];
__device__ float g_scale[HH];   // node-BN affine
__device__ float g_shift[HH];
__device__ float g_scale2[HH];  // vn-MLP BN affine
__device__ float g_shift2[HH];
// prebuilt B' per matrix: [768][256] bf16 = rows [Bhi ; Bhi ; Blo]
__device__ __align__(16) __nv_bfloat16 g_bw[(size_t)NMAT * 768 * HH];

// ---------------- PTX helpers ----------------
__device__ __forceinline__ uint32_t s2u(const void* p) {
    uint32_t a;
    asm("{ .reg .u64 t; cvta.to.shared.u64 t, %1; cvt.u32.u64 %0, t; }" : "=r"(a) : "l"(p));
    return a;
}
__device__ __forceinline__ void cpasync16(uint32_t dst, const void* src) {
    asm volatile("cp.async.cg.shared.global [%0], [%1], 16;" :: "r"(dst), "l"(src));
}
__device__ __forceinline__ void cp_commit() {
    asm volatile("cp.async.commit_group;" ::: "memory");
}
__device__ __forceinline__ void cp_wait1() {
    asm volatile("cp.async.wait_group 1;" ::: "memory");
}
__device__ __forceinline__ void ldsm4(uint32_t a, uint32_t& r0, uint32_t& r1, uint32_t& r2,
                                      uint32_t& r3) {
    asm volatile("ldmatrix.sync.aligned.m8n8.x4.shared.b16 {%0,%1,%2,%3}, [%4];"
                 : "=r"(r0), "=r"(r1), "=r"(r2), "=r"(r3) : "r"(a));
}
__device__ __forceinline__ void ldsm4t(uint32_t a, uint32_t& r0, uint32_t& r1, uint32_t& r2,
                                       uint32_t& r3) {
    asm volatile("ldmatrix.sync.aligned.m8n8.x4.trans.shared.b16 {%0,%1,%2,%3}, [%4];"
                 : "=r"(r0), "=r"(r1), "=r"(r2), "=r"(r3) : "r"(a));
}
__device__ __forceinline__ void mma16816(float* c, const uint32_t* a, uint32_t b0, uint32_t b1) {
    asm volatile(
        "mma.sync.aligned.m16n8k16.row.col.f32.bf16.bf16.f32 "
        "{%0,%1,%2,%3}, {%4,%5,%6,%7}, {%8,%9}, {%0,%1,%2,%3};"
        : "+f"(c[0]), "+f"(c[1]), "+f"(c[2]), "+f"(c[3])
        : "r"(a[0]), "r"(a[1]), "r"(a[2]), "r"(a[3]), "r"(b0), "r"(b1));
}
__device__ __forceinline__ void red_add4(float* p, float4 v) {
    asm volatile("red.global.add.v4.f32 [%0], {%1, %2, %3, %4};"
                 :: "l"(p), "f"(v.x), "f"(v.y), "f"(v.z), "f"(v.w) : "memory");
}
__device__ __forceinline__ void red_addf(float* p, float v) {
    asm volatile("red.global.add.f32 [%0], %1;" :: "l"(p), "f"(v) : "memory");
}
__device__ __forceinline__ uint32_t pkbf(float a, float b) {
    __nv_bfloat16 h0 = __float2bfloat16(a), h1 = __float2bfloat16(b);
    return (uint32_t)__bfloat16_as_ushort(h0) | ((uint32_t)__bfloat16_as_ushort(h1) << 16);
}

// ---------------- weight prep: W[k][n] fp32 -> B'[768][256] bf16 ----------------
__global__ void k_prepw(const float* __restrict__ W, __nv_bfloat16* __restrict__ out,
                        int nmat) {
    int b = blockIdx.x;
    int mat = b >> 8;
    if (mat >= nmat) return;
    int k = b & 255;
    int n = threadIdx.x;
    float v = W[(size_t)mat * 65536 + k * 256 + n];
    __nv_bfloat16 h = __float2bfloat16(v);
    __nv_bfloat16 l = __float2bfloat16(v - __bfloat162float(h));
    size_t base = (size_t)mat * 768 * 256;
    out[base + (size_t)k * 256 + n] = h;
    out[base + (size_t)(k + 256) * 256 + n] = h;
    out[base + (size_t)(k + 512) * 256 + n] = l;
}

// ---------------- big fused bf16 HMMA GEMM (BM=128) -----------------------------
// C[M,256] = (bnrelu?(X) + MS? + VN[bt]?)[M,256] @ B'[768,256] + bias (+R)
// Epilogue accumulates per-channel sum/sumsq into g_sum/g_sq.
#define BSTG 16384
#define FG_SMEM (131072 + 3 * BSTG)
#define NKC 24

__device__ __forceinline__ void bg_issue(int kc, uint32_t bb0, int tid,
                                         const __nv_bfloat16* __restrict__ Bw) {
    uint32_t bbase = bb0 + (uint32_t)(kc % 3) * BSTG;
    const __nv_bfloat16* bsrc = Bw + (size_t)kc * 32 * 256;
#pragma unroll
    for (int i = 0; i < 4; ++i) {
        int f = tid + i * 256;
        int k = f >> 5, c = f & 31;
        uint32_t dst = bbase + k * 512 + ((c ^ (k & 7)) << 4);
        cpasync16(dst, bsrc + k * 256 + c * 8);
    }
    cp_commit();
}

__global__ void __launch_bounds__(256, 1)
k_fgemm(const float* __restrict__ X, const float* __restrict__ MS,
        const int* __restrict__ bt, const float* __restrict__ VN,
        const __nv_bfloat16* __restrict__ Bw, const float* __restrict__ bias,
        const float* __restrict__ R, float* __restrict__ C, int M, int bnX) {
    extern __shared__ char sm[];
    uint32_t sb = s2u(sm);
    int tid = threadIdx.x;
    int lane = tid & 31;
    int wid = tid >> 5;
    int wm = wid & 1;
    int wn = wid >> 1;
    int row0 = blockIdx.x * 128;

    bg_issue(0, sb + 131072u, tid, Bw);
    bg_issue(1, sb + 131072u, tid, Bw);

    // A load (fp32, fused bn-relu + sum of sources) + split hi/lo into SMEM
#pragma unroll 4
    for (int it = 0; it < 16; ++it) {
        int f = tid + it * 256;
        int r = f >> 5, ci = f & 31;
        int row = row0 + r;
        float v[8];
        if (row < M) {
            size_t o = (size_t)row * 256 + ci * 8;
            float4 a0 = *(const float4*)&X[o];
            float4 a1 = *(const float4*)&X[o + 4];
            v[0] = a0.x; v[1] = a0.y; v[2] = a0.z; v[3] = a0.w;
            v[4] = a1.x; v[5] = a1.y; v[6] = a1.z; v[7] = a1.w;
            if (bnX) {
                float4 s0 = *(const float4*)&g_scale[ci * 8];
                float4 s1 = *(const float4*)&g_scale[ci * 8 + 4];
                float4 t0 = *(const float4*)&g_shift[ci * 8];
                float4 t1 = *(const float4*)&g_shift[ci * 8 + 4];
                v[0] = fmaxf(fmaf(v[0], s0.x, t0.x), 0.f);
                v[1] = fmaxf(fmaf(v[1], s0.y, t0.y), 0.f);
                v[2] = fmaxf(fmaf(v[2], s0.z, t0.z), 0.f);
                v[3] = fmaxf(fmaf(v[3], s0.w, t0.w), 0.f);
                v[4] = fmaxf(fmaf(v[4], s1.x, t1.x), 0.f);
                v[5] = fmaxf(fmaf(v[5], s1.y, t1.y), 0.f);
                v[6] = fmaxf(fmaf(v[6], s1.z, t1.z), 0.f);
                v[7] = fmaxf(fmaf(v[7], s1.w, t1.w), 0.f);
            }
            if (MS) {
                float4 m0 = *(const float4*)&MS[o];
                float4 m1 = *(const float4*)&MS[o + 4];
                v[0] += m0.x; v[1] += m0.y; v[2] += m0.z; v[3] += m0.w;
                v[4] += m1.x; v[5] += m1.y; v[6] += m1.z; v[7] += m1.w;
            }
            if (VN) {
                size_t vo = (size_t)bt[row] * 256 + ci * 8;
                float4 w0 = *(const float4*)&VN[vo];
                float4 w1 = *(const float4*)&VN[vo + 4];
                v[0] += w0.x; v[1] += w0.y; v[2] += w0.z; v[3] += w0.w;
                v[4] += w1.x; v[5] += w1.y; v[6] += w1.z; v[7] += w1.w;
            }
        } else {
#pragma unroll
            for (int i = 0; i < 8; ++i) v[i] = 0.f;
        }
        uint32_t hw[4], lw[4];
#pragma unroll
        for (int i = 0; i < 4; ++i) {
            float x = v[2 * i], y = v[2 * i + 1];
            float hx = __bfloat162float(__float2bfloat16(x));
            float hy = __bfloat162float(__float2bfloat16(y));
            hw[i] = pkbf(x, y);
            lw[i] = pkbf(x - hx, y - hy);
        }
        uint32_t off = (uint32_t)(r * 512) + (uint32_t)((ci ^ (r & 7)) << 4);
        asm volatile("st.shared.v4.b32 [%0], {%1,%2,%3,%4};"
                     :: "r"(sb + off), "r"(hw[0]), "r"(hw[1]), "r"(hw[2]), "r"(hw[3]));
        asm volatile("st.shared.v4.b32 [%0], {%1,%2,%3,%4};"
                     :: "r"(sb + 65536u + off), "r"(lw[0]), "r"(lw[1]), "r"(lw[2]), "r"(lw[3]));
    }

    float acc[4][8][4];
#pragma unroll
    for (int mi = 0; mi < 4; ++mi)
#pragma unroll
        for (int ni = 0; ni < 8; ++ni)
#pragma unroll
            for (int q = 0; q < 4; ++q) acc[mi][ni][q] = 0.f;

    for (int kc = 0; kc < NKC; ++kc) {
        cp_wait1();
        __syncthreads();
        if (kc + 2 < NKC) bg_issue(kc + 2, sb + 131072u, tid, Bw);
        else cp_commit();

        uint32_t abase = sb + ((kc >= 8 && kc < 16) ? 65536u : 0u);
        int cb8 = (kc & 7) * 4;
        uint32_t bbase = sb + 131072u + (uint32_t)(kc % 3) * BSTG;
#pragma unroll
        for (int ks = 0; ks < 2; ++ks) {
            uint32_t afr[4][4];
            int rl = lane & 15;
            int ci = cb8 + ks * 2 + (lane >> 4);
#pragma unroll
            for (int mi = 0; mi < 4; ++mi) {
                int r = wm * 64 + mi * 16 + rl;
                uint32_t addr = abase + r * 512 + ((ci ^ (r & 7)) << 4);
                ldsm4(addr, afr[mi][0], afr[mi][1], afr[mi][2], afr[mi][3]);
            }
            uint32_t bfr[4][4];
            int kb = ks * 16 + (lane & 15);
#pragma unroll
            for (int nj = 0; nj < 4; ++nj) {
                int n = wn * 64 + nj * 16 + ((lane >> 4) << 3);
                int cN = n >> 3;
                uint32_t addr = bbase + kb * 512 + ((cN ^ (kb & 7)) << 4);
                ldsm4t(addr, bfr[nj][0], bfr[nj][1], bfr[nj][2], bfr[nj][3]);
            }
#pragma unroll
            for (int mi = 0; mi < 4; ++mi)
#pragma unroll
                for (int nj = 0; nj < 4; ++nj) {
                    mma16816(acc[mi][nj * 2 + 0], afr[mi], bfr[nj][0], bfr[nj][1]);
                    mma16816(acc[mi][nj * 2 + 1], afr[mi], bfr[nj][2], bfr[nj][3]);
                }
        }
    }

    // epilogue: bias (+R) write, plus per-channel sum / sumsq accumulation
    int r_c = lane >> 2;
    int c_c = (lane & 3) * 2;
    float bv[8][2];
#pragma unroll
    for (int ni = 0; ni < 8; ++ni) {
        int gc = wn * 64 + ni * 8 + c_c;
        bv[ni][0] = bias[gc];
        bv[ni][1] = bias[gc + 1];
    }
    float ss[8][2], qq[8][2];
#pragma unroll
    for (int ni = 0; ni < 8; ++ni) {
        ss[ni][0] = ss[ni][1] = 0.f;
        qq[ni][0] = qq[ni][1] = 0.f;
    }
#pragma unroll
    for (int mi = 0; mi < 4; ++mi) {
        int gr0 = row0 + wm * 64 + mi * 16 + r_c;
        int gr1 = gr0 + 8;
#pragma unroll
        for (int ni = 0; ni < 8; ++ni) {
            int gc = wn * 64 + ni * 8 + c_c;
            if (gr0 < M) {
                size_t o = (size_t)gr0 * 256 + gc;
                float x0 = acc[mi][ni][0] + bv[ni][0];
                float x1 = acc[mi][ni][1] + bv[ni][1];
                if (R) { float2 rv = *(const float2*)&R[o]; x0 += rv.x; x1 += rv.y; }
                *(float2*)&C[o] = make_float2(x0, x1);
                ss[ni][0] += x0; qq[ni][0] += x0 * x0;
                ss[ni][1] += x1; qq[ni][1] += x1 * x1;
            }
            if (gr1 < M) {
                size_t o = (size_t)gr1 * 256 + gc;
                float x2 = acc[mi][ni][2] + bv[ni][0];
                float x3 = acc[mi][ni][3] + bv[ni][1];
                if (R) { float2 rv = *(const float2*)&R[o]; x2 += rv.x; x3 += rv.y; }
                *(float2*)&C[o] = make_float2(x2, x3);
                ss[ni][0] += x2; qq[ni][0] += x2 * x2;
                ss[ni][1] += x3; qq[ni][1] += x3 * x3;
            }
        }
    }
#pragma unroll
    for (int ni = 0; ni < 8; ++ni)
#pragma unroll
        for (int j = 0; j < 2; ++j) {
            float s = ss[ni][j], q = qq[ni][j];
            s += __shfl_xor_sync(0xffffffffu, s, 4);
            s += __shfl_xor_sync(0xffffffffu, s, 8);
            s += __shfl_xor_sync(0xffffffffu, s, 16);
            q += __shfl_xor_sync(0xffffffffu, q, 4);
            q += __shfl_xor_sync(0xffffffffu, q, 8);
            q += __shfl_xor_sync(0xffffffffu, q, 16);
            ss[ni][j] = s; qq[ni][j] = q;
        }
    if (r_c == 0) {
#pragma unroll
        for (int ni = 0; ni < 8; ++ni) {
            int gc = wn * 64 + ni * 8 + c_c;
            red_addf(&g_sum[gc], ss[ni][0]);
            red_addf(&g_sum[gc + 1], ss[ni][1]);
            red_addf(&g_sq[gc], qq[ni][0]);
            red_addf(&g_sq[gc + 1], qq[ni][1]);
        }
    }
}

// ---------------- small GEMM (BM=32) for vn-MLP, 128 CTAs -----------------------
// C[M,256] = (bnrelu2?(X))[M,256] @ B'[768,256] + bias; stats into g_sum/g_sq.
#define SG_SMEM (32768 + 3 * BSTG)

__global__ void __launch_bounds__(256, 1)
k_sgemm(const float* __restrict__ X, const __nv_bfloat16* __restrict__ Bw,
        const float* __restrict__ bias, float* __restrict__ C, int M, int bnX) {
    extern __shared__ char sm[];
    uint32_t sb = s2u(sm);
    int tid = threadIdx.x;
    int lane = tid & 31;
    int wn = tid >> 5;   // 8 N-warps of 32 cols
    int row0 = blockIdx.x * 32;

    bg_issue(0, sb + 32768u, tid, Bw);
    bg_issue(1, sb + 32768u, tid, Bw);

#pragma unroll
    for (int it = 0; it < 4; ++it) {
        int f = tid + it * 256;
        int r = f >> 5, ci = f & 31;
        int row = row0 + r;
        float v[8];
        if (row < M) {
            size_t o = (size_t)row * 256 + ci * 8;
            float4 a0 = *(const float4*)&X[o];
            float4 a1 = *(const float4*)&X[o + 4];
            v[0] = a0.x; v[1] = a0.y; v[2] = a0.z; v[3] = a0.w;
            v[4] = a1.x; v[5] = a1.y; v[6] = a1.z; v[7] = a1.w;
            if (bnX) {
                float4 s0 = *(const float4*)&g_scale2[ci * 8];
                float4 s1 = *(const float4*)&g_scale2[ci * 8 + 4];
                float4 t0 = *(const float4*)&g_shift2[ci * 8];
                float4 t1 = *(const float4*)&g_shift2[ci * 8 + 4];
                v[0] = fmaxf(fmaf(v[0], s0.x, t0.x), 0.f);
                v[1] = fmaxf(fmaf(v[1], s0.y, t0.y), 0.f);
                v[2] = fmaxf(fmaf(v[2], s0.z, t0.z), 0.f);
                v[3] = fmaxf(fmaf(v[3], s0.w, t0.w), 0.f);
                v[4] = fmaxf(fmaf(v[4], s1.x, t1.x), 0.f);
                v[5] = fmaxf(fmaf(v[5], s1.y, t1.y), 0.f);
                v[6] = fmaxf(fmaf(v[6], s1.z, t1.z), 0.f);
                v[7] = fmaxf(fmaf(v[7], s1.w, t1.w), 0.f);
            }
        } else {
#pragma unroll
            for (int i = 0; i < 8; ++i) v[i] = 0.f;
        }
        uint32_t hw[4], lw[4];
#pragma unroll
        for (int i = 0; i < 4; ++i) {
            float x = v[2 * i], y = v[2 * i + 1];
            float hx = __bfloat162float(__float2bfloat16(x));
            float hy = __bfloat162float(__float2bfloat16(y));
            hw[i] = pkbf(x, y);
            lw[i] = pkbf(x - hx, y - hy);
        }
        uint32_t off = (uint32_t)(r * 512) + (uint32_t)((ci ^ (r & 7)) << 4);
        asm volatile("st.shared.v4.b32 [%0], {%1,%2,%3,%4};"
                     :: "r"(sb + off), "r"(hw[0]), "r"(hw[1]), "r"(hw[2]), "r"(hw[3]));
        asm volatile("st.shared.v4.b32 [%0], {%1,%2,%3,%4};"
                     :: "r"(sb + 16384u + off), "r"(lw[0]), "r"(lw[1]), "r"(lw[2]), "r"(lw[3]));
    }

    float acc[2][4][4];
#pragma unroll
    for (int mi = 0; mi < 2; ++mi)
#pragma unroll
        for (int ni = 0; ni < 4; ++ni)
#pragma unroll
            for (int q = 0; q < 4; ++q) acc[mi][ni][q] = 0.f;

    for (int kc = 0; kc < NKC; ++kc) {
        cp_wait1();
        __syncthreads();
        if (kc + 2 < NKC) bg_issue(kc + 2, sb + 32768u, tid, Bw);
        else cp_commit();

        uint32_t abase = sb + ((kc >= 8 && kc < 16) ? 16384u : 0u);
        int cb8 = (kc & 7) * 4;
        uint32_t bbase = sb + 32768u + (uint32_t)(kc % 3) * BSTG;
#pragma unroll
        for (int ks = 0; ks < 2; ++ks) {
            uint32_t afr[2][4];
            int rl = lane & 15;
            int ci = cb8 + ks * 2 + (lane >> 4);
#pragma unroll
            for (int mi = 0; mi < 2; ++mi) {
                int r = mi * 16 + rl;
                uint32_t addr = abase + r * 512 + ((ci ^ (r & 7)) << 4);
                ldsm4(addr, afr[mi][0], afr[mi][1], afr[mi][2], afr[mi][3]);
            }
            uint32_t bfr[2][4];
            int kb = ks * 16 + (lane & 15);
#pragma unroll
            for (int nj = 0; nj < 2; ++nj) {
                int n = wn * 32 + nj * 16 + ((lane >> 4) << 3);
                int cN = n >> 3;
                uint32_t addr = bbase + kb * 512 + ((cN ^ (kb & 7)) << 4);
                ldsm4t(addr, bfr[nj][0], bfr[nj][1], bfr[nj][2], bfr[nj][3]);
            }
#pragma unroll
            for (int mi = 0; mi < 2; ++mi)
#pragma unroll
                for (int nj = 0; nj < 2; ++nj) {
                    mma16816(acc[mi][nj * 2 + 0], afr[mi], bfr[nj][0], bfr[nj][1]);
                    mma16816(acc[mi][nj * 2 + 1], afr[mi], bfr[nj][2], bfr[nj][3]);
                }
        }
    }

    int r_c = lane >> 2;
    int c_c = (lane & 3) * 2;
    float ss[4][2], qq[4][2];
#pragma unroll
    for (int ni = 0; ni < 4; ++ni) {
        ss[ni][0] = ss[ni][1] = 0.f;
        qq[ni][0] = qq[ni][1] = 0.f;
    }
#pragma unroll
    for (int mi = 0; mi < 2; ++mi) {
        int gr0 = row0 + mi * 16 + r_c;
        int gr1 = gr0 + 8;
#pragma unroll
        for (int ni = 0; ni < 4; ++ni) {
            int gc = wn * 32 + ni * 8 + c_c;
            float b0 = bias[gc], b1 = bias[gc + 1];
            if (gr0 < M) {
                size_t o = (size_t)gr0 * 256 + gc;
                float x0 = acc[mi][ni][0] + b0;
                float x1 = acc[mi][ni][1] + b1;
                *(float2*)&C[o] = make_float2(x0, x1);
                ss[ni][0] += x0; qq[ni][0] += x0 * x0;
                ss[ni][1] += x1; qq[ni][1] += x1 * x1;
            }
            if (gr1 < M) {
                size_t o = (size_t)gr1 * 256 + gc;
                float x2 = acc[mi][ni][2] + b0;
                float x3 = acc[mi][ni][3] + b1;
                *(float2*)&C[o] = make_float2(x2, x3);
                ss[ni][0] += x2; qq[ni][0] += x2 * x2;
                ss[ni][1] += x3; qq[ni][1] += x3 * x3;
            }
        }
    }
#pragma unroll
    for (int ni = 0; ni < 4; ++ni)
#pragma unroll
        for (int j = 0; j < 2; ++j) {
            float s = ss[ni][j], q = qq[ni][j];
            s += __shfl_xor_sync(0xffffffffu, s, 4);
            s += __shfl_xor_sync(0xffffffffu, s, 8);
            s += __shfl_xor_sync(0xffffffffu, s, 16);
            q += __shfl_xor_sync(0xffffffffu, q, 4);
            q += __shfl_xor_sync(0xffffffffu, q, 8);
            q += __shfl_xor_sync(0xffffffffu, q, 16);
            ss[ni][j] = s; qq[ni][j] = q;
        }
    if (r_c == 0) {
#pragma unroll
        for (int ni = 0; ni < 4; ++ni) {
            int gc = wn * 32 + ni * 8 + c_c;
            red_addf(&g_sum[gc], ss[ni][0]);
            red_addf(&g_sum[gc + 1], ss[ni][1]);
            red_addf(&g_sq[gc], qq[ni][0]);
            red_addf(&g_sq[gc + 1], qq[ni][1]);
        }
    }
}

// ---------------- elementwise / encode kernels ----------------
__global__ void k_atom(const int* __restrict__ x, const float* __restrict__ aemb,
                       const float* __restrict__ vnw, float* __restrict__ h,
                       float* __restrict__ msg) {
    int t = threadIdx.x;
    int n = blockIdx.x * 4 + (t >> 6);
    if (n >= NN) return;
    int c = (t & 63) << 2;
    float4 s = *(const float4*)&vnw[c];
#pragma unroll
    for (int f = 0; f < 9; ++f) {
        int v = x[n * 9 + f];
        float4 ev = *(const float4*)&aemb[(size_t)((f << 6) + v) * HH + c];
        s.x += ev.x; s.y += ev.y; s.z += ev.z; s.w += ev.w;
    }
    *(float4*)&h[(size_t)n * HH + c] = s;
    *(float4*)&msg[(size_t)n * HH + c] = make_float4(0.f, 0.f, 0.f, 0.f);
}

__global__ void k_vninit(float* __restrict__ vn, const float* __restrict__ vnw) {
    int t = threadIdx.x;
    int g = blockIdx.x * 4 + (t >> 6);
    int c = (t & 63) << 2;
    *(float4*)&vn[(size_t)g * HH + c] = *(const float4*)&vnw[c];
}

__global__ void k_zero(float4* __restrict__ d, size_t n) {
    size_t i = (size_t)blockIdx.x * blockDim.x + threadIdx.x;
    size_t stride = (size_t)gridDim.x * blockDim.x;
    float4 z = make_float4(0.f, 0.f, 0.f, 0.f);
    for (; i < n; i += stride) d[i] = z;
}

// messages: agg[dst] += relu(bn?(h[src]) (+vn[batch[src]]) + bond) + 1e-7
__global__ void k_msg(const float* __restrict__ hin, const int* __restrict__ ei,
                      const int* __restrict__ ea, const float* __restrict__ bemb,
                      const int* __restrict__ batch, const float* __restrict__ vn,
                      float* __restrict__ agg, int bnflag) {
    int t = threadIdx.x;
    int e = blockIdx.x * 4 + (t >> 6);
    if (e >= EE) return;
    int c = (t & 63) << 2;
    int src = ei[e];
    int dst = ei[EE + e];
    int a0 = ea[e * 3 + 0], a1 = ea[e * 3 + 1], a2 = ea[e * 3 + 2];
    float4 hv = *(const float4*)&hin[(size_t)src * HH + c];
    if (bnflag) {
        float4 sc = *(const float4*)&g_scale[c];
        float4 sh = *(const float4*)&g_shift[c];
        hv.x = fmaxf(fmaf(hv.x, sc.x, sh.x), 0.f);
        hv.y = fmaxf(fmaf(hv.y, sc.y, sh.y), 0.f);
        hv.z = fmaxf(fmaf(hv.z, sc.z, sh.z), 0.f);
        hv.w = fmaxf(fmaf(hv.w, sc.w, sh.w), 0.f);
    }
    if (vn) {
        float4 vv = *(const float4*)&vn[(size_t)batch[src] * HH + c];
        hv.x += vv.x; hv.y += vv.y; hv.z += vv.z; hv.w += vv.w;
    }
    float4 b0 = *(const float4*)&bemb[(size_t)(0 * 8 + a0) * HH + c];
    float4 b1 = *(const float4*)&bemb[(size_t)(1 * 8 + a1) * HH + c];
    float4 b2 = *(const float4*)&bemb[(size_t)(2 * 8 + a2) * HH + c];
    float4 m;
    m.x = fmaxf(hv.x + b0.x + b1.x + b2.x, 0.f) + 1e-7f;
    m.y = fmaxf(hv.y + b0.y + b1.y + b2.y, 0.f) + 1e-7f;
    m.z = fmaxf(hv.z + b0.z + b1.z + b2.z, 0.f) + 1e-7f;
    m.w = fmaxf(hv.w + b0.w + b1.w + b2.w, 0.f) + 1e-7f;
    red_add4(&agg[(size_t)dst * HH + c], m);
}

// ---------------- BN finalizers -------------------------------------------------
// generic: write affine to (osc, osh)
__global__ void k_bnfin(const float* __restrict__ gamma, const float* __restrict__ beta,
                        float invM, float* __restrict__ osc, float* __restrict__ osh) {
    int c = threadIdx.x;
    float mu = g_sum[c] * invM;
    float var = g_sq[c] * invM - mu * mu;
    float sc = gamma[c] * rsqrtf(var + 1e-5f);
    osc[c] = sc;
    osh[c] = beta[c] - mu * sc;
    g_sum[c] = 0.f;
    g_sq[c] = 0.f;
}

// fused: block 0 finalizes node BN into g_scale/g_shift; all blocks copy pool <- vn
__global__ void k_bnfin_pool(const float* __restrict__ gamma, const float* __restrict__ beta,
                             float invM, float4* __restrict__ pool,
                             const float4* __restrict__ vn) {
    if (blockIdx.x == 0) {
        int c = threadIdx.x;
        float mu = g_sum[c] * invM;
        float var = g_sq[c] * invM - mu * mu;
        float sc = gamma[c] * rsqrtf(var + 1e-5f);
        g_scale[c] = sc;
        g_shift[c] = beta[c] - mu * sc;
        g_sum[c] = 0.f;
        g_sq[c] = 0.f;
    }
    size_t n = (size_t)GG * HH / 4;
    size_t stride = (size_t)gridDim.x * blockDim.x;
    for (size_t i = (size_t)blockIdx.x * blockDim.x + threadIdx.x; i < n; i += stride)
        pool[i] = vn[i];
}

// pool[batch[n]] += relu(bn(h[n])); msg = 0
__global__ void k_pool(const float* __restrict__ X, const int* __restrict__ batch,
                       float* __restrict__ pool, float* __restrict__ msg) {
    int t = threadIdx.x;
    int n = blockIdx.x * 4 + (t >> 6);
    if (n >= NN) return;
    int c = (t & 63) << 2;
    float4 xv = *(const float4*)&X[(size_t)n * HH + c];
    float4 sc = *(const float4*)&g_scale[c];
    float4 sh = *(const float4*)&g_shift[c];
    float4 v;
    v.x = fmaxf(fmaf(xv.x, sc.x, sh.x), 0.f);
    v.y = fmaxf(fmaf(xv.y, sc.y, sh.y), 0.f);
    v.z = fmaxf(fmaf(xv.z, sc.z, sh.z), 0.f);
    v.w = fmaxf(fmaf(xv.w, sc.w, sh.w), 0.f);
    *(float4*)&msg[(size_t)n * HH + c] = make_float4(0.f, 0.f, 0.f, 0.f);
    red_add4(&pool[(size_t)batch[n] * HH + c], v);
}

// Y = relu(scale*X + shift)
__global__ void k_bnrelu(const float* __restrict__ X, float* __restrict__ Y,
                         const float* __restrict__ scale, const float* __restrict__ shift,
                         int M) {
    int t = threadIdx.x;
    int n = blockIdx.x * 4 + (t >> 6);
    if (n >= M) return;
    int c = (t & 63) << 2;
    size_t o = (size_t)n * HH + c;
    float4 xv = *(const float4*)&X[o];
    float4 sc = *(const float4*)&scale[c];
    float4 sh = *(const float4*)&shift[c];
    float4 v;
    v.x = fmaxf(fmaf(xv.x, sc.x, sh.x), 0.f);
    v.y = fmaxf(fmaf(xv.y, sc.y, sh.y), 0.f);
    v.z = fmaxf(fmaf(xv.z, sc.z, sh.z), 0.f);
    v.w = fmaxf(fmaf(xv.w, sc.w, sh.w), 0.f);
    *(float4*)&Y[o] = v;
}

// out[batch[n]] += bn(h[n])  (final pooling; no relu)
__global__ void k_outpool(const float* __restrict__ X, const int* __restrict__ batch,
                          float* __restrict__ out) {
    int t = threadIdx.x;
    int n = blockIdx.x * 4 + (t >> 6);
    if (n >= NN) return;
    int c = (t & 63) << 2;
    float4 xv = *(const float4*)&X[(size_t)n * HH + c];
    float4 sc = *(const float4*)&g_scale[c];
    float4 sh = *(const float4*)&g_shift[c];
    float4 v;
    v.x = fmaf(xv.x, sc.x, sh.x);
    v.y = fmaf(xv.y, sc.y, sh.y);
    v.z = fmaf(xv.z, sc.z, sh.z);
    v.w = fmaf(xv.w, sc.w, sh.w);
    red_add4(&out[(size_t)batch[n] * HH + c], v);
}

// ---------------- host orchestration ----------------
extern "C" void kernel_launch(void* const* d_in, const int* in_sizes, int n_in,
                              void* d_out, int out_size) {
    const int* x = (const int*)d_in[0];
    const int* ei = (const int*)d_in[1];
    const int* ea = (const int*)d_in[2];
    const int* batch = (const int*)d_in[3];
    const float* aemb = (const float*)d_in[4];
    const float* bemb = (const float*)d_in[5];
    const float* vnw = (const float*)d_in[6];
    const float* cw = (const float*)d_in[7];
    const float* cb = (const float*)d_in[8];
    const float* ng = (const float*)d_in[9];
    const float* nbt = (const float*)d_in[10];
    const float* vw = (const float*)d_in[11];
    const float* vb = (const float*)d_in[12];
    const float* vg = (const float*)d_in[13];
    const float* vbt = (const float*)d_in[14];
    float* out = (float*)d_out;

    float *ph, *pmsg, *pvn, *ppool, *pvtmp, *pscale, *pshift, *pscale2, *pshift2;
    __nv_bfloat16* pbw;
    cudaGetSymbolAddress((void**)&ph, g_h);
    cudaGetSymbolAddress((void**)&pmsg, g_msg);
    cudaGetSymbolAddress((void**)&pvn, g_vn);
    cudaGetSymbolAddress((void**)&ppool, g_pool);
    cudaGetSymbolAddress((void**)&pvtmp, g_vtmp);
    cudaGetSymbolAddress((void**)&pscale, g_scale);
    cudaGetSymbolAddress((void**)&pshift, g_shift);
    cudaGetSymbolAddress((void**)&pscale2, g_scale2);
    cudaGetSymbolAddress((void**)&pshift2, g_shift2);
    cudaGetSymbolAddress((void**)&pbw, g_bw);

    cudaFuncSetAttribute(k_fgemm, cudaFuncAttributeMaxDynamicSharedMemorySize, FG_SMEM);
    cudaFuncSetAttribute(k_sgemm, cudaFuncAttributeMaxDynamicSharedMemorySize, SG_SMEM);

    const int gN4 = (NN + 3) / 4;
    const int gE4 = (EE + 3) / 4;
    const size_t GH4 = (size_t)GG * HH / 4;
    const int tilesN = (NN + 127) / 128;
    const int tilesG = GG / 32;   // 128 CTAs for small GEMM
    const size_t WSTRIDE = (size_t)768 * HH;

    // ordered so the profiled launch slot lands on the big node GEMM
    k_prepw<<<7 * 256, 256>>>(cw, pbw, 7);                                    // 0
    k_atom<<<gN4, 256>>>(x, aemb, vnw, ph, pmsg);                             // 1
    k_msg<<<gE4, 256>>>(ph, ei, ea, bemb, batch, nullptr, pmsg, 0);           // 2
    k_fgemm<<<tilesN, 256, FG_SMEM>>>(ph, pmsg, nullptr, nullptr, pbw, cb,    // 3
                                      nullptr, ph, NN, 0);
    k_vninit<<<GG / 4, 256>>>(pvn, vnw);                                      // 4
    k_prepw<<<12 * 256, 256>>>(vw, pbw + 7 * WSTRIDE, 12);                    // 5

    for (int l = 1; l < 7; ++l) {
        // node BN finalize (+ pool <- vn), then pool atomics + msg zero
        k_bnfin_pool<<<64, 256>>>(ng + (l - 1) * HH, nbt + (l - 1) * HH, 1.0f / NN,
                                  (float4*)ppool, (const float4*)pvn);
        k_pool<<<gN4, 256>>>(ph, batch, ppool, pmsg);

        // vn MLP: Linear -> BN -> (ReLU fused into next A-load) -> Linear -> BN -> ReLU
        int m0 = 7 + (l - 1) * 2;
        const float* vbl = vb + (size_t)(l - 1) * 2 * HH;
        const float* vgl = vg + (size_t)(l - 1) * 2 * HH;
        const float* vbl2 = vbt + (size_t)(l - 1) * 2 * HH;
        k_sgemm<<<tilesG, 256, SG_SMEM>>>(ppool, pbw + (size_t)m0 * WSTRIDE, vbl,
                                          pvtmp, GG, 0);
        k_bnfin<<<1, 256>>>(vgl, vbl2, 1.0f / GG, pscale2, pshift2);
        k_sgemm<<<tilesG, 256, SG_SMEM>>>(pvtmp, pbw + (size_t)(m0 + 1) * WSTRIDE,
                                          vbl + HH, pvtmp, GG, 1);
        k_bnfin<<<1, 256>>>(vgl + HH, vbl2 + HH, 1.0f / GG, pscale2, pshift2);
        k_bnrelu<<<GG / 4, 256>>>(pvtmp, pvn, pscale2, pshift2, GG);

        // messages on bnrelu(h)+vn gathered on the fly; fused node GEMM:
        // h = (bnrelu(h) + vn[batch] + msg) @ Wl + bl + h
        k_msg<<<gE4, 256>>>(ph, ei, ea, bemb, batch, pvn, pmsg, 1);
        k_fgemm<<<tilesN, 256, FG_SMEM>>>(ph, pmsg, batch, pvn,
                                          pbw + (size_t)l * WSTRIDE, cb + l * HH, ph, ph,
                                          NN, 1);
    }

    // final BN (stats from last GEMM) + global_add_pool
    k_bnfin<<<1, 256>>>(ng + 6 * HH, nbt + 6 * HH, 1.0f / NN, pscale, pshift);
    k_zero<<<512, 256>>>((float4*)out, GH4);
    k_outpool<<<gN4, 256>>>(ph, batch, out);
}

// round 7
// speedup vs baseline: 1.7119x; 1.0241x over previous
#include <cuda_runtime.h>
#include <cuda_bf16.h>
#include <cstdint>

#define NN 150000
#define EE 300000
#define GG 4096
#define HH 256
#define NMAT 19

// ---------------- scratch (device globals; no allocations) ----------------
__device__ float g_h[(size_t)NN * HH];
__device__ float g_msg[(size_t)NN * HH];
__device__ float g_vn[GG * HH];
__device__ float g_pool[GG * HH];
__device__ float g_vtmp[GG * HH];
__device__ float g_sum[HH];     // zero at module load; re-zeroed by finalizers
__device__ float g_sq[HH];
__device__ float g_scale[HH];   // node-BN affine
__device__ float g_shift[HH];
__device__ float g_scale2[HH];  // vn-MLP BN affine
__device__ float g_shift2[HH];
// prebuilt B' per matrix: [768][256] bf16 = rows [Bhi ; Bhi ; Blo]
__device__ __align__(16) __nv_bfloat16 g_bw[(size_t)NMAT * 768 * HH];

// ---------------- PTX helpers ----------------
__device__ __forceinline__ uint32_t s2u(const void* p) {
    uint32_t a;
    asm("{ .reg .u64 t; cvta.to.shared.u64 t, %1; cvt.u32.u64 %0, t; }" : "=r"(a) : "l"(p));
    return a;
}
__device__ __forceinline__ void cpasync16(uint32_t dst, const void* src) {
    asm volatile("cp.async.cg.shared.global [%0], [%1], 16;" :: "r"(dst), "l"(src));
}
__device__ __forceinline__ void cp_commit() {
    asm volatile("cp.async.commit_group;" ::: "memory");
}
__device__ __forceinline__ void cp_wait1() {
    asm volatile("cp.async.wait_group 1;" ::: "memory");
}
__device__ __forceinline__ void ldsm4(uint32_t a, uint32_t& r0, uint32_t& r1, uint32_t& r2,
                                      uint32_t& r3) {
    asm volatile("ldmatrix.sync.aligned.m8n8.x4.shared.b16 {%0,%1,%2,%3}, [%4];"
                 : "=r"(r0), "=r"(r1), "=r"(r2), "=r"(r3) : "r"(a));
}
__device__ __forceinline__ void ldsm4t(uint32_t a, uint32_t& r0, uint32_t& r1, uint32_t& r2,
                                       uint32_t& r3) {
    asm volatile("ldmatrix.sync.aligned.m8n8.x4.trans.shared.b16 {%0,%1,%2,%3}, [%4];"
                 : "=r"(r0), "=r"(r1), "=r"(r2), "=r"(r3) : "r"(a));
}
__device__ __forceinline__ void mma16816(float* c, const uint32_t* a, uint32_t b0, uint32_t b1) {
    asm volatile(
        "mma.sync.aligned.m16n8k16.row.col.f32.bf16.bf16.f32 "
        "{%0,%1,%2,%3}, {%4,%5,%6,%7}, {%8,%9}, {%0,%1,%2,%3};"
        : "+f"(c[0]), "+f"(c[1]), "+f"(c[2]), "+f"(c[3])
        : "r"(a[0]), "r"(a[1]), "r"(a[2]), "r"(a[3]), "r"(b0), "r"(b1));
}
__device__ __forceinline__ void red_add4(float* p, float4 v) {
    asm volatile("red.global.add.v4.f32 [%0], {%1, %2, %3, %4};"
                 :: "l"(p), "f"(v.x), "f"(v.y), "f"(v.z), "f"(v.w) : "memory");
}
__device__ __forceinline__ void red_addf(float* p, float v) {
    asm volatile("red.global.add.f32 [%0], %1;" :: "l"(p), "f"(v) : "memory");
}
__device__ __forceinline__ uint32_t pkbf(float a, float b) {
    __nv_bfloat16 h0 = __float2bfloat16(a), h1 = __float2bfloat16(b);
    return (uint32_t)__bfloat16_as_ushort(h0) | ((uint32_t)__bfloat16_as_ushort(h1) << 16);
}

// ---------------- weight prep: W[k][n] fp32 -> B'[768][256] bf16 ----------------
__global__ void k_prepw(const float* __restrict__ W, __nv_bfloat16* __restrict__ out,
                        int nmat) {
    int b = blockIdx.x;
    int mat = b >> 8;
    if (mat >= nmat) return;
    int k = b & 255;
    int n = threadIdx.x;
    float v = W[(size_t)mat * 65536 + k * 256 + n];
    __nv_bfloat16 h = __float2bfloat16(v);
    __nv_bfloat16 l = __float2bfloat16(v - __bfloat162float(h));
    size_t base = (size_t)mat * 768 * 256;
    out[base + (size_t)k * 256 + n] = h;
    out[base + (size_t)(k + 256) * 256 + n] = h;
    out[base + (size_t)(k + 512) * 256 + n] = l;
}

// ---------------- big fused bf16 HMMA GEMM (BM=128, 512 threads) ----------------
// C[M,256] = (bnrelu?(X) + MS? + VN[bt]?)[M,256] @ B'[768,256] + bias (+R)
// Epilogue accumulates per-channel sum/sumsq into g_sum/g_sq.
#define BSTG 16384
#define FG_SMEM (131072 + 3 * BSTG)
#define NKC 24

__device__ __forceinline__ void bg_issue512(int kc, uint32_t bb0, int tid,
                                            const __nv_bfloat16* __restrict__ Bw) {
    uint32_t bbase = bb0 + (uint32_t)(kc % 3) * BSTG;
    const __nv_bfloat16* bsrc = Bw + (size_t)kc * 32 * 256;
#pragma unroll
    for (int i = 0; i < 2; ++i) {
        int f = tid + i * 512;
        int k = f >> 5, c = f & 31;
        uint32_t dst = bbase + k * 512 + ((c ^ (k & 7)) << 4);
        cpasync16(dst, bsrc + k * 256 + c * 8);
    }
    cp_commit();
}

__device__ __forceinline__ void bg_issue256(int kc, uint32_t bb0, int tid,
                                            const __nv_bfloat16* __restrict__ Bw) {
    uint32_t bbase = bb0 + (uint32_t)(kc % 3) * BSTG;
    const __nv_bfloat16* bsrc = Bw + (size_t)kc * 32 * 256;
#pragma unroll
    for (int i = 0; i < 4; ++i) {
        int f = tid + i * 256;
        int k = f >> 5, c = f & 31;
        uint32_t dst = bbase + k * 512 + ((c ^ (k & 7)) << 4);
        cpasync16(dst, bsrc + k * 256 + c * 8);
    }
    cp_commit();
}

__global__ void __launch_bounds__(512, 1)
k_fgemm(const float* __restrict__ X, const float* __restrict__ MS,
        const int* __restrict__ bt, const float* __restrict__ VN,
        const __nv_bfloat16* __restrict__ Bw, const float* __restrict__ bias,
        const float* __restrict__ R, float* __restrict__ C, int M, int bnX) {
    extern __shared__ char sm[];
    uint32_t sb = s2u(sm);
    int tid = threadIdx.x;
    int lane = tid & 31;
    int wid = tid >> 5;       // 0..15
    int wm = wid & 3;         // 32-row group
    int wn = wid >> 2;        // 64-col group
    int row0 = blockIdx.x * 128;

    bg_issue512(0, sb + 131072u, tid, Bw);
    bg_issue512(1, sb + 131072u, tid, Bw);

    // A load (fp32, fused bn-relu + sum of sources) + split hi/lo into SMEM
#pragma unroll 4
    for (int it = 0; it < 8; ++it) {
        int f = tid + it * 512;
        int r = f >> 5, ci = f & 31;
        int row = row0 + r;
        float v[8];
        if (row < M) {
            size_t o = (size_t)row * 256 + ci * 8;
            float4 a0 = *(const float4*)&X[o];
            float4 a1 = *(const float4*)&X[o + 4];
            v[0] = a0.x; v[1] = a0.y; v[2] = a0.z; v[3] = a0.w;
            v[4] = a1.x; v[5] = a1.y; v[6] = a1.z; v[7] = a1.w;
            if (bnX) {
                float4 s0 = *(const float4*)&g_scale[ci * 8];
                float4 s1 = *(const float4*)&g_scale[ci * 8 + 4];
                float4 t0 = *(const float4*)&g_shift[ci * 8];
                float4 t1 = *(const float4*)&g_shift[ci * 8 + 4];
                v[0] = fmaxf(fmaf(v[0], s0.x, t0.x), 0.f);
                v[1] = fmaxf(fmaf(v[1], s0.y, t0.y), 0.f);
                v[2] = fmaxf(fmaf(v[2], s0.z, t0.z), 0.f);
                v[3] = fmaxf(fmaf(v[3], s0.w, t0.w), 0.f);
                v[4] = fmaxf(fmaf(v[4], s1.x, t1.x), 0.f);
                v[5] = fmaxf(fmaf(v[5], s1.y, t1.y), 0.f);
                v[6] = fmaxf(fmaf(v[6], s1.z, t1.z), 0.f);
                v[7] = fmaxf(fmaf(v[7], s1.w, t1.w), 0.f);
            }
            if (MS) {
                float4 m0 = *(const float4*)&MS[o];
                float4 m1 = *(const float4*)&MS[o + 4];
                v[0] += m0.x; v[1] += m0.y; v[2] += m0.z; v[3] += m0.w;
                v[4] += m1.x; v[5] += m1.y; v[6] += m1.z; v[7] += m1.w;
            }
            if (VN) {
                size_t vo = (size_t)bt[row] * 256 + ci * 8;
                float4 w0 = *(const float4*)&VN[vo];
                float4 w1 = *(const float4*)&VN[vo + 4];
                v[0] += w0.x; v[1] += w0.y; v[2] += w0.z; v[3] += w0.w;
                v[4] += w1.x; v[5] += w1.y; v[6] += w1.z; v[7] += w1.w;
            }
        } else {
#pragma unroll
            for (int i = 0; i < 8; ++i) v[i] = 0.f;
        }
        uint32_t hw[4], lw[4];
#pragma unroll
        for (int i = 0; i < 4; ++i) {
            float x = v[2 * i], y = v[2 * i + 1];
            float hx = __bfloat162float(__float2bfloat16(x));
            float hy = __bfloat162float(__float2bfloat16(y));
            hw[i] = pkbf(x, y);
            lw[i] = pkbf(x - hx, y - hy);
        }
        uint32_t off = (uint32_t)(r * 512) + (uint32_t)((ci ^ (r & 7)) << 4);
        asm volatile("st.shared.v4.b32 [%0], {%1,%2,%3,%4};"
                     :: "r"(sb + off), "r"(hw[0]), "r"(hw[1]), "r"(hw[2]), "r"(hw[3]));
        asm volatile("st.shared.v4.b32 [%0], {%1,%2,%3,%4};"
                     :: "r"(sb + 65536u + off), "r"(lw[0]), "r"(lw[1]), "r"(lw[2]), "r"(lw[3]));
    }

    float acc[2][8][4];
#pragma unroll
    for (int mi = 0; mi < 2; ++mi)
#pragma unroll
        for (int ni = 0; ni < 8; ++ni)
#pragma unroll
            for (int q = 0; q < 4; ++q) acc[mi][ni][q] = 0.f;

    for (int kc = 0; kc < NKC; ++kc) {
        cp_wait1();
        __syncthreads();
        if (kc + 2 < NKC) bg_issue512(kc + 2, sb + 131072u, tid, Bw);
        else cp_commit();

        uint32_t abase = sb + ((kc >= 8 && kc < 16) ? 65536u : 0u);
        int cb8 = (kc & 7) * 4;
        uint32_t bbase = sb + 131072u + (uint32_t)(kc % 3) * BSTG;
#pragma unroll
        for (int ks = 0; ks < 2; ++ks) {
            uint32_t afr[2][4];
            int rl = lane & 15;
            int ci = cb8 + ks * 2 + (lane >> 4);
#pragma unroll
            for (int mi = 0; mi < 2; ++mi) {
                int r = wm * 32 + mi * 16 + rl;
                uint32_t addr = abase + r * 512 + ((ci ^ (r & 7)) << 4);
                ldsm4(addr, afr[mi][0], afr[mi][1], afr[mi][2], afr[mi][3]);
            }
            uint32_t bfr[4][4];
            int kb = ks * 16 + (lane & 15);
#pragma unroll
            for (int nj = 0; nj < 4; ++nj) {
                int n = wn * 64 + nj * 16 + ((lane >> 4) << 3);
                int cN = n >> 3;
                uint32_t addr = bbase + kb * 512 + ((cN ^ (kb & 7)) << 4);
                ldsm4t(addr, bfr[nj][0], bfr[nj][1], bfr[nj][2], bfr[nj][3]);
            }
#pragma unroll
            for (int mi = 0; mi < 2; ++mi)
#pragma unroll
                for (int nj = 0; nj < 4; ++nj) {
                    mma16816(acc[mi][nj * 2 + 0], afr[mi], bfr[nj][0], bfr[nj][1]);
                    mma16816(acc[mi][nj * 2 + 1], afr[mi], bfr[nj][2], bfr[nj][3]);
                }
        }
    }

    // epilogue: bias (+R) write, plus per-channel sum / sumsq accumulation
    int r_c = lane >> 2;
    int c_c = (lane & 3) * 2;
    float ss[8][2], qq[8][2];
#pragma unroll
    for (int ni = 0; ni < 8; ++ni) {
        ss[ni][0] = ss[ni][1] = 0.f;
        qq[ni][0] = qq[ni][1] = 0.f;
    }
#pragma unroll
    for (int mi = 0; mi < 2; ++mi) {
        int gr0 = row0 + wm * 32 + mi * 16 + r_c;
        int gr1 = gr0 + 8;
#pragma unroll
        for (int ni = 0; ni < 8; ++ni) {
            int gc = wn * 64 + ni * 8 + c_c;
            float b0 = bias[gc], b1 = bias[gc + 1];
            if (gr0 < M) {
                size_t o = (size_t)gr0 * 256 + gc;
                float x0 = acc[mi][ni][0] + b0;
                float x1 = acc[mi][ni][1] + b1;
                if (R) { float2 rv = *(const float2*)&R[o]; x0 += rv.x; x1 += rv.y; }
                *(float2*)&C[o] = make_float2(x0, x1);
                ss[ni][0] += x0; qq[ni][0] += x0 * x0;
                ss[ni][1] += x1; qq[ni][1] += x1 * x1;
            }
            if (gr1 < M) {
                size_t o = (size_t)gr1 * 256 + gc;
                float x2 = acc[mi][ni][2] + b0;
                float x3 = acc[mi][ni][3] + b1;
                if (R) { float2 rv = *(const float2*)&R[o]; x2 += rv.x; x3 += rv.y; }
                *(float2*)&C[o] = make_float2(x2, x3);
                ss[ni][0] += x2; qq[ni][0] += x2 * x2;
                ss[ni][1] += x3; qq[ni][1] += x3 * x3;
            }
        }
    }
#pragma unroll
    for (int ni = 0; ni < 8; ++ni)
#pragma unroll
        for (int j = 0; j < 2; ++j) {
            float s = ss[ni][j], q = qq[ni][j];
            s += __shfl_xor_sync(0xffffffffu, s, 4);
            s += __shfl_xor_sync(0xffffffffu, s, 8);
            s += __shfl_xor_sync(0xffffffffu, s, 16);
            q += __shfl_xor_sync(0xffffffffu, q, 4);
            q += __shfl_xor_sync(0xffffffffu, q, 8);
            q += __shfl_xor_sync(0xffffffffu, q, 16);
            ss[ni][j] = s; qq[ni][j] = q;
        }
    if (r_c == 0) {
#pragma unroll
        for (int ni = 0; ni < 8; ++ni) {
            int gc = wn * 64 + ni * 8 + c_c;
            red_addf(&g_sum[gc], ss[ni][0]);
            red_addf(&g_sum[gc + 1], ss[ni][1]);
            red_addf(&g_sq[gc], qq[ni][0]);
            red_addf(&g_sq[gc + 1], qq[ni][1]);
        }
    }
}

// ---------------- small GEMM (BM=32) for vn-MLP, 128 CTAs -----------------------
// C[M,256] = (bnrelu2?(X))[M,256] @ B'[768,256] + bias; stats into g_sum/g_sq.
#define SG_SMEM (32768 + 3 * BSTG)

__global__ void __launch_bounds__(256, 1)
k_sgemm(const float* __restrict__ X, const __nv_bfloat16* __restrict__ Bw,
        const float* __restrict__ bias, float* __restrict__ C, int M, int bnX) {
    extern __shared__ char sm[];
    uint32_t sb = s2u(sm);
    int tid = threadIdx.x;
    int lane = tid & 31;
    int wn = tid >> 5;   // 8 N-warps of 32 cols
    int row0 = blockIdx.x * 32;

    bg_issue256(0, sb + 32768u, tid, Bw);
    bg_issue256(1, sb + 32768u, tid, Bw);

#pragma unroll
    for (int it = 0; it < 4; ++it) {
        int f = tid + it * 256;
        int r = f >> 5, ci = f & 31;
        int row = row0 + r;
        float v[8];
        if (row < M) {
            size_t o = (size_t)row * 256 + ci * 8;
            float4 a0 = *(const float4*)&X[o];
            float4 a1 = *(const float4*)&X[o + 4];
            v[0] = a0.x; v[1] = a0.y; v[2] = a0.z; v[3] = a0.w;
            v[4] = a1.x; v[5] = a1.y; v[6] = a1.z; v[7] = a1.w;
            if (bnX) {
                float4 s0 = *(const float4*)&g_scale2[ci * 8];
                float4 s1 = *(const float4*)&g_scale2[ci * 8 + 4];
                float4 t0 = *(const float4*)&g_shift2[ci * 8];
                float4 t1 = *(const float4*)&g_shift2[ci * 8 + 4];
                v[0] = fmaxf(fmaf(v[0], s0.x, t0.x), 0.f);
                v[1] = fmaxf(fmaf(v[1], s0.y, t0.y), 0.f);
                v[2] = fmaxf(fmaf(v[2], s0.z, t0.z), 0.f);
                v[3] = fmaxf(fmaf(v[3], s0.w, t0.w), 0.f);
                v[4] = fmaxf(fmaf(v[4], s1.x, t1.x), 0.f);
                v[5] = fmaxf(fmaf(v[5], s1.y, t1.y), 0.f);
                v[6] = fmaxf(fmaf(v[6], s1.z, t1.z), 0.f);
                v[7] = fmaxf(fmaf(v[7], s1.w, t1.w), 0.f);
            }
        } else {
#pragma unroll
            for (int i = 0; i < 8; ++i) v[i] = 0.f;
        }
        uint32_t hw[4], lw[4];
#pragma unroll
        for (int i = 0; i < 4; ++i) {
            float x = v[2 * i], y = v[2 * i + 1];
            float hx = __bfloat162float(__float2bfloat16(x));
            float hy = __bfloat162float(__float2bfloat16(y));
            hw[i] = pkbf(x, y);
            lw[i] = pkbf(x - hx, y - hy);
        }
        uint32_t off = (uint32_t)(r * 512) + (uint32_t)((ci ^ (r & 7)) << 4);
        asm volatile("st.shared.v4.b32 [%0], {%1,%2,%3,%4};"
                     :: "r"(sb + off), "r"(hw[0]), "r"(hw[1]), "r"(hw[2]), "r"(hw[3]));
        asm volatile("st.shared.v4.b32 [%0], {%1,%2,%3,%4};"
                     :: "r"(sb + 16384u + off), "r"(lw[0]), "r"(lw[1]), "r"(lw[2]), "r"(lw[3]));
    }

    float acc[2][4][4];
#pragma unroll
    for (int mi = 0; mi < 2; ++mi)
#pragma unroll
        for (int ni = 0; ni < 4; ++ni)
#pragma unroll
            for (int q = 0; q < 4; ++q) acc[mi][ni][q] = 0.f;

    for (int kc = 0; kc < NKC; ++kc) {
        cp_wait1();
        __syncthreads();
        if (kc + 2 < NKC) bg_issue256(kc + 2, sb + 32768u, tid, Bw);
        else cp_commit();

        uint32_t abase = sb + ((kc >= 8 && kc < 16) ? 16384u : 0u);
        int cb8 = (kc & 7) * 4;
        uint32_t bbase = sb + 32768u + (uint32_t)(kc % 3) * BSTG;
#pragma unroll
        for (int ks = 0; ks < 2; ++ks) {
            uint32_t afr[2][4];
            int rl = lane & 15;
            int ci = cb8 + ks * 2 + (lane >> 4);
#pragma unroll
            for (int mi = 0; mi < 2; ++mi) {
                int r = mi * 16 + rl;
                uint32_t addr = abase + r * 512 + ((ci ^ (r & 7)) << 4);
                ldsm4(addr, afr[mi][0], afr[mi][1], afr[mi][2], afr[mi][3]);
            }
            uint32_t bfr[2][4];
            int kb = ks * 16 + (lane & 15);
#pragma unroll
            for (int nj = 0; nj < 2; ++nj) {
                int n = wn * 32 + nj * 16 + ((lane >> 4) << 3);
                int cN = n >> 3;
                uint32_t addr = bbase + kb * 512 + ((cN ^ (kb & 7)) << 4);
                ldsm4t(addr, bfr[nj][0], bfr[nj][1], bfr[nj][2], bfr[nj][3]);
            }
#pragma unroll
            for (int mi = 0; mi < 2; ++mi)
#pragma unroll
                for (int nj = 0; nj < 2; ++nj) {
                    mma16816(acc[mi][nj * 2 + 0], afr[mi], bfr[nj][0], bfr[nj][1]);
                    mma16816(acc[mi][nj * 2 + 1], afr[mi], bfr[nj][2], bfr[nj][3]);
                }
        }
    }

    int r_c = lane >> 2;
    int c_c = (lane & 3) * 2;
    float ss[4][2], qq[4][2];
#pragma unroll
    for (int ni = 0; ni < 4; ++ni) {
        ss[ni][0] = ss[ni][1] = 0.f;
        qq[ni][0] = qq[ni][1] = 0.f;
    }
#pragma unroll
    for (int mi = 0; mi < 2; ++mi) {
        int gr0 = row0 + mi * 16 + r_c;
        int gr1 = gr0 + 8;
#pragma unroll
        for (int ni = 0; ni < 4; ++ni) {
            int gc = wn * 32 + ni * 8 + c_c;
            float b0 = bias[gc], b1 = bias[gc + 1];
            if (gr0 < M) {
                size_t o = (size_t)gr0 * 256 + gc;
                float x0 = acc[mi][ni][0] + b0;
                float x1 = acc[mi][ni][1] + b1;
                *(float2*)&C[o] = make_float2(x0, x1);
                ss[ni][0] += x0; qq[ni][0] += x0 * x0;
                ss[ni][1] += x1; qq[ni][1] += x1 * x1;
            }
            if (gr1 < M) {
                size_t o = (size_t)gr1 * 256 + gc;
                float x2 = acc[mi][ni][2] + b0;
                float x3 = acc[mi][ni][3] + b1;
                *(float2*)&C[o] = make_float2(x2, x3);
                ss[ni][0] += x2; qq[ni][0] += x2 * x2;
                ss[ni][1] += x3; qq[ni][1] += x3 * x3;
            }
        }
    }
#pragma unroll
    for (int ni = 0; ni < 4; ++ni)
#pragma unroll
        for (int j = 0; j < 2; ++j) {
            float s = ss[ni][j], q = qq[ni][j];
            s += __shfl_xor_sync(0xffffffffu, s, 4);
            s += __shfl_xor_sync(0xffffffffu, s, 8);
            s += __shfl_xor_sync(0xffffffffu, s, 16);
            q += __shfl_xor_sync(0xffffffffu, q, 4);
            q += __shfl_xor_sync(0xffffffffu, q, 8);
            q += __shfl_xor_sync(0xffffffffu, q, 16);
            ss[ni][j] = s; qq[ni][j] = q;
        }
    if (r_c == 0) {
#pragma unroll
        for (int ni = 0; ni < 4; ++ni) {
            int gc = wn * 32 + ni * 8 + c_c;
            red_addf(&g_sum[gc], ss[ni][0]);
            red_addf(&g_sum[gc + 1], ss[ni][1]);
            red_addf(&g_sq[gc], qq[ni][0]);
            red_addf(&g_sq[gc + 1], qq[ni][1]);
        }
    }
}

// ---------------- elementwise / encode kernels ----------------
__global__ void k_atom(const int* __restrict__ x, const float* __restrict__ aemb,
                       const float* __restrict__ vnw, float* __restrict__ h,
                       float* __restrict__ msg) {
    int t = threadIdx.x;
    int n = blockIdx.x * 4 + (t >> 6);
    if (n >= NN) return;
    int c = (t & 63) << 2;
    float4 s = *(const float4*)&vnw[c];
#pragma unroll
    for (int f = 0; f < 9; ++f) {
        int v = x[n * 9 + f];
        float4 ev = *(const float4*)&aemb[(size_t)((f << 6) + v) * HH + c];
        s.x += ev.x; s.y += ev.y; s.z += ev.z; s.w += ev.w;
    }
    *(float4*)&h[(size_t)n * HH + c] = s;
    *(float4*)&msg[(size_t)n * HH + c] = make_float4(0.f, 0.f, 0.f, 0.f);
}

__global__ void k_vninit(float* __restrict__ vn, const float* __restrict__ vnw) {
    int t = threadIdx.x;
    int g = blockIdx.x * 4 + (t >> 6);
    int c = (t & 63) << 2;
    *(float4*)&vn[(size_t)g * HH + c] = *(const float4*)&vnw[c];
}

__global__ void k_zero(float4* __restrict__ d, size_t n) {
    size_t i = (size_t)blockIdx.x * blockDim.x + threadIdx.x;
    size_t stride = (size_t)gridDim.x * blockDim.x;
    float4 z = make_float4(0.f, 0.f, 0.f, 0.f);
    for (; i < n; i += stride) d[i] = z;
}

// messages: agg[dst] += relu(bn?(h[src]) (+vn[batch[src]]) + bond) + 1e-7
__global__ void k_msg(const float* __restrict__ hin, const int* __restrict__ ei,
                      const int* __restrict__ ea, const float* __restrict__ bemb,
                      const int* __restrict__ batch, const float* __restrict__ vn,
                      float* __restrict__ agg, int bnflag) {
    int t = threadIdx.x;
    int e = blockIdx.x * 4 + (t >> 6);
    if (e >= EE) return;
    int c = (t & 63) << 2;
    int src = ei[e];
    int dst = ei[EE + e];
    int a0 = ea[e * 3 + 0], a1 = ea[e * 3 + 1], a2 = ea[e * 3 + 2];
    float4 hv = *(const float4*)&hin[(size_t)src * HH + c];
    if (bnflag) {
        float4 sc = *(const float4*)&g_scale[c];
        float4 sh = *(const float4*)&g_shift[c];
        hv.x = fmaxf(fmaf(hv.x, sc.x, sh.x), 0.f);
        hv.y = fmaxf(fmaf(hv.y, sc.y, sh.y), 0.f);
        hv.z = fmaxf(fmaf(hv.z, sc.z, sh.z), 0.f);
        hv.w = fmaxf(fmaf(hv.w, sc.w, sh.w), 0.f);
    }
    if (vn) {
        float4 vv = *(const float4*)&vn[(size_t)batch[src] * HH + c];
        hv.x += vv.x; hv.y += vv.y; hv.z += vv.z; hv.w += vv.w;
    }
    float4 b0 = *(const float4*)&bemb[(size_t)(0 * 8 + a0) * HH + c];
    float4 b1 = *(const float4*)&bemb[(size_t)(1 * 8 + a1) * HH + c];
    float4 b2 = *(const float4*)&bemb[(size_t)(2 * 8 + a2) * HH + c];
    float4 m;
    m.x = fmaxf(hv.x + b0.x + b1.x + b2.x, 0.f) + 1e-7f;
    m.y = fmaxf(hv.y + b0.y + b1.y + b2.y, 0.f) + 1e-7f;
    m.z = fmaxf(hv.z + b0.z + b1.z + b2.z, 0.f) + 1e-7f;
    m.w = fmaxf(hv.w + b0.w + b1.w + b2.w, 0.f) + 1e-7f;
    red_add4(&agg[(size_t)dst * HH + c], m);
}

// ---------------- BN finalizers -------------------------------------------------
__global__ void k_bnfin(const float* __restrict__ gamma, const float* __restrict__ beta,
                        float invM, float* __restrict__ osc, float* __restrict__ osh) {
    int c = threadIdx.x;
    float mu = g_sum[c] * invM;
    float var = g_sq[c] * invM - mu * mu;
    float sc = gamma[c] * rsqrtf(var + 1e-5f);
    osc[c] = sc;
    osh[c] = beta[c] - mu * sc;
    g_sum[c] = 0.f;
    g_sq[c] = 0.f;
}

// fused: block 0 finalizes node BN into g_scale/g_shift; all blocks copy pool <- vn
__global__ void k_bnfin_pool(const float* __restrict__ gamma, const float* __restrict__ beta,
                             float invM, float4* __restrict__ pool,
                             const float4* __restrict__ vn) {
    if (blockIdx.x == 0) {
        int c = threadIdx.x;
        float mu = g_sum[c] * invM;
        float var = g_sq[c] * invM - mu * mu;
        float sc = gamma[c] * rsqrtf(var + 1e-5f);
        g_scale[c] = sc;
        g_shift[c] = beta[c] - mu * sc;
        g_sum[c] = 0.f;
        g_sq[c] = 0.f;
    }
    size_t n = (size_t)GG * HH / 4;
    size_t stride = (size_t)gridDim.x * blockDim.x;
    for (size_t i = (size_t)blockIdx.x * blockDim.x + threadIdx.x; i < n; i += stride)
        pool[i] = vn[i];
}

// pool[batch[n]] += relu(bn(h[n])); msg = 0
__global__ void k_pool(const float* __restrict__ X, const int* __restrict__ batch,
                       float* __restrict__ pool, float* __restrict__ msg) {
    int t = threadIdx.x;
    int n = blockIdx.x * 4 + (t >> 6);
    if (n >= NN) return;
    int c = (t & 63) << 2;
    float4 xv = *(const float4*)&X[(size_t)n * HH + c];
    float4 sc = *(const float4*)&g_scale[c];
    float4 sh = *(const float4*)&g_shift[c];
    float4 v;
    v.x = fmaxf(fmaf(xv.x, sc.x, sh.x), 0.f);
    v.y = fmaxf(fmaf(xv.y, sc.y, sh.y), 0.f);
    v.z = fmaxf(fmaf(xv.z, sc.z, sh.z), 0.f);
    v.w = fmaxf(fmaf(xv.w, sc.w, sh.w), 0.f);
    *(float4*)&msg[(size_t)n * HH + c] = make_float4(0.f, 0.f, 0.f, 0.f);
    red_add4(&pool[(size_t)batch[n] * HH + c], v);
}

// Y = relu(scale*X + shift)
__global__ void k_bnrelu(const float* __restrict__ X, float* __restrict__ Y,
                         const float* __restrict__ scale, const float* __restrict__ shift,
                         int M) {
    int t = threadIdx.x;
    int n = blockIdx.x * 4 + (t >> 6);
    if (n >= M) return;
    int c = (t & 63) << 2;
    size_t o = (size_t)n * HH + c;
    float4 xv = *(const float4*)&X[o];
    float4 sc = *(const float4*)&scale[c];
    float4 sh = *(const float4*)&shift[c];
    float4 v;
    v.x = fmaxf(fmaf(xv.x, sc.x, sh.x), 0.f);
    v.y = fmaxf(fmaf(xv.y, sc.y, sh.y), 0.f);
    v.z = fmaxf(fmaf(xv.z, sc.z, sh.z), 0.f);
    v.w = fmaxf(fmaf(xv.w, sc.w, sh.w), 0.f);
    *(float4*)&Y[o] = v;
}

// out[batch[n]] += bn(h[n])  (final pooling; no relu)
__global__ void k_outpool(const float* __restrict__ X, const int* __restrict__ batch,
                          float* __restrict__ out) {
    int t = threadIdx.x;
    int n = blockIdx.x * 4 + (t >> 6);
    if (n >= NN) return;
    int c = (t & 63) << 2;
    float4 xv = *(const float4*)&X[(size_t)n * HH + c];
    float4 sc = *(const float4*)&g_scale[c];
    float4 sh = *(const float4*)&g_shift[c];
    float4 v;
    v.x = fmaf(xv.x, sc.x, sh.x);
    v.y = fmaf(xv.y, sc.y, sh.y);
    v.z = fmaf(xv.z, sc.z, sh.z);
    v.w = fmaf(xv.w, sc.w, sh.w);
    red_add4(&out[(size_t)batch[n] * HH + c], v);
}

// ---------------- host orchestration ----------------
extern "C" void kernel_launch(void* const* d_in, const int* in_sizes, int n_in,
                              void* d_out, int out_size) {
    const int* x = (const int*)d_in[0];
    const int* ei = (const int*)d_in[1];
    const int* ea = (const int*)d_in[2];
    const int* batch = (const int*)d_in[3];
    const float* aemb = (const float*)d_in[4];
    const float* bemb = (const float*)d_in[5];
    const float* vnw = (const float*)d_in[6];
    const float* cw = (const float*)d_in[7];
    const float* cb = (const float*)d_in[8];
    const float* ng = (const float*)d_in[9];
    const float* nbt = (const float*)d_in[10];
    const float* vw = (const float*)d_in[11];
    const float* vb = (const float*)d_in[12];
    const float* vg = (const float*)d_in[13];
    const float* vbt = (const float*)d_in[14];
    float* out = (float*)d_out;

    float *ph, *pmsg, *pvn, *ppool, *pvtmp, *pscale, *pshift, *pscale2, *pshift2;
    __nv_bfloat16* pbw;
    cudaGetSymbolAddress((void**)&ph, g_h);
    cudaGetSymbolAddress((void**)&pmsg, g_msg);
    cudaGetSymbolAddress((void**)&pvn, g_vn);
    cudaGetSymbolAddress((void**)&ppool, g_pool);
    cudaGetSymbolAddress((void**)&pvtmp, g_vtmp);
    cudaGetSymbolAddress((void**)&pscale, g_scale);
    cudaGetSymbolAddress((void**)&pshift, g_shift);
    cudaGetSymbolAddress((void**)&pscale2, g_scale2);
    cudaGetSymbolAddress((void**)&pshift2, g_shift2);
    cudaGetSymbolAddress((void**)&pbw, g_bw);

    cudaFuncSetAttribute(k_fgemm, cudaFuncAttributeMaxDynamicSharedMemorySize, FG_SMEM);
    cudaFuncSetAttribute(k_sgemm, cudaFuncAttributeMaxDynamicSharedMemorySize, SG_SMEM);

    const int gN4 = (NN + 3) / 4;
    const int gE4 = (EE + 3) / 4;
    const size_t GH4 = (size_t)GG * HH / 4;
    const int tilesN = (NN + 127) / 128;
    const int tilesG = GG / 32;   // 128 CTAs for small GEMM
    const size_t WSTRIDE = (size_t)768 * HH;

    // ordered so the profiled launch slot lands on the big node GEMM
    k_prepw<<<7 * 256, 256>>>(cw, pbw, 7);                                    // 0
    k_atom<<<gN4, 256>>>(x, aemb, vnw, ph, pmsg);                             // 1
    k_msg<<<gE4, 256>>>(ph, ei, ea, bemb, batch, nullptr, pmsg, 0);           // 2
    k_fgemm<<<tilesN, 512, FG_SMEM>>>(ph, pmsg, nullptr, nullptr, pbw, cb,    // 3
                                      nullptr, ph, NN, 0);
    k_vninit<<<GG / 4, 256>>>(pvn, vnw);                                      // 4
    k_prepw<<<12 * 256, 256>>>(vw, pbw + 7 * WSTRIDE, 12);                    // 5

    for (int l = 1; l < 7; ++l) {
        // node BN finalize (+ pool <- vn), then pool atomics + msg zero
        k_bnfin_pool<<<64, 256>>>(ng + (l - 1) * HH, nbt + (l - 1) * HH, 1.0f / NN,
                                  (float4*)ppool, (const float4*)pvn);
        k_pool<<<gN4, 256>>>(ph, batch, ppool, pmsg);

        // vn MLP: Linear -> BN -> (ReLU fused into next A-load) -> Linear -> BN -> ReLU
        int m0 = 7 + (l - 1) * 2;
        const float* vbl = vb + (size_t)(l - 1) * 2 * HH;
        const float* vgl = vg + (size_t)(l - 1) * 2 * HH;
        const float* vbl2 = vbt + (size_t)(l - 1) * 2 * HH;
        k_sgemm<<<tilesG, 256, SG_SMEM>>>(ppool, pbw + (size_t)m0 * WSTRIDE, vbl,
                                          pvtmp, GG, 0);
        k_bnfin<<<1, 256>>>(vgl, vbl2, 1.0f / GG, pscale2, pshift2);
        k_sgemm<<<tilesG, 256, SG_SMEM>>>(pvtmp, pbw + (size_t)(m0 + 1) * WSTRIDE,
                                          vbl + HH, pvtmp, GG, 1);
        k_bnfin<<<1, 256>>>(vgl + HH, vbl2 + HH, 1.0f / GG, pscale2, pshift2);
        k_bnrelu<<<GG / 4, 256>>>(pvtmp, pvn, pscale2, pshift2, GG);

        // messages on bnrelu(h)+vn gathered on the fly; fused node GEMM:
        // h = (bnrelu(h) + vn[batch] + msg) @ Wl + bl + h
        k_msg<<<gE4, 256>>>(ph, ei, ea, bemb, batch, pvn, pmsg, 1);
        k_fgemm<<<tilesN, 512, FG_SMEM>>>(ph, pmsg, batch, pvn,
                                          pbw + (size_t)l * WSTRIDE, cb + l * HH, ph, ph,
                                          NN, 1);
    }

    // final BN (stats from last GEMM) + global_add_pool
    k_bnfin<<<1, 256>>>(ng + 6 * HH, nbt + 6 * HH, 1.0f / NN, pscale, pshift);
    k_zero<<<512, 256>>>((float4*)out, GH4);
    k_outpool<<<gN4, 256>>>(ph, batch, out);
}

// round 8
// speedup vs baseline: 1.8043x; 1.0540x over previous
#include <cuda_runtime.h>
#include <cuda_bf16.h>
#include <cstdint>

#define NN 150000
#define EE 300000
#define GG 4096
#define HH 256
#define NMAT 19

// ---------------- scratch (device globals; no allocations) ----------------
__device__ float g_h[(size_t)NN * HH];
__device__ float g_msg[(size_t)NN * HH];
__device__ float g_vn[GG * HH];
__device__ float g_pool[GG * HH];
__device__ float g_vtmp[GG * HH];
__device__ float g_stats[NMAT][512];  // per-BN {sum[256], sq[256]}; zeroed by first k_prepw
__device__ float g_scale[HH];   // node-BN affine
__device__ float g_shift[HH];
__device__ float g_scale2[HH];  // vn-MLP mid BN affine
__device__ float g_shift2[HH];
// prebuilt B' per matrix: [768][256] bf16 = rows [Bhi ; Bhi ; Blo]
__device__ __align__(16) __nv_bfloat16 g_bw[(size_t)NMAT * 768 * HH];

// ---------------- PTX helpers ----------------
__device__ __forceinline__ uint32_t s2u(const void* p) {
    uint32_t a;
    asm("{ .reg .u64 t; cvta.to.shared.u64 t, %1; cvt.u32.u64 %0, t; }" : "=r"(a) : "l"(p));
    return a;
}
__device__ __forceinline__ void cpasync16(uint32_t dst, const void* src) {
    asm volatile("cp.async.cg.shared.global [%0], [%1], 16;" :: "r"(dst), "l"(src));
}
__device__ __forceinline__ void cp_commit() {
    asm volatile("cp.async.commit_group;" ::: "memory");
}
__device__ __forceinline__ void cp_wait0() {
    asm volatile("cp.async.wait_group 0;" ::: "memory");
}
__device__ __forceinline__ void ldsm4(uint32_t a, uint32_t& r0, uint32_t& r1, uint32_t& r2,
                                      uint32_t& r3) {
    asm volatile("ldmatrix.sync.aligned.m8n8.x4.shared.b16 {%0,%1,%2,%3}, [%4];"
                 : "=r"(r0), "=r"(r1), "=r"(r2), "=r"(r3) : "r"(a));
}
__device__ __forceinline__ void ldsm4t(uint32_t a, uint32_t& r0, uint32_t& r1, uint32_t& r2,
                                       uint32_t& r3) {
    asm volatile("ldmatrix.sync.aligned.m8n8.x4.trans.shared.b16 {%0,%1,%2,%3}, [%4];"
                 : "=r"(r0), "=r"(r1), "=r"(r2), "=r"(r3) : "r"(a));
}
__device__ __forceinline__ void mma16816(float* c, const uint32_t* a, uint32_t b0, uint32_t b1) {
    asm volatile(
        "mma.sync.aligned.m16n8k16.row.col.f32.bf16.bf16.f32 "
        "{%0,%1,%2,%3}, {%4,%5,%6,%7}, {%8,%9}, {%0,%1,%2,%3};"
        : "+f"(c[0]), "+f"(c[1]), "+f"(c[2]), "+f"(c[3])
        : "r"(a[0]), "r"(a[1]), "r"(a[2]), "r"(a[3]), "r"(b0), "r"(b1));
}
__device__ __forceinline__ void red_add4(float* p, float4 v) {
    asm volatile("red.global.add.v4.f32 [%0], {%1, %2, %3, %4};"
                 :: "l"(p), "f"(v.x), "f"(v.y), "f"(v.z), "f"(v.w) : "memory");
}
__device__ __forceinline__ void red_addf(float* p, float v) {
    asm volatile("red.global.add.f32 [%0], %1;" :: "l"(p), "f"(v) : "memory");
}
__device__ __forceinline__ uint32_t pkbf(float a, float b) {
    __nv_bfloat16 h0 = __float2bfloat16(a), h1 = __float2bfloat16(b);
    return (uint32_t)__bfloat16_as_ushort(h0) | ((uint32_t)__bfloat16_as_ushort(h1) << 16);
}

// ---------------- weight prep: W[k][n] fp32 -> B'[768][256] bf16 ----------------
// zs=1: blocks 0..18 also zero the BN stat slots (first launch of the pass only).
__global__ void k_prepw(const float* __restrict__ W, __nv_bfloat16* __restrict__ out,
                        int nmat, int zs) {
    int b = blockIdx.x;
    if (zs && b < NMAT) {
        g_stats[b][threadIdx.x] = 0.f;
        g_stats[b][threadIdx.x + 256] = 0.f;
    }
    int mat = b >> 8;
    if (mat >= nmat) return;
    int k = b & 255;
    int n = threadIdx.x;
    float v = W[(size_t)mat * 65536 + k * 256 + n];
    __nv_bfloat16 h = __float2bfloat16(v);
    __nv_bfloat16 l = __float2bfloat16(v - __bfloat162float(h));
    size_t base = (size_t)mat * 768 * 256;
    out[base + (size_t)k * 256 + n] = h;
    out[base + (size_t)(k + 256) * 256 + n] = h;
    out[base + (size_t)(k + 512) * 256 + n] = l;
}

// ---------------- big fused bf16 HMMA GEMM (BM=128, 512 threads, BK=64) ---------
// C[M,256] = (bnrelu?(X) + MS? + VN[bt]?)[M,256] @ B'[768,256] + bias (+R)
// Epilogue accumulates per-channel sum/sumsq into stats slot.
#define BSTG 32768
#define FG_SMEM (131072 + 2 * BSTG)
#define NKC 12

__device__ __forceinline__ void bg_issue512(int kc, uint32_t bb0, int tid,
                                            const __nv_bfloat16* __restrict__ Bw) {
    uint32_t bbase = bb0 + (uint32_t)(kc & 1) * BSTG;
    const __nv_bfloat16* bsrc = Bw + (size_t)kc * 64 * 256;
#pragma unroll
    for (int i = 0; i < 4; ++i) {
        int f = tid + i * 512;
        int k = f >> 5, c = f & 31;
        uint32_t dst = bbase + k * 512 + ((c ^ (k & 7)) << 4);
        cpasync16(dst, bsrc + k * 256 + c * 8);
    }
    cp_commit();
}

__device__ __forceinline__ void bg_issue256(int kc, uint32_t bb0, int tid,
                                            const __nv_bfloat16* __restrict__ Bw) {
    uint32_t bbase = bb0 + (uint32_t)(kc & 1) * BSTG;
    const __nv_bfloat16* bsrc = Bw + (size_t)kc * 64 * 256;
#pragma unroll
    for (int i = 0; i < 8; ++i) {
        int f = tid + i * 256;
        int k = f >> 5, c = f & 31;
        uint32_t dst = bbase + k * 512 + ((c ^ (k & 7)) << 4);
        cpasync16(dst, bsrc + k * 256 + c * 8);
    }
    cp_commit();
}

__global__ void __launch_bounds__(512, 1)
k_fgemm(const float* __restrict__ X, const float* __restrict__ MS,
        const int* __restrict__ bt, const float* __restrict__ VN,
        const __nv_bfloat16* __restrict__ Bw, const float* __restrict__ bias,
        const float* __restrict__ R, float* __restrict__ C, float* __restrict__ stats,
        int M, int bnX) {
    extern __shared__ char sm[];
    uint32_t sb = s2u(sm);
    int tid = threadIdx.x;
    int lane = tid & 31;
    int wid = tid >> 5;       // 0..15
    int wm = wid & 3;         // 32-row group
    int wn = wid >> 2;        // 64-col group
    int row0 = blockIdx.x * 128;

    bg_issue512(0, sb + 131072u, tid, Bw);

    // A load (fp32, fused bn-relu + sum of sources) + split hi/lo into SMEM
#pragma unroll 4
    for (int it = 0; it < 8; ++it) {
        int f = tid + it * 512;
        int r = f >> 5, ci = f & 31;
        int row = row0 + r;
        float v[8];
        if (row < M) {
            size_t o = (size_t)row * 256 + ci * 8;
            float4 a0 = *(const float4*)&X[o];
            float4 a1 = *(const float4*)&X[o + 4];
            v[0] = a0.x; v[1] = a0.y; v[2] = a0.z; v[3] = a0.w;
            v[4] = a1.x; v[5] = a1.y; v[6] = a1.z; v[7] = a1.w;
            if (bnX) {
                float4 s0 = *(const float4*)&g_scale[ci * 8];
                float4 s1 = *(const float4*)&g_scale[ci * 8 + 4];
                float4 t0 = *(const float4*)&g_shift[ci * 8];
                float4 t1 = *(const float4*)&g_shift[ci * 8 + 4];
                v[0] = fmaxf(fmaf(v[0], s0.x, t0.x), 0.f);
                v[1] = fmaxf(fmaf(v[1], s0.y, t0.y), 0.f);
                v[2] = fmaxf(fmaf(v[2], s0.z, t0.z), 0.f);
                v[3] = fmaxf(fmaf(v[3], s0.w, t0.w), 0.f);
                v[4] = fmaxf(fmaf(v[4], s1.x, t1.x), 0.f);
                v[5] = fmaxf(fmaf(v[5], s1.y, t1.y), 0.f);
                v[6] = fmaxf(fmaf(v[6], s1.z, t1.z), 0.f);
                v[7] = fmaxf(fmaf(v[7], s1.w, t1.w), 0.f);
            }
            if (MS) {
                float4 m0 = *(const float4*)&MS[o];
                float4 m1 = *(const float4*)&MS[o + 4];
                v[0] += m0.x; v[1] += m0.y; v[2] += m0.z; v[3] += m0.w;
                v[4] += m1.x; v[5] += m1.y; v[6] += m1.z; v[7] += m1.w;
            }
            if (VN) {
                size_t vo = (size_t)bt[row] * 256 + ci * 8;
                float4 w0 = *(const float4*)&VN[vo];
                float4 w1 = *(const float4*)&VN[vo + 4];
                v[0] += w0.x; v[1] += w0.y; v[2] += w0.z; v[3] += w0.w;
                v[4] += w1.x; v[5] += w1.y; v[6] += w1.z; v[7] += w1.w;
            }
        } else {
#pragma unroll
            for (int i = 0; i < 8; ++i) v[i] = 0.f;
        }
        uint32_t hw[4], lw[4];
#pragma unroll
        for (int i = 0; i < 4; ++i) {
            float x = v[2 * i], y = v[2 * i + 1];
            float hx = __bfloat162float(__float2bfloat16(x));
            float hy = __bfloat162float(__float2bfloat16(y));
            hw[i] = pkbf(x, y);
            lw[i] = pkbf(x - hx, y - hy);
        }
        uint32_t off = (uint32_t)(r * 512) + (uint32_t)((ci ^ (r & 7)) << 4);
        asm volatile("st.shared.v4.b32 [%0], {%1,%2,%3,%4};"
                     :: "r"(sb + off), "r"(hw[0]), "r"(hw[1]), "r"(hw[2]), "r"(hw[3]));
        asm volatile("st.shared.v4.b32 [%0], {%1,%2,%3,%4};"
                     :: "r"(sb + 65536u + off), "r"(lw[0]), "r"(lw[1]), "r"(lw[2]), "r"(lw[3]));
    }

    float acc[2][8][4];
#pragma unroll
    for (int mi = 0; mi < 2; ++mi)
#pragma unroll
        for (int ni = 0; ni < 8; ++ni)
#pragma unroll
            for (int q = 0; q < 4; ++q) acc[mi][ni][q] = 0.f;

    for (int kc = 0; kc < NKC; ++kc) {
        cp_wait0();
        __syncthreads();
        if (kc + 1 < NKC) bg_issue512(kc + 1, sb + 131072u, tid, Bw);

        uint32_t abase = sb + ((kc >= 4 && kc < 8) ? 65536u : 0u);
        uint32_t bbase = sb + 131072u + (uint32_t)(kc & 1) * BSTG;
#pragma unroll
        for (int ks = 0; ks < 4; ++ks) {
            uint32_t afr[2][4];
            int rl = lane & 15;
            int ci = (kc & 3) * 8 + ks * 2 + (lane >> 4);
#pragma unroll
            for (int mi = 0; mi < 2; ++mi) {
                int r = wm * 32 + mi * 16 + rl;
                uint32_t addr = abase + r * 512 + ((ci ^ (r & 7)) << 4);
                ldsm4(addr, afr[mi][0], afr[mi][1], afr[mi][2], afr[mi][3]);
            }
            uint32_t bfr[4][4];
            int kb = ks * 16 + (lane & 15);
#pragma unroll
            for (int nj = 0; nj < 4; ++nj) {
                int n = wn * 64 + nj * 16 + ((lane >> 4) << 3);
                int cN = n >> 3;
                uint32_t addr = bbase + kb * 512 + ((cN ^ (kb & 7)) << 4);
                ldsm4t(addr, bfr[nj][0], bfr[nj][1], bfr[nj][2], bfr[nj][3]);
            }
#pragma unroll
            for (int mi = 0; mi < 2; ++mi)
#pragma unroll
                for (int nj = 0; nj < 4; ++nj) {
                    mma16816(acc[mi][nj * 2 + 0], afr[mi], bfr[nj][0], bfr[nj][1]);
                    mma16816(acc[mi][nj * 2 + 1], afr[mi], bfr[nj][2], bfr[nj][3]);
                }
        }
    }

    // epilogue: bias (+R) write, plus per-channel sum / sumsq accumulation
    int r_c = lane >> 2;
    int c_c = (lane & 3) * 2;
    float ss[8][2], qq[8][2];
#pragma unroll
    for (int ni = 0; ni < 8; ++ni) {
        ss[ni][0] = ss[ni][1] = 0.f;
        qq[ni][0] = qq[ni][1] = 0.f;
    }
#pragma unroll
    for (int mi = 0; mi < 2; ++mi) {
        int gr0 = row0 + wm * 32 + mi * 16 + r_c;
        int gr1 = gr0 + 8;
#pragma unroll
        for (int ni = 0; ni < 8; ++ni) {
            int gc = wn * 64 + ni * 8 + c_c;
            float b0 = bias[gc], b1 = bias[gc + 1];
            if (gr0 < M) {
                size_t o = (size_t)gr0 * 256 + gc;
                float x0 = acc[mi][ni][0] + b0;
                float x1 = acc[mi][ni][1] + b1;
                if (R) { float2 rv = *(const float2*)&R[o]; x0 += rv.x; x1 += rv.y; }
                *(float2*)&C[o] = make_float2(x0, x1);
                ss[ni][0] += x0; qq[ni][0] += x0 * x0;
                ss[ni][1] += x1; qq[ni][1] += x1 * x1;
            }
            if (gr1 < M) {
                size_t o = (size_t)gr1 * 256 + gc;
                float x2 = acc[mi][ni][2] + b0;
                float x3 = acc[mi][ni][3] + b1;
                if (R) { float2 rv = *(const float2*)&R[o]; x2 += rv.x; x3 += rv.y; }
                *(float2*)&C[o] = make_float2(x2, x3);
                ss[ni][0] += x2; qq[ni][0] += x2 * x2;
                ss[ni][1] += x3; qq[ni][1] += x3 * x3;
            }
        }
    }
#pragma unroll
    for (int ni = 0; ni < 8; ++ni)
#pragma unroll
        for (int j = 0; j < 2; ++j) {
            float s = ss[ni][j], q = qq[ni][j];
            s += __shfl_xor_sync(0xffffffffu, s, 4);
            s += __shfl_xor_sync(0xffffffffu, s, 8);
            s += __shfl_xor_sync(0xffffffffu, s, 16);
            q += __shfl_xor_sync(0xffffffffu, q, 4);
            q += __shfl_xor_sync(0xffffffffu, q, 8);
            q += __shfl_xor_sync(0xffffffffu, q, 16);
            ss[ni][j] = s; qq[ni][j] = q;
        }
    if (r_c == 0) {
#pragma unroll
        for (int ni = 0; ni < 8; ++ni) {
            int gc = wn * 64 + ni * 8 + c_c;
            red_addf(&stats[gc], ss[ni][0]);
            red_addf(&stats[gc + 1], ss[ni][1]);
            red_addf(&stats[256 + gc], qq[ni][0]);
            red_addf(&stats[256 + gc + 1], qq[ni][1]);
        }
    }
}

// ---------------- small GEMM (BM=32) for vn-MLP, 128 CTAs, BK=64 ----------------
#define SG_SMEM (32768 + 2 * BSTG)

__global__ void __launch_bounds__(256, 1)
k_sgemm(const float* __restrict__ X, const __nv_bfloat16* __restrict__ Bw,
        const float* __restrict__ bias, float* __restrict__ C, float* __restrict__ stats,
        int M, int bnX) {
    extern __shared__ char sm[];
    uint32_t sb = s2u(sm);
    int tid = threadIdx.x;
    int lane = tid & 31;
    int wn = tid >> 5;   // 8 N-warps of 32 cols
    int row0 = blockIdx.x * 32;

    bg_issue256(0, sb + 32768u, tid, Bw);

#pragma unroll
    for (int it = 0; it < 4; ++it) {
        int f = tid + it * 256;
        int r = f >> 5, ci = f & 31;
        int row = row0 + r;
        float v[8];
        if (row < M) {
            size_t o = (size_t)row * 256 + ci * 8;
            float4 a0 = *(const float4*)&X[o];
            float4 a1 = *(const float4*)&X[o + 4];
            v[0] = a0.x; v[1] = a0.y; v[2] = a0.z; v[3] = a0.w;
            v[4] = a1.x; v[5] = a1.y; v[6] = a1.z; v[7] = a1.w;
            if (bnX) {
                float4 s0 = *(const float4*)&g_scale2[ci * 8];
                float4 s1 = *(const float4*)&g_scale2[ci * 8 + 4];
                float4 t0 = *(const float4*)&g_shift2[ci * 8];
                float4 t1 = *(const float4*)&g_shift2[ci * 8 + 4];
                v[0] = fmaxf(fmaf(v[0], s0.x, t0.x), 0.f);
                v[1] = fmaxf(fmaf(v[1], s0.y, t0.y), 0.f);
                v[2] = fmaxf(fmaf(v[2], s0.z, t0.z), 0.f);
                v[3] = fmaxf(fmaf(v[3], s0.w, t0.w), 0.f);
                v[4] = fmaxf(fmaf(v[4], s1.x, t1.x), 0.f);
                v[5] = fmaxf(fmaf(v[5], s1.y, t1.y), 0.f);
                v[6] = fmaxf(fmaf(v[6], s1.z, t1.z), 0.f);
                v[7] = fmaxf(fmaf(v[7], s1.w, t1.w), 0.f);
            }
        } else {
#pragma unroll
            for (int i = 0; i < 8; ++i) v[i] = 0.f;
        }
        uint32_t hw[4], lw[4];
#pragma unroll
        for (int i = 0; i < 4; ++i) {
            float x = v[2 * i], y = v[2 * i + 1];
            float hx = __bfloat162float(__float2bfloat16(x));
            float hy = __bfloat162float(__float2bfloat16(y));
            hw[i] = pkbf(x, y);
            lw[i] = pkbf(x - hx, y - hy);
        }
        uint32_t off = (uint32_t)(r * 512) + (uint32_t)((ci ^ (r & 7)) << 4);
        asm volatile("st.shared.v4.b32 [%0], {%1,%2,%3,%4};"
                     :: "r"(sb + off), "r"(hw[0]), "r"(hw[1]), "r"(hw[2]), "r"(hw[3]));
        asm volatile("st.shared.v4.b32 [%0], {%1,%2,%3,%4};"
                     :: "r"(sb + 16384u + off), "r"(lw[0]), "r"(lw[1]), "r"(lw[2]), "r"(lw[3]));
    }

    float acc[2][4][4];
#pragma unroll
    for (int mi = 0; mi < 2; ++mi)
#pragma unroll
        for (int ni = 0; ni < 4; ++ni)
#pragma unroll
            for (int q = 0; q < 4; ++q) acc[mi][ni][q] = 0.f;

    for (int kc = 0; kc < NKC; ++kc) {
        cp_wait0();
        __syncthreads();
        if (kc + 1 < NKC) bg_issue256(kc + 1, sb + 32768u, tid, Bw);

        uint32_t abase = sb + ((kc >= 4 && kc < 8) ? 16384u : 0u);
        uint32_t bbase = sb + 32768u + (uint32_t)(kc & 1) * BSTG;
#pragma unroll
        for (int ks = 0; ks < 4; ++ks) {
            uint32_t afr[2][4];
            int rl = lane & 15;
            int ci = (kc & 3) * 8 + ks * 2 + (lane >> 4);
#pragma unroll
            for (int mi = 0; mi < 2; ++mi) {
                int r = mi * 16 + rl;
                uint32_t addr = abase + r * 512 + ((ci ^ (r & 7)) << 4);
                ldsm4(addr, afr[mi][0], afr[mi][1], afr[mi][2], afr[mi][3]);
            }
            uint32_t bfr[2][4];
            int kb = ks * 16 + (lane & 15);
#pragma unroll
            for (int nj = 0; nj < 2; ++nj) {
                int n = wn * 32 + nj * 16 + ((lane >> 4) << 3);
                int cN = n >> 3;
                uint32_t addr = bbase + kb * 512 + ((cN ^ (kb & 7)) << 4);
                ldsm4t(addr, bfr[nj][0], bfr[nj][1], bfr[nj][2], bfr[nj][3]);
            }
#pragma unroll
            for (int mi = 0; mi < 2; ++mi)
#pragma unroll
                for (int nj = 0; nj < 2; ++nj) {
                    mma16816(acc[mi][nj * 2 + 0], afr[mi], bfr[nj][0], bfr[nj][1]);
                    mma16816(acc[mi][nj * 2 + 1], afr[mi], bfr[nj][2], bfr[nj][3]);
                }
        }
    }

    int r_c = lane >> 2;
    int c_c = (lane & 3) * 2;
    float ss[4][2], qq[4][2];
#pragma unroll
    for (int ni = 0; ni < 4; ++ni) {
        ss[ni][0] = ss[ni][1] = 0.f;
        qq[ni][0] = qq[ni][1] = 0.f;
    }
#pragma unroll
    for (int mi = 0; mi < 2; ++mi) {
        int gr0 = row0 + mi * 16 + r_c;
        int gr1 = gr0 + 8;
#pragma unroll
        for (int ni = 0; ni < 4; ++ni) {
            int gc = wn * 32 + ni * 8 + c_c;
            float b0 = bias[gc], b1 = bias[gc + 1];
            if (gr0 < M) {
                size_t o = (size_t)gr0 * 256 + gc;
                float x0 = acc[mi][ni][0] + b0;
                float x1 = acc[mi][ni][1] + b1;
                *(float2*)&C[o] = make_float2(x0, x1);
                ss[ni][0] += x0; qq[ni][0] += x0 * x0;
                ss[ni][1] += x1; qq[ni][1] += x1 * x1;
            }
            if (gr1 < M) {
                size_t o = (size_t)gr1 * 256 + gc;
                float x2 = acc[mi][ni][2] + b0;
                float x3 = acc[mi][ni][3] + b1;
                *(float2*)&C[o] = make_float2(x2, x3);
                ss[ni][0] += x2; qq[ni][0] += x2 * x2;
                ss[ni][1] += x3; qq[ni][1] += x3 * x3;
            }
        }
    }
#pragma unroll
    for (int ni = 0; ni < 4; ++ni)
#pragma unroll
        for (int j = 0; j < 2; ++j) {
            float s = ss[ni][j], q = qq[ni][j];
            s += __shfl_xor_sync(0xffffffffu, s, 4);
            s += __shfl_xor_sync(0xffffffffu, s, 8);
            s += __shfl_xor_sync(0xffffffffu, s, 16);
            q += __shfl_xor_sync(0xffffffffu, q, 4);
            q += __shfl_xor_sync(0xffffffffu, q, 8);
            q += __shfl_xor_sync(0xffffffffu, q, 16);
            ss[ni][j] = s; qq[ni][j] = q;
        }
    if (r_c == 0) {
#pragma unroll
        for (int ni = 0; ni < 4; ++ni) {
            int gc = wn * 32 + ni * 8 + c_c;
            red_addf(&stats[gc], ss[ni][0]);
            red_addf(&stats[gc + 1], ss[ni][1]);
            red_addf(&stats[256 + gc], qq[ni][0]);
            red_addf(&stats[256 + gc + 1], qq[ni][1]);
        }
    }
}

// ---------------- elementwise / encode kernels ----------------
__global__ void k_atom(const int* __restrict__ x, const float* __restrict__ aemb,
                       const float* __restrict__ vnw, float* __restrict__ h,
                       float* __restrict__ msg) {
    int t = threadIdx.x;
    int n = blockIdx.x * 4 + (t >> 6);
    if (n >= NN) return;
    int c = (t & 63) << 2;
    float4 s = *(const float4*)&vnw[c];
#pragma unroll
    for (int f = 0; f < 9; ++f) {
        int v = x[n * 9 + f];
        float4 ev = *(const float4*)&aemb[(size_t)((f << 6) + v) * HH + c];
        s.x += ev.x; s.y += ev.y; s.z += ev.z; s.w += ev.w;
    }
    *(float4*)&h[(size_t)n * HH + c] = s;
    *(float4*)&msg[(size_t)n * HH + c] = make_float4(0.f, 0.f, 0.f, 0.f);
}

// vn = vnw broadcast; pool = vn
__global__ void k_vninit(float* __restrict__ vn, float* __restrict__ pool,
                         const float* __restrict__ vnw) {
    int t = threadIdx.x;
    int g = blockIdx.x * 4 + (t >> 6);
    int c = (t & 63) << 2;
    float4 v = *(const float4*)&vnw[c];
    *(float4*)&vn[(size_t)g * HH + c] = v;
    *(float4*)&pool[(size_t)g * HH + c] = v;
}

__global__ void k_zero(float4* __restrict__ d, size_t n) {
    size_t i = (size_t)blockIdx.x * blockDim.x + threadIdx.x;
    size_t stride = (size_t)gridDim.x * blockDim.x;
    float4 z = make_float4(0.f, 0.f, 0.f, 0.f);
    for (; i < n; i += stride) d[i] = z;
}

// messages: agg[dst] += relu(bn?(h[src]) (+vn[batch[src]]) + bond) + 1e-7
__global__ void k_msg(const float* __restrict__ hin, const int* __restrict__ ei,
                      const int* __restrict__ ea, const float* __restrict__ bemb,
                      const int* __restrict__ batch, const float* __restrict__ vn,
                      float* __restrict__ agg, int bnflag) {
    int t = threadIdx.x;
    int e = blockIdx.x * 4 + (t >> 6);
    if (e >= EE) return;
    int c = (t & 63) << 2;
    int src = ei[e];
    int dst = ei[EE + e];
    int a0 = ea[e * 3 + 0], a1 = ea[e * 3 + 1], a2 = ea[e * 3 + 2];
    float4 hv = *(const float4*)&hin[(size_t)src * HH + c];
    if (bnflag) {
        float4 sc = *(const float4*)&g_scale[c];
        float4 sh = *(const float4*)&g_shift[c];
        hv.x = fmaxf(fmaf(hv.x, sc.x, sh.x), 0.f);
        hv.y = fmaxf(fmaf(hv.y, sc.y, sh.y), 0.f);
        hv.z = fmaxf(fmaf(hv.z, sc.z, sh.z), 0.f);
        hv.w = fmaxf(fmaf(hv.w, sc.w, sh.w), 0.f);
    }
    if (vn) {
        float4 vv = *(const float4*)&vn[(size_t)batch[src] * HH + c];
        hv.x += vv.x; hv.y += vv.y; hv.z += vv.z; hv.w += vv.w;
    }
    float4 b0 = *(const float4*)&bemb[(size_t)(0 * 8 + a0) * HH + c];
    float4 b1 = *(const float4*)&bemb[(size_t)(1 * 8 + a1) * HH + c];
    float4 b2 = *(const float4*)&bemb[(size_t)(2 * 8 + a2) * HH + c];
    float4 m;
    m.x = fmaxf(hv.x + b0.x + b1.x + b2.x, 0.f) + 1e-7f;
    m.y = fmaxf(hv.y + b0.y + b1.y + b2.y, 0.f) + 1e-7f;
    m.z = fmaxf(hv.z + b0.z + b1.z + b2.z, 0.f) + 1e-7f;
    m.w = fmaxf(hv.w + b0.w + b1.w + b2.w, 0.f) + 1e-7f;
    red_add4(&agg[(size_t)dst * HH + c], m);
}

// ---------------- BN finalizers (stat slots; no resets) -------------------------
__global__ void k_bnfin(const float* __restrict__ stats, const float* __restrict__ gamma,
                        const float* __restrict__ beta, float invM,
                        float* __restrict__ osc, float* __restrict__ osh) {
    int c = threadIdx.x;
    float mu = stats[c] * invM;
    float var = stats[256 + c] * invM - mu * mu;
    float sc = gamma[c] * rsqrtf(var + 1e-5f);
    osc[c] = sc;
    osh[c] = beta[c] - mu * sc;
}

// 64 CTAs: compute BN affine from slot, vn = relu(bn(X)), pool = vn
__global__ void k_bnfin2relu_pool(const float* __restrict__ stats,
                                  const float* __restrict__ gamma,
                                  const float* __restrict__ beta, float invM,
                                  const float* __restrict__ X, float* __restrict__ vn,
                                  float* __restrict__ pool) {
    __shared__ float ssc[256], ssh[256];
    int t = threadIdx.x;
    {
        float mu = stats[t] * invM;
        float var = stats[256 + t] * invM - mu * mu;
        float sc = gamma[t] * rsqrtf(var + 1e-5f);
        ssc[t] = sc;
        ssh[t] = beta[t] - mu * sc;
    }
    __syncthreads();
    // each block: 64 rows (4096/64), 64 float4 per row
    size_t base = (size_t)blockIdx.x * 4096;   // in float4 units
#pragma unroll 4
    for (int i = 0; i < 16; ++i) {
        size_t idx = base + t + i * 256;
        int c = (idx & 63) << 2;
        float4 x = *(const float4*)&X[idx * 4];
        float4 sc = *(const float4*)&ssc[c];
        float4 sh = *(const float4*)&ssh[c];
        float4 v;
        v.x = fmaxf(fmaf(x.x, sc.x, sh.x), 0.f);
        v.y = fmaxf(fmaf(x.y, sc.y, sh.y), 0.f);
        v.z = fmaxf(fmaf(x.z, sc.z, sh.z), 0.f);
        v.w = fmaxf(fmaf(x.w, sc.w, sh.w), 0.f);
        *(float4*)&vn[idx * 4] = v;
        *(float4*)&pool[idx * 4] = v;
    }
}

// pool[batch[n]] += relu(bn(h[n])); msg = 0
__global__ void k_pool(const float* __restrict__ X, const int* __restrict__ batch,
                       float* __restrict__ pool, float* __restrict__ msg) {
    int t = threadIdx.x;
    int n = blockIdx.x * 4 + (t >> 6);
    if (n >= NN) return;
    int c = (t & 63) << 2;
    float4 xv = *(const float4*)&X[(size_t)n * HH + c];
    float4 sc = *(const float4*)&g_scale[c];
    float4 sh = *(const float4*)&g_shift[c];
    float4 v;
    v.x = fmaxf(fmaf(xv.x, sc.x, sh.x), 0.f);
    v.y = fmaxf(fmaf(xv.y, sc.y, sh.y), 0.f);
    v.z = fmaxf(fmaf(xv.z, sc.z, sh.z), 0.f);
    v.w = fmaxf(fmaf(xv.w, sc.w, sh.w), 0.f);
    *(float4*)&msg[(size_t)n * HH + c] = make_float4(0.f, 0.f, 0.f, 0.f);
    red_add4(&pool[(size_t)batch[n] * HH + c], v);
}

// out[batch[n]] += bn(h[n])  (final pooling; no relu)
__global__ void k_outpool(const float* __restrict__ X, const int* __restrict__ batch,
                          float* __restrict__ out) {
    int t = threadIdx.x;
    int n = blockIdx.x * 4 + (t >> 6);
    if (n >= NN) return;
    int c = (t & 63) << 2;
    float4 xv = *(const float4*)&X[(size_t)n * HH + c];
    float4 sc = *(const float4*)&g_scale[c];
    float4 sh = *(const float4*)&g_shift[c];
    float4 v;
    v.x = fmaf(xv.x, sc.x, sh.x);
    v.y = fmaf(xv.y, sc.y, sh.y);
    v.z = fmaf(xv.z, sc.z, sh.z);
    v.w = fmaf(xv.w, sc.w, sh.w);
    red_add4(&out[(size_t)batch[n] * HH + c], v);
}

// ---------------- host orchestration ----------------
extern "C" void kernel_launch(void* const* d_in, const int* in_sizes, int n_in,
                              void* d_out, int out_size) {
    const int* x = (const int*)d_in[0];
    const int* ei = (const int*)d_in[1];
    const int* ea = (const int*)d_in[2];
    const int* batch = (const int*)d_in[3];
    const float* aemb = (const float*)d_in[4];
    const float* bemb = (const float*)d_in[5];
    const float* vnw = (const float*)d_in[6];
    const float* cw = (const float*)d_in[7];
    const float* cb = (const float*)d_in[8];
    const float* ng = (const float*)d_in[9];
    const float* nbt = (const float*)d_in[10];
    const float* vw = (const float*)d_in[11];
    const float* vb = (const float*)d_in[12];
    const float* vg = (const float*)d_in[13];
    const float* vbt = (const float*)d_in[14];
    float* out = (float*)d_out;

    float *ph, *pmsg, *pvn, *ppool, *pvtmp, *pscale, *pshift, *pscale2, *pshift2, *pstats;
    __nv_bfloat16* pbw;
    cudaGetSymbolAddress((void**)&ph, g_h);
    cudaGetSymbolAddress((void**)&pmsg, g_msg);
    cudaGetSymbolAddress((void**)&pvn, g_vn);
    cudaGetSymbolAddress((void**)&ppool, g_pool);
    cudaGetSymbolAddress((void**)&pvtmp, g_vtmp);
    cudaGetSymbolAddress((void**)&pscale, g_scale);
    cudaGetSymbolAddress((void**)&pshift, g_shift);
    cudaGetSymbolAddress((void**)&pscale2, g_scale2);
    cudaGetSymbolAddress((void**)&pshift2, g_shift2);
    cudaGetSymbolAddress((void**)&pstats, g_stats);
    cudaGetSymbolAddress((void**)&pbw, g_bw);

    cudaFuncSetAttribute(k_fgemm, cudaFuncAttributeMaxDynamicSharedMemorySize, FG_SMEM);
    cudaFuncSetAttribute(k_sgemm, cudaFuncAttributeMaxDynamicSharedMemorySize, SG_SMEM);

    const int gN4 = (NN + 3) / 4;
    const int gE4 = (EE + 3) / 4;
    const size_t GH4 = (size_t)GG * HH / 4;
    const int tilesN = (NN + 127) / 128;
    const int tilesG = GG / 32;
    const size_t WSTRIDE = (size_t)768 * HH;
    auto slot = [&](int s) { return pstats + (size_t)s * 512; };

    // conv weights -> mats 0..6 (+ zero all stat slots); vn weights -> mats 7..18
    k_prepw<<<7 * 256, 256>>>(cw, pbw, 7, 1);                                   // 0
    k_atom<<<gN4, 256>>>(x, aemb, vnw, ph, pmsg);                               // 1
    k_msg<<<gE4, 256>>>(ph, ei, ea, bemb, batch, nullptr, pmsg, 0);             // 2
    k_fgemm<<<tilesN, 512, FG_SMEM>>>(ph, pmsg, nullptr, nullptr, pbw, cb,      // 3
                                      nullptr, ph, slot(0), NN, 0);
    k_vninit<<<GG / 4, 256>>>(pvn, ppool, vnw);                                 // 4
    k_prepw<<<12 * 256, 256>>>(vw, pbw + 7 * WSTRIDE, 12, 0);                   // 5

    for (int l = 1; l < 7; ++l) {
        int s1 = 7 + (l - 1) * 2, s2 = s1 + 1;
        const float* vbl = vb + (size_t)(l - 1) * 2 * HH;
        const float* vgl = vg + (size_t)(l - 1) * 2 * HH;
        const float* vbl2 = vbt + (size_t)(l - 1) * 2 * HH;

        // node BN affine (stats from last fgemm), then pool atomics + msg zero
        k_bnfin<<<1, 256>>>(slot(l - 1), ng + (l - 1) * HH, nbt + (l - 1) * HH,
                            1.0f / NN, pscale, pshift);
        k_pool<<<gN4, 256>>>(ph, batch, ppool, pmsg);

        // vn MLP: Linear -> BN -> (ReLU fused) -> Linear -> BN+ReLU (+pool init)
        k_sgemm<<<tilesG, 256, SG_SMEM>>>(ppool, pbw + (size_t)s1 * WSTRIDE, vbl,
                                          pvtmp, slot(s1), GG, 0);
        k_bnfin<<<1, 256>>>(slot(s1), vgl, vbl2, 1.0f / GG, pscale2, pshift2);
        k_sgemm<<<tilesG, 256, SG_SMEM>>>(pvtmp, pbw + (size_t)s2 * WSTRIDE,
                                          vbl + HH, pvtmp, slot(s2), GG, 1);
        k_bnfin2relu_pool<<<64, 256>>>(slot(s2), vgl + HH, vbl2 + HH, 1.0f / GG,
                                       pvtmp, pvn, ppool);

        // messages on bnrelu(h)+vn gathered on the fly; fused node GEMM
        k_msg<<<gE4, 256>>>(ph, ei, ea, bemb, batch, pvn, pmsg, 1);
        k_fgemm<<<tilesN, 512, FG_SMEM>>>(ph, pmsg, batch, pvn,
                                          pbw + (size_t)l * WSTRIDE, cb + l * HH, ph, ph,
                                          slot(l), NN, 1);
    }

    // final BN (stats from last fgemm) + global_add_pool
    k_bnfin<<<1, 256>>>(slot(6), ng + 6 * HH, nbt + 6 * HH, 1.0f / NN, pscale, pshift);
    k_zero<<<512, 256>>>((float4*)out, GH4);
    k_outpool<<<gN4, 256>>>(ph, batch, out);
}

// round 9
// speedup vs baseline: 1.9164x; 1.0621x over previous
#include <cuda_runtime.h>
#include <cuda_bf16.h>
#include <cstdint>

#define NN 150000
#define EE 300000
#define GG 4096
#define HH 256
#define NMAT 19

// ---------------- scratch (device globals; no allocations) ----------------
__device__ float g_h[(size_t)NN * HH];
__device__ float g_msg[(size_t)NN * HH];
__device__ float g_vn[GG * HH];
__device__ float g_pool[GG * HH];
__device__ float g_vtmp[GG * HH];
__device__ float g_stats[NMAT][512];  // per-BN {sum[256], sq[256]}; zeroed by first k_prepw
__device__ float g_scale[HH];   // node-BN affine
__device__ float g_shift[HH];
__device__ float g_scale2[HH];  // vn-MLP mid BN affine
__device__ float g_shift2[HH];
// prebuilt B' per matrix: [768][256] bf16 = rows [Bhi ; Bhi ; Blo]
__device__ __align__(16) __nv_bfloat16 g_bw[(size_t)NMAT * 768 * HH];

// ---------------- PTX helpers ----------------
__device__ __forceinline__ uint32_t s2u(const void* p) {
    uint32_t a;
    asm("{ .reg .u64 t; cvta.to.shared.u64 t, %1; cvt.u32.u64 %0, t; }" : "=r"(a) : "l"(p));
    return a;
}
__device__ __forceinline__ void cpasync16(uint32_t dst, const void* src) {
    asm volatile("cp.async.cg.shared.global [%0], [%1], 16;" :: "r"(dst), "l"(src));
}
__device__ __forceinline__ void cp_commit() {
    asm volatile("cp.async.commit_group;" ::: "memory");
}
__device__ __forceinline__ void cp_wait0() {
    asm volatile("cp.async.wait_group 0;" ::: "memory");
}
__device__ __forceinline__ void cp_wait1() {
    asm volatile("cp.async.wait_group 1;" ::: "memory");
}
__device__ __forceinline__ void ldsm4(uint32_t a, uint32_t& r0, uint32_t& r1, uint32_t& r2,
                                      uint32_t& r3) {
    asm volatile("ldmatrix.sync.aligned.m8n8.x4.shared.b16 {%0,%1,%2,%3}, [%4];"
                 : "=r"(r0), "=r"(r1), "=r"(r2), "=r"(r3) : "r"(a));
}
__device__ __forceinline__ void ldsm4t(uint32_t a, uint32_t& r0, uint32_t& r1, uint32_t& r2,
                                       uint32_t& r3) {
    asm volatile("ldmatrix.sync.aligned.m8n8.x4.trans.shared.b16 {%0,%1,%2,%3}, [%4];"
                 : "=r"(r0), "=r"(r1), "=r"(r2), "=r"(r3) : "r"(a));
}
__device__ __forceinline__ void mma16816(float* c, const uint32_t* a, uint32_t b0, uint32_t b1) {
    asm volatile(
        "mma.sync.aligned.m16n8k16.row.col.f32.bf16.bf16.f32 "
        "{%0,%1,%2,%3}, {%4,%5,%6,%7}, {%8,%9}, {%0,%1,%2,%3};"
        : "+f"(c[0]), "+f"(c[1]), "+f"(c[2]), "+f"(c[3])
        : "r"(a[0]), "r"(a[1]), "r"(a[2]), "r"(a[3]), "r"(b0), "r"(b1));
}
__device__ __forceinline__ void red_add4(float* p, float4 v) {
    asm volatile("red.global.add.v4.f32 [%0], {%1, %2, %3, %4};"
                 :: "l"(p), "f"(v.x), "f"(v.y), "f"(v.z), "f"(v.w) : "memory");
}
__device__ __forceinline__ void red_addf(float* p, float v) {
    asm volatile("red.global.add.f32 [%0], %1;" :: "l"(p), "f"(v) : "memory");
}
__device__ __forceinline__ uint32_t pkbf(float a, float b) {
    __nv_bfloat16 h0 = __float2bfloat16(a), h1 = __float2bfloat16(b);
    return (uint32_t)__bfloat16_as_ushort(h0) | ((uint32_t)__bfloat16_as_ushort(h1) << 16);
}

// ---------------- weight prep: W[k][n] fp32 -> B'[768][256] bf16 ----------------
__global__ void k_prepw(const float* __restrict__ W, __nv_bfloat16* __restrict__ out,
                        int nmat, int zs) {
    int b = blockIdx.x;
    if (zs && b < NMAT) {
        g_stats[b][threadIdx.x] = 0.f;
        g_stats[b][threadIdx.x + 256] = 0.f;
    }
    int mat = b >> 8;
    if (mat >= nmat) return;
    int k = b & 255;
    int n = threadIdx.x;
    float v = W[(size_t)mat * 65536 + k * 256 + n];
    __nv_bfloat16 h = __float2bfloat16(v);
    __nv_bfloat16 l = __float2bfloat16(v - __bfloat162float(h));
    size_t base = (size_t)mat * 768 * 256;
    out[base + (size_t)k * 256 + n] = h;
    out[base + (size_t)(k + 256) * 256 + n] = h;
    out[base + (size_t)(k + 512) * 256 + n] = l;
}

// ---------------- fused bf16 HMMA GEMM (BM=64, 256 threads, BK=32, 2 CTA/SM) ----
// C[M,256] = (bnrelu?(X) + MS? + VN[bt]?)[M,256] @ B'[768,256] + bias (+R)
#define FBSTG 16384
#define FG_SMEM (65536 + 3 * FBSTG)   // 64KB A(hi+lo) + 48KB B ring = 112KB
#define FNKC 24

__device__ __forceinline__ void bg_issue_f(int kc, uint32_t bb0, int tid,
                                           const __nv_bfloat16* __restrict__ Bw) {
    uint32_t bbase = bb0 + (uint32_t)(kc % 3) * FBSTG;
    const __nv_bfloat16* bsrc = Bw + (size_t)kc * 32 * 256;
#pragma unroll
    for (int i = 0; i < 4; ++i) {
        int f = tid + i * 256;
        int k = f >> 5, c = f & 31;
        uint32_t dst = bbase + k * 512 + ((c ^ (k & 7)) << 4);
        cpasync16(dst, bsrc + k * 256 + c * 8);
    }
    cp_commit();
}

__global__ void __launch_bounds__(256, 2)
k_fgemm(const float* __restrict__ X, const float* __restrict__ MS,
        const int* __restrict__ bt, const float* __restrict__ VN,
        const __nv_bfloat16* __restrict__ Bw, const float* __restrict__ bias,
        const float* __restrict__ R, float* __restrict__ C, float* __restrict__ stats,
        int M, int bnX) {
    extern __shared__ char sm[];
    uint32_t sb = s2u(sm);
    int tid = threadIdx.x;
    int lane = tid & 31;
    int wid = tid >> 5;       // 0..7
    int wm = wid & 1;         // 32-row group
    int wn = wid >> 1;        // 64-col group
    int row0 = blockIdx.x * 64;

    bg_issue_f(0, sb + 65536u, tid, Bw);
    bg_issue_f(1, sb + 65536u, tid, Bw);

    // A load (fp32, fused bn-relu + sum of sources) + split hi/lo into SMEM
#pragma unroll 4
    for (int it = 0; it < 8; ++it) {
        int f = tid + it * 256;
        int r = f >> 5, ci = f & 31;
        int row = row0 + r;
        float v[8];
        if (row < M) {
            size_t o = (size_t)row * 256 + ci * 8;
            float4 a0 = *(const float4*)&X[o];
            float4 a1 = *(const float4*)&X[o + 4];
            v[0] = a0.x; v[1] = a0.y; v[2] = a0.z; v[3] = a0.w;
            v[4] = a1.x; v[5] = a1.y; v[6] = a1.z; v[7] = a1.w;
            if (bnX) {
                float4 s0 = *(const float4*)&g_scale[ci * 8];
                float4 s1 = *(const float4*)&g_scale[ci * 8 + 4];
                float4 t0 = *(const float4*)&g_shift[ci * 8];
                float4 t1 = *(const float4*)&g_shift[ci * 8 + 4];
                v[0] = fmaxf(fmaf(v[0], s0.x, t0.x), 0.f);
                v[1] = fmaxf(fmaf(v[1], s0.y, t0.y), 0.f);
                v[2] = fmaxf(fmaf(v[2], s0.z, t0.z), 0.f);
                v[3] = fmaxf(fmaf(v[3], s0.w, t0.w), 0.f);
                v[4] = fmaxf(fmaf(v[4], s1.x, t1.x), 0.f);
                v[5] = fmaxf(fmaf(v[5], s1.y, t1.y), 0.f);
                v[6] = fmaxf(fmaf(v[6], s1.z, t1.z), 0.f);
                v[7] = fmaxf(fmaf(v[7], s1.w, t1.w), 0.f);
            }
            if (MS) {
                float4 m0 = *(const float4*)&MS[o];
                float4 m1 = *(const float4*)&MS[o + 4];
                v[0] += m0.x; v[1] += m0.y; v[2] += m0.z; v[3] += m0.w;
                v[4] += m1.x; v[5] += m1.y; v[6] += m1.z; v[7] += m1.w;
            }
            if (VN) {
                size_t vo = (size_t)bt[row] * 256 + ci * 8;
                float4 w0 = *(const float4*)&VN[vo];
                float4 w1 = *(const float4*)&VN[vo + 4];
                v[0] += w0.x; v[1] += w0.y; v[2] += w0.z; v[3] += w0.w;
                v[4] += w1.x; v[5] += w1.y; v[6] += w1.z; v[7] += w1.w;
            }
        } else {
#pragma unroll
            for (int i = 0; i < 8; ++i) v[i] = 0.f;
        }
        uint32_t hw[4], lw[4];
#pragma unroll
        for (int i = 0; i < 4; ++i) {
            float x = v[2 * i], y = v[2 * i + 1];
            float hx = __bfloat162float(__float2bfloat16(x));
            float hy = __bfloat162float(__float2bfloat16(y));
            hw[i] = pkbf(x, y);
            lw[i] = pkbf(x - hx, y - hy);
        }
        uint32_t off = (uint32_t)(r * 512) + (uint32_t)((ci ^ (r & 7)) << 4);
        asm volatile("st.shared.v4.b32 [%0], {%1,%2,%3,%4};"
                     :: "r"(sb + off), "r"(hw[0]), "r"(hw[1]), "r"(hw[2]), "r"(hw[3]));
        asm volatile("st.shared.v4.b32 [%0], {%1,%2,%3,%4};"
                     :: "r"(sb + 32768u + off), "r"(lw[0]), "r"(lw[1]), "r"(lw[2]), "r"(lw[3]));
    }

    float acc[2][8][4];
#pragma unroll
    for (int mi = 0; mi < 2; ++mi)
#pragma unroll
        for (int ni = 0; ni < 8; ++ni)
#pragma unroll
            for (int q = 0; q < 4; ++q) acc[mi][ni][q] = 0.f;

    for (int kc = 0; kc < FNKC; ++kc) {
        cp_wait1();
        __syncthreads();
        if (kc + 2 < FNKC) bg_issue_f(kc + 2, sb + 65536u, tid, Bw);
        else cp_commit();   // empty group keeps wait_group 1 semantics

        uint32_t abase = sb + ((kc >= 8 && kc < 16) ? 32768u : 0u);
        int cb8 = (kc & 7) * 4;
        uint32_t bbase = sb + 65536u + (uint32_t)(kc % 3) * FBSTG;
#pragma unroll
        for (int ks = 0; ks < 2; ++ks) {
            uint32_t afr[2][4];
            int rl = lane & 15;
            int ci = cb8 + ks * 2 + (lane >> 4);
#pragma unroll
            for (int mi = 0; mi < 2; ++mi) {
                int r = wm * 32 + mi * 16 + rl;
                uint32_t addr = abase + r * 512 + ((ci ^ (r & 7)) << 4);
                ldsm4(addr, afr[mi][0], afr[mi][1], afr[mi][2], afr[mi][3]);
            }
            uint32_t bfr[4][4];
            int kb = ks * 16 + (lane & 15);
#pragma unroll
            for (int nj = 0; nj < 4; ++nj) {
                int n = wn * 64 + nj * 16 + ((lane >> 4) << 3);
                int cN = n >> 3;
                uint32_t addr = bbase + kb * 512 + ((cN ^ (kb & 7)) << 4);
                ldsm4t(addr, bfr[nj][0], bfr[nj][1], bfr[nj][2], bfr[nj][3]);
            }
#pragma unroll
            for (int mi = 0; mi < 2; ++mi)
#pragma unroll
                for (int nj = 0; nj < 4; ++nj) {
                    mma16816(acc[mi][nj * 2 + 0], afr[mi], bfr[nj][0], bfr[nj][1]);
                    mma16816(acc[mi][nj * 2 + 1], afr[mi], bfr[nj][2], bfr[nj][3]);
                }
        }
    }

    // epilogue: bias (+R) write, plus per-channel sum / sumsq accumulation
    int r_c = lane >> 2;
    int c_c = (lane & 3) * 2;
    float ss[8][2], qq[8][2];
#pragma unroll
    for (int ni = 0; ni < 8; ++ni) {
        ss[ni][0] = ss[ni][1] = 0.f;
        qq[ni][0] = qq[ni][1] = 0.f;
    }
#pragma unroll
    for (int mi = 0; mi < 2; ++mi) {
        int gr0 = row0 + wm * 32 + mi * 16 + r_c;
        int gr1 = gr0 + 8;
#pragma unroll
        for (int ni = 0; ni < 8; ++ni) {
            int gc = wn * 64 + ni * 8 + c_c;
            float b0 = bias[gc], b1 = bias[gc + 1];
            if (gr0 < M) {
                size_t o = (size_t)gr0 * 256 + gc;
                float x0 = acc[mi][ni][0] + b0;
                float x1 = acc[mi][ni][1] + b1;
                if (R) { float2 rv = *(const float2*)&R[o]; x0 += rv.x; x1 += rv.y; }
                *(float2*)&C[o] = make_float2(x0, x1);
                ss[ni][0] += x0; qq[ni][0] += x0 * x0;
                ss[ni][1] += x1; qq[ni][1] += x1 * x1;
            }
            if (gr1 < M) {
                size_t o = (size_t)gr1 * 256 + gc;
                float x2 = acc[mi][ni][2] + b0;
                float x3 = acc[mi][ni][3] + b1;
                if (R) { float2 rv = *(const float2*)&R[o]; x2 += rv.x; x3 += rv.y; }
                *(float2*)&C[o] = make_float2(x2, x3);
                ss[ni][0] += x2; qq[ni][0] += x2 * x2;
                ss[ni][1] += x3; qq[ni][1] += x3 * x3;
            }
        }
    }
#pragma unroll
    for (int ni = 0; ni < 8; ++ni)
#pragma unroll
        for (int j = 0; j < 2; ++j) {
            float s = ss[ni][j], q = qq[ni][j];
            s += __shfl_xor_sync(0xffffffffu, s, 4);
            s += __shfl_xor_sync(0xffffffffu, s, 8);
            s += __shfl_xor_sync(0xffffffffu, s, 16);
            q += __shfl_xor_sync(0xffffffffu, q, 4);
            q += __shfl_xor_sync(0xffffffffu, q, 8);
            q += __shfl_xor_sync(0xffffffffu, q, 16);
            ss[ni][j] = s; qq[ni][j] = q;
        }
    if (r_c == 0) {
#pragma unroll
        for (int ni = 0; ni < 8; ++ni) {
            int gc = wn * 64 + ni * 8 + c_c;
            red_addf(&stats[gc], ss[ni][0]);
            red_addf(&stats[gc + 1], ss[ni][1]);
            red_addf(&stats[256 + gc], qq[ni][0]);
            red_addf(&stats[256 + gc + 1], qq[ni][1]);
        }
    }
}

// ---------------- small GEMM (BM=32) for vn-MLP, 128 CTAs, BK=64 ----------------
#define BSTG 32768
#define SG_SMEM (32768 + 2 * BSTG)
#define SNKC 12

__device__ __forceinline__ void bg_issue256(int kc, uint32_t bb0, int tid,
                                            const __nv_bfloat16* __restrict__ Bw) {
    uint32_t bbase = bb0 + (uint32_t)(kc & 1) * BSTG;
    const __nv_bfloat16* bsrc = Bw + (size_t)kc * 64 * 256;
#pragma unroll
    for (int i = 0; i < 8; ++i) {
        int f = tid + i * 256;
        int k = f >> 5, c = f & 31;
        uint32_t dst = bbase + k * 512 + ((c ^ (k & 7)) << 4);
        cpasync16(dst, bsrc + k * 256 + c * 8);
    }
    cp_commit();
}

__global__ void __launch_bounds__(256, 1)
k_sgemm(const float* __restrict__ X, const __nv_bfloat16* __restrict__ Bw,
        const float* __restrict__ bias, float* __restrict__ C, float* __restrict__ stats,
        int M, int bnX) {
    extern __shared__ char sm[];
    uint32_t sb = s2u(sm);
    int tid = threadIdx.x;
    int lane = tid & 31;
    int wn = tid >> 5;   // 8 N-warps of 32 cols
    int row0 = blockIdx.x * 32;

    bg_issue256(0, sb + 32768u, tid, Bw);

#pragma unroll
    for (int it = 0; it < 4; ++it) {
        int f = tid + it * 256;
        int r = f >> 5, ci = f & 31;
        int row = row0 + r;
        float v[8];
        if (row < M) {
            size_t o = (size_t)row * 256 + ci * 8;
            float4 a0 = *(const float4*)&X[o];
            float4 a1 = *(const float4*)&X[o + 4];
            v[0] = a0.x; v[1] = a0.y; v[2] = a0.z; v[3] = a0.w;
            v[4] = a1.x; v[5] = a1.y; v[6] = a1.z; v[7] = a1.w;
            if (bnX) {
                float4 s0 = *(const float4*)&g_scale2[ci * 8];
                float4 s1 = *(const float4*)&g_scale2[ci * 8 + 4];
                float4 t0 = *(const float4*)&g_shift2[ci * 8];
                float4 t1 = *(const float4*)&g_shift2[ci * 8 + 4];
                v[0] = fmaxf(fmaf(v[0], s0.x, t0.x), 0.f);
                v[1] = fmaxf(fmaf(v[1], s0.y, t0.y), 0.f);
                v[2] = fmaxf(fmaf(v[2], s0.z, t0.z), 0.f);
                v[3] = fmaxf(fmaf(v[3], s0.w, t0.w), 0.f);
                v[4] = fmaxf(fmaf(v[4], s1.x, t1.x), 0.f);
                v[5] = fmaxf(fmaf(v[5], s1.y, t1.y), 0.f);
                v[6] = fmaxf(fmaf(v[6], s1.z, t1.z), 0.f);
                v[7] = fmaxf(fmaf(v[7], s1.w, t1.w), 0.f);
            }
        } else {
#pragma unroll
            for (int i = 0; i < 8; ++i) v[i] = 0.f;
        }
        uint32_t hw[4], lw[4];
#pragma unroll
        for (int i = 0; i < 4; ++i) {
            float x = v[2 * i], y = v[2 * i + 1];
            float hx = __bfloat162float(__float2bfloat16(x));
            float hy = __bfloat162float(__float2bfloat16(y));
            hw[i] = pkbf(x, y);
            lw[i] = pkbf(x - hx, y - hy);
        }
        uint32_t off = (uint32_t)(r * 512) + (uint32_t)((ci ^ (r & 7)) << 4);
        asm volatile("st.shared.v4.b32 [%0], {%1,%2,%3,%4};"
                     :: "r"(sb + off), "r"(hw[0]), "r"(hw[1]), "r"(hw[2]), "r"(hw[3]));
        asm volatile("st.shared.v4.b32 [%0], {%1,%2,%3,%4};"
                     :: "r"(sb + 16384u + off), "r"(lw[0]), "r"(lw[1]), "r"(lw[2]), "r"(lw[3]));
    }

    float acc[2][4][4];
#pragma unroll
    for (int mi = 0; mi < 2; ++mi)
#pragma unroll
        for (int ni = 0; ni < 4; ++ni)
#pragma unroll
            for (int q = 0; q < 4; ++q) acc[mi][ni][q] = 0.f;

    for (int kc = 0; kc < SNKC; ++kc) {
        cp_wait0();
        __syncthreads();
        if (kc + 1 < SNKC) bg_issue256(kc + 1, sb + 32768u, tid, Bw);

        uint32_t abase = sb + ((kc >= 4 && kc < 8) ? 16384u : 0u);
        uint32_t bbase = sb + 32768u + (uint32_t)(kc & 1) * BSTG;
#pragma unroll
        for (int ks = 0; ks < 4; ++ks) {
            uint32_t afr[2][4];
            int rl = lane & 15;
            int ci = (kc & 3) * 8 + ks * 2 + (lane >> 4);
#pragma unroll
            for (int mi = 0; mi < 2; ++mi) {
                int r = mi * 16 + rl;
                uint32_t addr = abase + r * 512 + ((ci ^ (r & 7)) << 4);
                ldsm4(addr, afr[mi][0], afr[mi][1], afr[mi][2], afr[mi][3]);
            }
            uint32_t bfr[2][4];
            int kb = ks * 16 + (lane & 15);
#pragma unroll
            for (int nj = 0; nj < 2; ++nj) {
                int n = wn * 32 + nj * 16 + ((lane >> 4) << 3);
                int cN = n >> 3;
                uint32_t addr = bbase + kb * 512 + ((cN ^ (kb & 7)) << 4);
                ldsm4t(addr, bfr[nj][0], bfr[nj][1], bfr[nj][2], bfr[nj][3]);
            }
#pragma unroll
            for (int mi = 0; mi < 2; ++mi)
#pragma unroll
                for (int nj = 0; nj < 2; ++nj) {
                    mma16816(acc[mi][nj * 2 + 0], afr[mi], bfr[nj][0], bfr[nj][1]);
                    mma16816(acc[mi][nj * 2 + 1], afr[mi], bfr[nj][2], bfr[nj][3]);
                }
        }
    }

    int r_c = lane >> 2;
    int c_c = (lane & 3) * 2;
    float ss[4][2], qq[4][2];
#pragma unroll
    for (int ni = 0; ni < 4; ++ni) {
        ss[ni][0] = ss[ni][1] = 0.f;
        qq[ni][0] = qq[ni][1] = 0.f;
    }
#pragma unroll
    for (int mi = 0; mi < 2; ++mi) {
        int gr0 = row0 + mi * 16 + r_c;
        int gr1 = gr0 + 8;
#pragma unroll
        for (int ni = 0; ni < 4; ++ni) {
            int gc = wn * 32 + ni * 8 + c_c;
            float b0 = bias[gc], b1 = bias[gc + 1];
            if (gr0 < M) {
                size_t o = (size_t)gr0 * 256 + gc;
                float x0 = acc[mi][ni][0] + b0;
                float x1 = acc[mi][ni][1] + b1;
                *(float2*)&C[o] = make_float2(x0, x1);
                ss[ni][0] += x0; qq[ni][0] += x0 * x0;
                ss[ni][1] += x1; qq[ni][1] += x1 * x1;
            }
            if (gr1 < M) {
                size_t o = (size_t)gr1 * 256 + gc;
                float x2 = acc[mi][ni][2] + b0;
                float x3 = acc[mi][ni][3] + b1;
                *(float2*)&C[o] = make_float2(x2, x3);
                ss[ni][0] += x2; qq[ni][0] += x2 * x2;
                ss[ni][1] += x3; qq[ni][1] += x3 * x3;
            }
        }
    }
#pragma unroll
    for (int ni = 0; ni < 4; ++ni)
#pragma unroll
        for (int j = 0; j < 2; ++j) {
            float s = ss[ni][j], q = qq[ni][j];
            s += __shfl_xor_sync(0xffffffffu, s, 4);
            s += __shfl_xor_sync(0xffffffffu, s, 8);
            s += __shfl_xor_sync(0xffffffffu, s, 16);
            q += __shfl_xor_sync(0xffffffffu, q, 4);
            q += __shfl_xor_sync(0xffffffffu, q, 8);
            q += __shfl_xor_sync(0xffffffffu, q, 16);
            ss[ni][j] = s; qq[ni][j] = q;
        }
    if (r_c == 0) {
#pragma unroll
        for (int ni = 0; ni < 4; ++ni) {
            int gc = wn * 32 + ni * 8 + c_c;
            red_addf(&stats[gc], ss[ni][0]);
            red_addf(&stats[gc + 1], ss[ni][1]);
            red_addf(&stats[256 + gc], qq[ni][0]);
            red_addf(&stats[256 + gc + 1], qq[ni][1]);
        }
    }
}

// ---------------- elementwise / encode kernels ----------------
__global__ void k_atom(const int* __restrict__ x, const float* __restrict__ aemb,
                       const float* __restrict__ vnw, float* __restrict__ h,
                       float* __restrict__ msg) {
    int t = threadIdx.x;
    int n = blockIdx.x * 4 + (t >> 6);
    if (n >= NN) return;
    int c = (t & 63) << 2;
    float4 s = *(const float4*)&vnw[c];
#pragma unroll
    for (int f = 0; f < 9; ++f) {
        int v = x[n * 9 + f];
        float4 ev = *(const float4*)&aemb[(size_t)((f << 6) + v) * HH + c];
        s.x += ev.x; s.y += ev.y; s.z += ev.z; s.w += ev.w;
    }
    *(float4*)&h[(size_t)n * HH + c] = s;
    *(float4*)&msg[(size_t)n * HH + c] = make_float4(0.f, 0.f, 0.f, 0.f);
}

// vn = vnw broadcast; pool = vn
__global__ void k_vninit(float* __restrict__ vn, float* __restrict__ pool,
                         const float* __restrict__ vnw) {
    int t = threadIdx.x;
    int g = blockIdx.x * 4 + (t >> 6);
    int c = (t & 63) << 2;
    float4 v = *(const float4*)&vnw[c];
    *(float4*)&vn[(size_t)g * HH + c] = v;
    *(float4*)&pool[(size_t)g * HH + c] = v;
}

__global__ void k_zero(float4* __restrict__ d, size_t n) {
    size_t i = (size_t)blockIdx.x * blockDim.x + threadIdx.x;
    size_t stride = (size_t)gridDim.x * blockDim.x;
    float4 z = make_float4(0.f, 0.f, 0.f, 0.f);
    for (; i < n; i += stride) d[i] = z;
}

// messages: agg[dst] += relu(bn?(h[src]) (+vn[batch[src]]) + bond) + 1e-7
__global__ void k_msg(const float* __restrict__ hin, const int* __restrict__ ei,
                      const int* __restrict__ ea, const float* __restrict__ bemb,
                      const int* __restrict__ batch, const float* __restrict__ vn,
                      float* __restrict__ agg, int bnflag) {
    int t = threadIdx.x;
    int e = blockIdx.x * 4 + (t >> 6);
    if (e >= EE) return;
    int c = (t & 63) << 2;
    int src = ei[e];
    int dst = ei[EE + e];
    int a0 = ea[e * 3 + 0], a1 = ea[e * 3 + 1], a2 = ea[e * 3 + 2];
    float4 hv = *(const float4*)&hin[(size_t)src * HH + c];
    if (bnflag) {
        float4 sc = *(const float4*)&g_scale[c];
        float4 sh = *(const float4*)&g_shift[c];
        hv.x = fmaxf(fmaf(hv.x, sc.x, sh.x), 0.f);
        hv.y = fmaxf(fmaf(hv.y, sc.y, sh.y), 0.f);
        hv.z = fmaxf(fmaf(hv.z, sc.z, sh.z), 0.f);
        hv.w = fmaxf(fmaf(hv.w, sc.w, sh.w), 0.f);
    }
    if (vn) {
        float4 vv = *(const float4*)&vn[(size_t)batch[src] * HH + c];
        hv.x += vv.x; hv.y += vv.y; hv.z += vv.z; hv.w += vv.w;
    }
    float4 b0 = *(const float4*)&bemb[(size_t)(0 * 8 + a0) * HH + c];
    float4 b1 = *(const float4*)&bemb[(size_t)(1 * 8 + a1) * HH + c];
    float4 b2 = *(const float4*)&bemb[(size_t)(2 * 8 + a2) * HH + c];
    float4 m;
    m.x = fmaxf(hv.x + b0.x + b1.x + b2.x, 0.f) + 1e-7f;
    m.y = fmaxf(hv.y + b0.y + b1.y + b2.y, 0.f) + 1e-7f;
    m.z = fmaxf(hv.z + b0.z + b1.z + b2.z, 0.f) + 1e-7f;
    m.w = fmaxf(hv.w + b0.w + b1.w + b2.w, 0.f) + 1e-7f;
    red_add4(&agg[(size_t)dst * HH + c], m);
}

// ---------------- BN finalizers (stat slots; no resets) -------------------------
__global__ void k_bnfin(const float* __restrict__ stats, const float* __restrict__ gamma,
                        const float* __restrict__ beta, float invM,
                        float* __restrict__ osc, float* __restrict__ osh) {
    int c = threadIdx.x;
    float mu = stats[c] * invM;
    float var = stats[256 + c] * invM - mu * mu;
    float sc = gamma[c] * rsqrtf(var + 1e-5f);
    osc[c] = sc;
    osh[c] = beta[c] - mu * sc;
}

// 64 CTAs: compute BN affine from slot, vn = relu(bn(X)), pool = vn
__global__ void k_bnfin2relu_pool(const float* __restrict__ stats,
                                  const float* __restrict__ gamma,
                                  const float* __restrict__ beta, float invM,
                                  const float* __restrict__ X, float* __restrict__ vn,
                                  float* __restrict__ pool) {
    __shared__ float ssc[256], ssh[256];
    int t = threadIdx.x;
    {
        float mu = stats[t] * invM;
        float var = stats[256 + t] * invM - mu * mu;
        float sc = gamma[t] * rsqrtf(var + 1e-5f);
        ssc[t] = sc;
        ssh[t] = beta[t] - mu * sc;
    }
    __syncthreads();
    size_t base = (size_t)blockIdx.x * 4096;   // in float4 units
#pragma unroll 4
    for (int i = 0; i < 16; ++i) {
        size_t idx = base + t + i * 256;
        int c = (idx & 63) << 2;
        float4 x = *(const float4*)&X[idx * 4];
        float4 sc = *(const float4*)&ssc[c];
        float4 sh = *(const float4*)&ssh[c];
        float4 v;
        v.x = fmaxf(fmaf(x.x, sc.x, sh.x), 0.f);
        v.y = fmaxf(fmaf(x.y, sc.y, sh.y), 0.f);
        v.z = fmaxf(fmaf(x.z, sc.z, sh.z), 0.f);
        v.w = fmaxf(fmaf(x.w, sc.w, sh.w), 0.f);
        *(float4*)&vn[idx * 4] = v;
        *(float4*)&pool[idx * 4] = v;
    }
}

// pool[batch[n]] += relu(bn(h[n])); msg = 0
__global__ void k_pool(const float* __restrict__ X, const int* __restrict__ batch,
                       float* __restrict__ pool, float* __restrict__ msg) {
    int t = threadIdx.x;
    int n = blockIdx.x * 4 + (t >> 6);
    if (n >= NN) return;
    int c = (t & 63) << 2;
    float4 xv = *(const float4*)&X[(size_t)n * HH + c];
    float4 sc = *(const float4*)&g_scale[c];
    float4 sh = *(const float4*)&g_shift[c];
    float4 v;
    v.x = fmaxf(fmaf(xv.x, sc.x, sh.x), 0.f);
    v.y = fmaxf(fmaf(xv.y, sc.y, sh.y), 0.f);
    v.z = fmaxf(fmaf(xv.z, sc.z, sh.z), 0.f);
    v.w = fmaxf(fmaf(xv.w, sc.w, sh.w), 0.f);
    *(float4*)&msg[(size_t)n * HH + c] = make_float4(0.f, 0.f, 0.f, 0.f);
    red_add4(&pool[(size_t)batch[n] * HH + c], v);
}

// out[batch[n]] += bn(h[n])  (final pooling; no relu)
__global__ void k_outpool(const float* __restrict__ X, const int* __restrict__ batch,
                          float* __restrict__ out) {
    int t = threadIdx.x;
    int n = blockIdx.x * 4 + (t >> 6);
    if (n >= NN) return;
    int c = (t & 63) << 2;
    float4 xv = *(const float4*)&X[(size_t)n * HH + c];
    float4 sc = *(const float4*)&g_scale[c];
    float4 sh = *(const float4*)&g_shift[c];
    float4 v;
    v.x = fmaf(xv.x, sc.x, sh.x);
    v.y = fmaf(xv.y, sc.y, sh.y);
    v.z = fmaf(xv.z, sc.z, sh.z);
    v.w = fmaf(xv.w, sc.w, sh.w);
    red_add4(&out[(size_t)batch[n] * HH + c], v);
}

// ---------------- host orchestration ----------------
extern "C" void kernel_launch(void* const* d_in, const int* in_sizes, int n_in,
                              void* d_out, int out_size) {
    const int* x = (const int*)d_in[0];
    const int* ei = (const int*)d_in[1];
    const int* ea = (const int*)d_in[2];
    const int* batch = (const int*)d_in[3];
    const float* aemb = (const float*)d_in[4];
    const float* bemb = (const float*)d_in[5];
    const float* vnw = (const float*)d_in[6];
    const float* cw = (const float*)d_in[7];
    const float* cb = (const float*)d_in[8];
    const float* ng = (const float*)d_in[9];
    const float* nbt = (const float*)d_in[10];
    const float* vw = (const float*)d_in[11];
    const float* vb = (const float*)d_in[12];
    const float* vg = (const float*)d_in[13];
    const float* vbt = (const float*)d_in[14];
    float* out = (float*)d_out;

    float *ph, *pmsg, *pvn, *ppool, *pvtmp, *pscale, *pshift, *pscale2, *pshift2, *pstats;
    __nv_bfloat16* pbw;
    cudaGetSymbolAddress((void**)&ph, g_h);
    cudaGetSymbolAddress((void**)&pmsg, g_msg);
    cudaGetSymbolAddress((void**)&pvn, g_vn);
    cudaGetSymbolAddress((void**)&ppool, g_pool);
    cudaGetSymbolAddress((void**)&pvtmp, g_vtmp);
    cudaGetSymbolAddress((void**)&pscale, g_scale);
    cudaGetSymbolAddress((void**)&pshift, g_shift);
    cudaGetSymbolAddress((void**)&pscale2, g_scale2);
    cudaGetSymbolAddress((void**)&pshift2, g_shift2);
    cudaGetSymbolAddress((void**)&pstats, g_stats);
    cudaGetSymbolAddress((void**)&pbw, g_bw);

    cudaFuncSetAttribute(k_fgemm, cudaFuncAttributeMaxDynamicSharedMemorySize, FG_SMEM);
    cudaFuncSetAttribute(k_sgemm, cudaFuncAttributeMaxDynamicSharedMemorySize, SG_SMEM);

    const int gN4 = (NN + 3) / 4;
    const int gE4 = (EE + 3) / 4;
    const size_t GH4 = (size_t)GG * HH / 4;
    const int tilesN = (NN + 63) / 64;   // 2344, BM=64, 2 CTAs/SM
    const int tilesG = GG / 32;
    const size_t WSTRIDE = (size_t)768 * HH;
    auto slot = [&](int s) { return pstats + (size_t)s * 512; };

    // conv weights -> mats 0..6 (+ zero all stat slots); vn weights -> mats 7..18
    k_prepw<<<7 * 256, 256>>>(cw, pbw, 7, 1);                                   // 0
    k_atom<<<gN4, 256>>>(x, aemb, vnw, ph, pmsg);                               // 1
    k_msg<<<gE4, 256>>>(ph, ei, ea, bemb, batch, nullptr, pmsg, 0);             // 2
    k_fgemm<<<tilesN, 256, FG_SMEM>>>(ph, pmsg, nullptr, nullptr, pbw, cb,      // 3
                                      nullptr, ph, slot(0), NN, 0);
    k_vninit<<<GG / 4, 256>>>(pvn, ppool, vnw);                                 // 4
    k_prepw<<<12 * 256, 256>>>(vw, pbw + 7 * WSTRIDE, 12, 0);                   // 5

    for (int l = 1; l < 7; ++l) {
        int s1 = 7 + (l - 1) * 2, s2 = s1 + 1;
        const float* vbl = vb + (size_t)(l - 1) * 2 * HH;
        const float* vgl = vg + (size_t)(l - 1) * 2 * HH;
        const float* vbl2 = vbt + (size_t)(l - 1) * 2 * HH;

        // node BN affine (stats from last fgemm), then pool atomics + msg zero
        k_bnfin<<<1, 256>>>(slot(l - 1), ng + (l - 1) * HH, nbt + (l - 1) * HH,
                            1.0f / NN, pscale, pshift);
        k_pool<<<gN4, 256>>>(ph, batch, ppool, pmsg);

        // vn MLP: Linear -> BN -> (ReLU fused) -> Linear -> BN+ReLU (+pool init)
        k_sgemm<<<tilesG, 256, SG_SMEM>>>(ppool, pbw + (size_t)s1 * WSTRIDE, vbl,
                                          pvtmp, slot(s1), GG, 0);
        k_bnfin<<<1, 256>>>(slot(s1), vgl, vbl2, 1.0f / GG, pscale2, pshift2);
        k_sgemm<<<tilesG, 256, SG_SMEM>>>(pvtmp, pbw + (size_t)s2 * WSTRIDE,
                                          vbl + HH, pvtmp, slot(s2), GG, 1);
        k_bnfin2relu_pool<<<64, 256>>>(slot(s2), vgl + HH, vbl2 + HH, 1.0f / GG,
                                       pvtmp, pvn, ppool);

        // messages on bnrelu(h)+vn gathered on the fly; fused node GEMM
        k_msg<<<gE4, 256>>>(ph, ei, ea, bemb, batch, pvn, pmsg, 1);
        k_fgemm<<<tilesN, 256, FG_SMEM>>>(ph, pmsg, batch, pvn,
                                          pbw + (size_t)l * WSTRIDE, cb + l * HH, ph, ph,
                                          slot(l), NN, 1);
    }

    // final BN (stats from last fgemm) + global_add_pool
    k_bnfin<<<1, 256>>>(slot(6), ng + 6 * HH, nbt + 6 * HH, 1.0f / NN, pscale, pshift);
    k_zero<<<512, 256>>>((float4*)out, GH4);
    k_outpool<<<gN4, 256>>>(ph, batch, out);
}